// round 12
// baseline (speedup 1.0000x reference)
#include <cuda_runtime.h>
#include <cuda_bf16.h>
#include <cuda_fp16.h>
#include <math.h>
#include <stdint.h>

// ---------------- problem constants ----------------
#define NOBJ 256
#define NHUM 64
#define EDIM 1024
#define NPAIR 16384
#define NKEEP 16320
#define OUTC 4213
#define NCLS 117

// ---------------- scratch ----------------
__device__ float g_enc1[NOBJ*EDIM];
__device__ float g_nssa[NOBJ*EDIM];
__device__ float g_Af[NHUM*2048];
__device__ float g_Aof[NOBJ*2048];
__device__ __half g_Ahh[NHUM*2048];
__device__ __half g_Aoh[NOBJ*2048];
__device__ float g_adjp[NPAIR];
__device__ float g_obj[NOBJ*EDIM];
__device__ float g_hum[NHUM*EDIM];
__device__ float g_hf[NHUM*2048];      // [h_enc | h_sp]
__device__ float g_hcatA[NHUM*2048];   // [h_enc | agg_o] ping
__device__ float g_hcatB[NHUM*2048];   // pong
__device__ float g_of[NOBJ*2048];      // [enc | nsp]
__device__ float g_ocatA[NOBJ*2048];
__device__ float g_ocatB[NOBJ*2048];
__device__ float g_whuhm[2048*1024];   // W_hu @ W_hm (fp32)
__device__ int   g_mask_mode;

// pre-split transposed weights [n][k]
__device__ __nv_bfloat16 g_bh1hi[1024*12544];
__device__ __nv_bfloat16 g_bh1lo[1024*12544];
__device__ __nv_bfloat16 g_bh2hi[1024*1024];
__device__ __nv_bfloat16 g_bh2lo[1024*1024];
__device__ __nv_bfloat16 g_sahi[1024*1024];
__device__ __nv_bfloat16 g_salo[1024*1024];
__device__ __nv_bfloat16 g_omhi[1024*1024];
__device__ __nv_bfloat16 g_omlo[1024*1024];
__device__ __nv_bfloat16 g_hmhi[1024*1024];
__device__ __nv_bfloat16 g_hmlo[1024*1024];
__device__ __nv_bfloat16 g_a1hi[2*2048*2048];
__device__ __nv_bfloat16 g_a1lo[2*2048*2048];
__device__ __nv_bfloat16 g_huhi[1024*2048];
__device__ __nv_bfloat16 g_hulo[1024*2048];
__device__ __nv_bfloat16 g_ouhi[1024*2048];
__device__ __nv_bfloat16 g_oulo[1024*2048];
__device__ __nv_bfloat16 g_huhmhi[1024*2048];  // W_huhm^T split
__device__ __nv_bfloat16 g_huhmlo[1024*2048];
__device__ __half        g_a2h[1024*2048];
__device__ __nv_bfloat16 g_boxhi[NOBJ*12544];
__device__ __nv_bfloat16 g_boxlo[NOBJ*12544];

__device__ __forceinline__ uint32_t smem_u32(const void* p) {
    uint32_t a;
    asm("{ .reg .u64 t; cvta.to.shared.u64 t, %1; cvt.u32.u64 %0, t; }" : "=r"(a) : "l"(p));
    return a;
}
__device__ __forceinline__ void cpasync16(uint32_t saddr, const void* g) {
    asm volatile("{ .reg .u64 gg; cvta.to.global.u64 gg, %1; "
                 "cp.async.cg.shared.global [%0], [gg], 16; }"
                 :: "r"(saddr), "l"(g));
}
#define CP_COMMIT() asm volatile("cp.async.commit_group;")
#define CP_WAIT0()  asm volatile("cp.async.wait_group 0;")

// ================= mma.sync helpers =================
__device__ __forceinline__ void mma_bf16(float* c, const uint32_t* a, const uint32_t* b)
{
    asm volatile("mma.sync.aligned.m16n8k16.row.col.f32.bf16.bf16.f32 "
                 "{%0,%1,%2,%3}, {%4,%5,%6,%7}, {%8,%9}, {%0,%1,%2,%3};"
                 : "+f"(c[0]), "+f"(c[1]), "+f"(c[2]), "+f"(c[3])
                 : "r"(a[0]), "r"(a[1]), "r"(a[2]), "r"(a[3]), "r"(b[0]), "r"(b[1]));
}
__device__ __forceinline__ void mma_f16(float* c, const uint32_t* a, const uint32_t* b)
{
    asm volatile("mma.sync.aligned.m16n8k16.row.col.f32.f16.f16.f32 "
                 "{%0,%1,%2,%3}, {%4,%5,%6,%7}, {%8,%9}, {%0,%1,%2,%3};"
                 : "+f"(c[0]), "+f"(c[1]), "+f"(c[2]), "+f"(c[3])
                 : "r"(a[0]), "r"(a[1]), "r"(a[2]), "r"(a[3]), "r"(b[0]), "r"(b[1]));
}
__device__ __forceinline__ void ldmx4(uint32_t* d, uint32_t addr)
{
    asm volatile("ldmatrix.sync.aligned.m8n8.x4.shared.b16 {%0,%1,%2,%3}, [%4];"
                 : "=r"(d[0]), "=r"(d[1]), "=r"(d[2]), "=r"(d[3]) : "r"(addr));
}
__device__ __forceinline__ void ldmx2(uint32_t* d, uint32_t addr)
{
    asm volatile("ldmatrix.sync.aligned.m8n8.x2.shared.b16 {%0,%1}, [%2];"
                 : "=r"(d[0]), "=r"(d[1]) : "r"(addr));
}

// bf16 hi/lo 3-pass chunk: 128x128 tile, K=64, stride 144B
__device__ __forceinline__ void mma_chunk(uint32_t abase_hi, uint32_t abase_lo,
                                          uint32_t wbase_hi, uint32_t wbase_lo,
                                          float acc[4][4][4], int lid,
                                          int warp_row, int warp_col)
{
    #pragma unroll
    for (int ks = 0; ks < 4; ks++) {
        const int kk = ks * 16;
        uint32_t bh[4][2], bl[4][2];
        const int l2 = lid & 15;
        const uint32_t bro = (uint32_t)((l2 & 7) * 144 + (kk + ((l2 & 8) ? 8 : 0)) * 2);
        #pragma unroll
        for (int an = 0; an < 4; an++) {
            uint32_t nbase = (uint32_t)((warp_col * 32 + an * 8) * 144);
            ldmx2(bh[an], wbase_hi + nbase + bro);
            ldmx2(bl[an], wbase_lo + nbase + bro);
        }
        const uint32_t aro = (uint32_t)((lid & 15) * 144 + (kk + ((lid & 16) ? 8 : 0)) * 2);
        #pragma unroll
        for (int am = 0; am < 4; am++) {
            uint32_t mbase = (uint32_t)((warp_row * 64 + am * 16) * 144);
            uint32_t ah4[4], al4[4];
            ldmx4(ah4, abase_hi + mbase + aro);
            ldmx4(al4, abase_lo + mbase + aro);
            #pragma unroll
            for (int an = 0; an < 4; an++) {
                mma_bf16(acc[am][an], ah4, bh[an]);
                mma_bf16(acc[am][an], ah4, bl[an]);
                mma_bf16(acc[am][an], al4, bh[an]);
            }
        }
    }
}

// ---------------- batched weight conversions ----------------
struct CvJobs {
    const float* W[10];
    void* hi[10];
    __nv_bfloat16* lo[10];
    int K[10];
    int N[10];
    int b0[10];
    int njobs;
};

__global__ void convall_k(CvJobs J)
{
    __shared__ float t[32][33];
    int bid = blockIdx.x;
    int j = 0;
    #pragma unroll
    for (int q = 1; q < 10; q++)
        if (q < J.njobs && bid >= J.b0[q]) j = q;
    int local = bid - J.b0[j];
    int K = J.K[j], N = J.N[j];
    int kblocks = K >> 5;
    int kb = (local % kblocks) * 32;
    int nb = (local / kblocks) * 32;
    const float* W = J.W[j];
    int tx = threadIdx.x, ty = threadIdx.y;
    #pragma unroll
    for (int i = 0; i < 4; i++)
        t[ty + 8 * i][tx] = W[(size_t)(kb + ty + 8 * i) * N + nb + tx];
    __syncthreads();
    if (J.lo[j]) {
        __nv_bfloat16* hi = (__nv_bfloat16*)J.hi[j];
        __nv_bfloat16* lo = J.lo[j];
        #pragma unroll
        for (int i = 0; i < 4; i++) {
            float v = t[tx][ty + 8 * i];
            __nv_bfloat16 h = __float2bfloat16(v);
            size_t oi = (size_t)(nb + ty + 8 * i) * K + kb + tx;
            hi[oi] = h;
            lo[oi] = __float2bfloat16(v - __bfloat162float(h));
        }
    } else {
        __half* out = (__half*)J.hi[j];
        #pragma unroll
        for (int i = 0; i < 4; i++)
            out[(size_t)(nb + ty + 8 * i) * K + kb + tx] = __float2half_rn(t[tx][ty + 8 * i]);
    }
}

__global__ void convA_k(const float* __restrict__ src, __nv_bfloat16* __restrict__ hi,
                        __nv_bfloat16* __restrict__ lo, int n)
{
    int base = (blockIdx.x * 256 + threadIdx.x) * 8;
    if (base >= n) return;
    float4 a = *(const float4*)(src + base);
    float4 b = *(const float4*)(src + base + 4);
    float v[8] = { a.x, a.y, a.z, a.w, b.x, b.y, b.z, b.w };
    __nv_bfloat16 hv[8], lv[8];
    #pragma unroll
    for (int i = 0; i < 8; i++) {
        hv[i] = __float2bfloat16(v[i]);
        lv[i] = __float2bfloat16(v[i] - __bfloat162float(hv[i]));
    }
    *(uint4*)(hi + base) = *(uint4*)hv;
    *(uint4*)(lo + base) = *(uint4*)lv;
}

// ================= unified jobs GEMM =================
#define GM_AHI 0
#define GM_ALO 18432
#define GM_WHI 36864
#define GM_WLO 55296
#define GM_SMEM 73728

struct GJobs {
    const float* A[3];
    const __nv_bfloat16* Ahi[3];
    const __nv_bfloat16* Alo[3];
    const __nv_bfloat16* Bhi[3];
    const __nv_bfloat16* Blo[3];
    const float* bias[3];
    float* C[3];
    float* C2[3];   // optional dual atomic target (same ldc)
    int lda[3], ldc[3], M[3], N[3], K[3], kslice[3], b0[3], gx[3], gy[3], reluA[3];
    int njobs;
};

__device__ void gemm_body(const float* __restrict__ A,
                          const __nv_bfloat16* __restrict__ A16h,
                          const __nv_bfloat16* __restrict__ A16l, int lda,
                          const __nv_bfloat16* __restrict__ Bhi,
                          const __nv_bfloat16* __restrict__ Blo,
                          const float* __restrict__ bias, float* __restrict__ C,
                          float* __restrict__ C2,
                          int ldc, int M, int N, int K, int kslice, int reluA,
                          int bx, int by, int bz, char* smem)
{
    uint32_t sb = smem_u32(smem);
    const int tid = threadIdx.x;
    const int wid = tid >> 5, lid = tid & 31;
    const int col0 = bx * 128;
    const int row0 = by * 128;
    const int kstart = bz * kslice;
    const int warp_row = wid >> 2, warp_col = wid & 3;

    const int r = tid >> 1, kh = tid & 1;
    int arow = row0 + r; if (arow >= M) arow = M - 1;
    const __nv_bfloat16* whp = Bhi + (size_t)(col0 + r) * K + kstart + kh * 32;
    const __nv_bfloat16* wlp = Blo + (size_t)(col0 + r) * K + kstart + kh * 32;
    const uint32_t soff = (uint32_t)(r * 144 + kh * 64);

    float acc[4][4][4];
    #pragma unroll
    for (int i = 0; i < 4; i++)
        #pragma unroll
        for (int j = 0; j < 4; j++)
            #pragma unroll
            for (int q = 0; q < 4; q++) acc[i][j][q] = 0.f;

    const int nchunk = kslice >> 6;
    if (A16h) {
        const __nv_bfloat16* ahp = A16h + (size_t)arow * lda + kstart + kh * 32;
        const __nv_bfloat16* alp = A16l + (size_t)arow * lda + kstart + kh * 32;
        for (int c = 0; c < nchunk; c++) {
            const int k0 = c * 64;
            __syncthreads();
            #pragma unroll
            for (int j = 0; j < 4; j++) {
                cpasync16(sb + GM_WHI + soff + j * 16, whp + k0 + j * 8);
                cpasync16(sb + GM_WLO + soff + j * 16, wlp + k0 + j * 8);
            }
            #pragma unroll
            for (int j = 0; j < 4; j++) {
                cpasync16(sb + GM_AHI + soff + j * 16, ahp + k0 + j * 8);
                cpasync16(sb + GM_ALO + soff + j * 16, alp + k0 + j * 8);
            }
            CP_COMMIT();
            CP_WAIT0();
            __syncthreads();
            mma_chunk(sb + GM_AHI, sb + GM_ALO, sb + GM_WHI, sb + GM_WLO,
                      acc, lid, warp_row, warp_col);
        }
    } else {
        const float* agp = A + (size_t)arow * lda + kstart + kh * 32;
        for (int c = 0; c < nchunk; c++) {
            const int k0 = c * 64;
            __syncthreads();
            #pragma unroll
            for (int j = 0; j < 4; j++) {
                cpasync16(sb + GM_WHI + soff + j * 16, whp + k0 + j * 8);
                cpasync16(sb + GM_WLO + soff + j * 16, wlp + k0 + j * 8);
            }
            CP_COMMIT();
            const float4* p = (const float4*)(agp + k0);
            #pragma unroll
            for (int j = 0; j < 8; j++) {
                float4 a = p[j];
                if (reluA) {
                    a.x = fmaxf(a.x, 0.f); a.y = fmaxf(a.y, 0.f);
                    a.z = fmaxf(a.z, 0.f); a.w = fmaxf(a.w, 0.f);
                }
                __nv_bfloat16 h0 = __float2bfloat16(a.x), h1 = __float2bfloat16(a.y);
                __nv_bfloat16 h2 = __float2bfloat16(a.z), h3 = __float2bfloat16(a.w);
                __nv_bfloat162 hw0 = __nv_bfloat162(h0, h1), hw1 = __nv_bfloat162(h2, h3);
                __nv_bfloat162 lw0 = __nv_bfloat162(__float2bfloat16(a.x - __bfloat162float(h0)),
                                                    __float2bfloat16(a.y - __bfloat162float(h1)));
                __nv_bfloat162 lw1 = __nv_bfloat162(__float2bfloat16(a.z - __bfloat162float(h2)),
                                                    __float2bfloat16(a.w - __bfloat162float(h3)));
                *(uint2*)(smem + GM_AHI + soff + j * 8) = make_uint2(*(uint32_t*)&hw0, *(uint32_t*)&hw1);
                *(uint2*)(smem + GM_ALO + soff + j * 8) = make_uint2(*(uint32_t*)&lw0, *(uint32_t*)&lw1);
            }
            CP_WAIT0();
            __syncthreads();
            mma_chunk(sb + GM_AHI, sb + GM_ALO, sb + GM_WHI, sb + GM_WLO,
                      acc, lid, warp_row, warp_col);
        }
    }

    #pragma unroll
    for (int am = 0; am < 4; am++) {
        #pragma unroll
        for (int q = 0; q < 4; q++) {
            int row = row0 + warp_row * 64 + am * 16 + (lid >> 2) + ((q >= 2) ? 8 : 0);
            if (row >= M) continue;
            #pragma unroll
            for (int an = 0; an < 4; an++) {
                int col = col0 + warp_col * 32 + an * 8 + (lid & 3) * 2 + (q & 1);
                float v = acc[am][an][q];
                if (bz == 0 && bias) v += bias[col];
                size_t idx = (size_t)row * ldc + col;
                atomicAdd(C + idx, v);
                if (C2) atomicAdd(C2 + idx, v);
            }
        }
    }
}

__global__ void __launch_bounds__(256, 2)
gemm_jobs_k(GJobs J)
{
    extern __shared__ char smem[];
    int bid = blockIdx.x;
    int j = 0;
    #pragma unroll
    for (int q = 1; q < 3; q++)
        if (q < J.njobs && bid >= J.b0[q]) j = q;
    int local = bid - J.b0[j];
    int gxy = J.gx[j] * J.gy[j];
    int bz = local / gxy;
    int rem = local % gxy;
    int by = rem / J.gx[j];
    int bx = rem % J.gx[j];
    gemm_body(J.A[j], J.Ahi[j], J.Alo[j], J.lda[j], J.Bhi[j], J.Blo[j], J.bias[j], J.C[j],
              J.C2[j], J.ldc[j], J.M[j], J.N[j], J.K[j], J.kslice[j], J.reluA[j],
              bx, by, bz, smem);
}

// ================= fp16 pair MMA: 64-row tiles =================
#define PR_AHS   0
#define PR_ST0   4096
#define PR_A     0
#define PR_W     9216
#define PR_STAGE 27648
#define PR_RED   59392
#define PR_B2    59904
#define PR_W3    60416
#define PR_SMEM  60928

__global__ void __launch_bounds__(256, 2)
pair_mma_k(const __half* __restrict__ Ahh, const __half* __restrict__ Aoh,
           const __half* __restrict__ Wt, const float* __restrict__ b2,
           const float* __restrict__ w3, float* __restrict__ adjp)
{
    extern __shared__ char smem[];
    uint32_t sb = smem_u32(smem);
    const int tid = threadIdx.x;
    const int wid = tid >> 5, lid = tid & 31;
    const int col0 = blockIdx.x * 128;
    const int row0 = blockIdx.y * 64;
    const int h = row0 >> 8;
    const int nb = row0 & 255;
    const int warp_row = wid >> 2, warp_col = wid & 3;   // 2 x 4

    if (tid < 128) {
        *(float*)(smem + PR_B2 + tid * 4) = b2[col0 + tid];
        *(float*)(smem + PR_W3 + tid * 4) = w3[col0 + tid];
    }
    if (tid < 64) *(float*)(smem + PR_RED + tid * 4) = 0.f;
    *(uint4*)(smem + PR_AHS + tid * 16) = *(const uint4*)(Ahh + h * 2048 + tid * 8);

    // A loader: row ra (0..63), quarter kq (0..3) — 16 halves each
    const int ra = tid >> 2, kq = tid & 3;
    const __half* aop = Aoh + (size_t)(nb + ra) * 2048 + kq * 16;
    const uint32_t soffA = (uint32_t)(ra * 144 + kq * 32);
    // W loader: row rw (0..127), half kh (0..1) — 32 halves each
    const int rw = tid >> 1, kh = tid & 1;
    const __half* whp = Wt + (size_t)(col0 + rw) * 2048 + kh * 32;
    const uint32_t soffW = (uint32_t)(rw * 144 + kh * 64);

    float acc[2][4][4];
    #pragma unroll
    for (int i = 0; i < 2; i++)
        #pragma unroll
        for (int j = 0; j < 4; j++)
            #pragma unroll
            for (int q = 0; q < 4; q++) acc[i][j][q] = 0.f;

    {
        uint32_t stb = sb + PR_ST0;
        cpasync16(stb + PR_A + soffA, aop);
        cpasync16(stb + PR_A + soffA + 16, aop + 8);
        #pragma unroll
        for (int j = 0; j < 2; j++) {
            cpasync16(stb + PR_W + soffW + j * 16, whp + j * 8);
            cpasync16(stb + PR_W + soffW + 32 + j * 16, whp + 16 + j * 8);
        }
        CP_COMMIT();
    }
    __syncthreads();

    const __half2 hz = __floats2half2_rn(0.f, 0.f);
    const int n_off = ((lid >> 4) & 1) * 8 + (lid & 7);
    const int kb_ = ((lid >> 3) & 1) * 8;

    for (int c = 0; c < 32; c++) {
        const int cur = c & 1;
        CP_WAIT0();
        // in-place add+relu on this thread's own 16 A halves
        {
            char* av = smem + PR_ST0 + cur * PR_STAGE + PR_A + soffA;
            const uint4* ahq = (const uint4*)(smem + PR_AHS + (c * 64 + kq * 16) * 2);
            #pragma unroll
            for (int j = 0; j < 2; j++) {
                uint4 vo = *(uint4*)(av + j * 16);
                uint4 vh = ahq[j];
                __half2 r0 = __hmax2(__hadd2(*(__half2*)&vo.x, *(__half2*)&vh.x), hz);
                __half2 r1 = __hmax2(__hadd2(*(__half2*)&vo.y, *(__half2*)&vh.y), hz);
                __half2 r2 = __hmax2(__hadd2(*(__half2*)&vo.z, *(__half2*)&vh.z), hz);
                __half2 r3 = __hmax2(__hadd2(*(__half2*)&vo.w, *(__half2*)&vh.w), hz);
                *(uint4*)(av + j * 16) = make_uint4(*(uint32_t*)&r0, *(uint32_t*)&r1,
                                                    *(uint32_t*)&r2, *(uint32_t*)&r3);
            }
        }
        __syncthreads();
        if (c < 31) {
            uint32_t stb = sb + PR_ST0 + (cur ^ 1) * PR_STAGE;
            const int kn = (c + 1) * 64;
            cpasync16(stb + PR_A + soffA, aop + kn);
            cpasync16(stb + PR_A + soffA + 16, aop + kn + 8);
            #pragma unroll
            for (int j = 0; j < 2; j++) {
                cpasync16(stb + PR_W + soffW + j * 16, whp + kn + j * 8);
                cpasync16(stb + PR_W + soffW + 32 + j * 16, whp + kn + 16 + j * 8);
            }
            CP_COMMIT();
        }
        uint32_t abase = sb + PR_ST0 + cur * PR_STAGE + PR_A;
        uint32_t wbase = sb + PR_ST0 + cur * PR_STAGE + PR_W;
        #pragma unroll
        for (int ks = 0; ks < 4; ks++) {
            const int kk = ks * 16;
            uint32_t b[4][2];
            #pragma unroll
            for (int anp = 0; anp < 2; anp++) {
                uint32_t t[4];
                ldmx4(t, wbase + (uint32_t)((warp_col * 32 + anp * 16 + n_off) * 144
                                            + (kk + kb_) * 2));
                b[anp * 2][0] = t[0]; b[anp * 2][1] = t[1];
                b[anp * 2 + 1][0] = t[2]; b[anp * 2 + 1][1] = t[3];
            }
            const uint32_t aro = (uint32_t)((lid & 15) * 144 + (kk + ((lid & 16) ? 8 : 0)) * 2);
            #pragma unroll
            for (int am = 0; am < 2; am++) {
                uint32_t a4[4];
                ldmx4(a4, abase + (uint32_t)((warp_row * 32 + am * 16) * 144) + aro);
                #pragma unroll
                for (int an = 0; an < 4; an++)
                    mma_f16(acc[am][an], a4, b[an]);
            }
        }
    }

    const float* b2s = (const float*)(smem + PR_B2);
    const float* w3s = (const float*)(smem + PR_W3);
    float* sred = (float*)(smem + PR_RED);
    #pragma unroll
    for (int am = 0; am < 2; am++) {
        float pl = 0.f, ph = 0.f;
        #pragma unroll
        for (int an = 0; an < 4; an++) {
            int cb = warp_col * 32 + an * 8 + 2 * (lid & 3);
            float w0 = w3s[cb], w1 = w3s[cb + 1];
            float bb0 = b2s[cb], bb1 = b2s[cb + 1];
            pl += fmaxf(acc[am][an][0] + bb0, 0.f) * w0 + fmaxf(acc[am][an][1] + bb1, 0.f) * w1;
            ph += fmaxf(acc[am][an][2] + bb0, 0.f) * w0 + fmaxf(acc[am][an][3] + bb1, 0.f) * w1;
        }
        pl += __shfl_xor_sync(0xffffffffu, pl, 1);
        pl += __shfl_xor_sync(0xffffffffu, pl, 2);
        ph += __shfl_xor_sync(0xffffffffu, ph, 1);
        ph += __shfl_xor_sync(0xffffffffu, ph, 2);
        if ((lid & 3) == 0) {
            int rloc = warp_row * 32 + am * 16 + (lid >> 2);
            atomicAdd(sred + rloc, pl);
            atomicAdd(sred + rloc + 8, ph);
        }
    }
    __syncthreads();
    if (tid < 64) atomicAdd(adjp + row0 + tid, sred[tid]);
}

// ---------------- small fused kernels ----------------
__device__ __forceinline__ float sigf(float z) { return 1.f / (1.f + expf(-z)); }

__global__ void zeroinit_k(float* enc1, float* Af, float* Aof, float* obj,
                           float* hum, float* adjp, float* nssa, float* of,
                           float* whuhm)
{
    int i = blockIdx.x * 256 + threadIdx.x;
    if (i < 262144) enc1[i] = 0.f;
    else if (i < 393216) Af[i - 262144] = 0.f;
    else if (i < 917504) Aof[i - 393216] = 0.f;
    else if (i < 1179648) obj[i - 917504] = 0.f;
    else if (i < 1245184) hum[i - 1179648] = 0.f;
    else if (i < 1261568) adjp[i - 1245184] = 0.f;
    else if (i < 1523712) nssa[i - 1261568] = 0.f;
    else if (i < 1785856) {
        int j = i - 1523712;
        of[(j >> 10) * 2048 + (j & 1023)] = 0.f;
    }
    else if (i < 3883008) whuhm[i - 1785856] = 0.f;
}

__global__ void zero2_k(float* Af, float* Aof, float* adjp)
{
    int i = blockIdx.x * 256 + threadIdx.x;
    if (i < 131072) Af[i] = 0.f;
    else if (i < 655360) Aof[i - 131072] = 0.f;
    else if (i < 671744) adjp[i - 655360] = 0.f;
}

__global__ void copyinit_k(float* of, float* ocat, float* hf, float* hcat,
                           const float* __restrict__ nsp)
{
    int i = blockIdx.x * 256 + threadIdx.x;
    if (i >= 262144) return;
    int r = i >> 10, c = i & 1023;
    float e = fmaxf(of[r * 2048 + c], 0.f);
    of[r * 2048 + c] = e;
    float s = nsp[i];
    of[r * 2048 + 1024 + c] = s;
    ocat[r * 2048 + c] = e;
    if (r < 64) {
        hf[r * 2048 + c] = e;
        hf[r * 2048 + 1024 + c] = s;
        hcat[r * 2048 + c] = e;
    }
}

__global__ void cvt_k(const float* __restrict__ Af, const float* __restrict__ Aof,
                      __half* __restrict__ Ahh, __half* __restrict__ Aoh)
{
    int i = blockIdx.x * 256 + threadIdx.x;
    if (i < 131072) Ahh[i] = __float2half_rn(Af[i]);
    else if (i < 655360) Aoh[i - 131072] = __float2half_rn(Aof[i - 131072]);
}

// aggo: writes hcat_in-right; zeroes hf-left, hum, hcat_out-left
__global__ void aggo_k(const float* __restrict__ adjp, const float* __restrict__ b3,
                       const float* __restrict__ obj, const float* __restrict__ nssa,
                       float* __restrict__ hcat_in, float* __restrict__ hcat_out,
                       float* __restrict__ hf, float* __restrict__ hum)
{
    int h = blockIdx.y;
    int e = blockIdx.x * 128 + threadIdx.x;
    __shared__ float sa[256];
    float b3v = b3[0];
    for (int i = threadIdx.x; i < 256; i += 128)
        sa[i] = sigf(adjp[h * 256 + i] + b3v);
    __syncthreads();
    float a1 = 0.f, a2 = 0.f;
    #pragma unroll 4
    for (int n = 0; n < 256; n++) {
        float a = sa[n];
        float om = fmaxf(obj[n * 1024 + e], 0.f);
        float ns = nssa[n * 1024 + e];
        a1 += a * om;
        a2 += a * om * ns;
    }
    hcat_in[h * 2048 + 1024 + e] = nssa[h * 1024 + e] * a1 - a2;
    hcat_out[h * 2048 + e] = 0.f;
    hf[h * 2048 + e] = 0.f;
    hum[h * 1024 + e] = 0.f;
}

// aggh: writes ocat_in-right; zeroes of-left, obj, ocat_out-left
__global__ void aggh_k(const float* __restrict__ adjp, const float* __restrict__ b3,
                       const float* __restrict__ hum, const float* __restrict__ nssa,
                       float* __restrict__ ocat_in, float* __restrict__ ocat_out,
                       float* __restrict__ of, float* __restrict__ obj)
{
    int n = blockIdx.y;
    int e = blockIdx.x * 128 + threadIdx.x;
    __shared__ float sa[64];
    float b3v = b3[0];
    if (threadIdx.x < 64) sa[threadIdx.x] = sigf(adjp[threadIdx.x * 256 + n] + b3v);
    __syncthreads();
    float a1 = 0.f, a2 = 0.f;
    #pragma unroll 4
    for (int h = 0; h < 64; h++) {
        float a = sa[h];
        float hm = fmaxf(hum[h * 1024 + e], 0.f);
        float hs = nssa[h * 1024 + e];
        a1 += a * hm;
        a2 += a * hm * hs;
    }
    ocat_in[n * 2048 + 1024 + e] = nssa[n * 1024 + e] * a1 - a2;
    ocat_out[n * 2048 + e] = 0.f;
    of[n * 2048 + e] = 0.f;
    obj[n * 1024 + e] = 0.f;
}

__global__ void detect_k(const unsigned char* __restrict__ cm)
{
    __shared__ int s_f, s_nz;
    if (threadIdx.x == 0) { s_f = 0; s_nz = 0; }
    __syncthreads();
    int lf = 0, lnz = 0;
    for (int i = threadIdx.x; i < 9360; i += blockDim.x) {
        unsigned char b = cm[i];
        int m4 = i & 3;
        if (m4 == 3 && b == 0x3F) lf = 1;
        if (m4 != 0 && b != 0) lnz = 1;
    }
    if (lf) atomicOr(&s_f, 1);
    if (lnz) atomicOr(&s_nz, 1);
    __syncthreads();
    if (threadIdx.x == 0) g_mask_mode = s_f ? 2 : (s_nz ? 0 : 1);
}

__device__ __forceinline__ float lisf(float x)
{
    return 8.3f / (1.f + expf(12.f - 10.f * x));
}

__global__ void out_k(const float* __restrict__ hf, const float* __restrict__ of,
                      const float* __restrict__ adjp, const float* __restrict__ b3,
                      const float* __restrict__ scores, const int* __restrict__ labels,
                      const void* __restrict__ cmask, float* __restrict__ out)
{
    int p = blockIdx.x;
    int x = p / 255;
    int r = p % 255;
    int y = (r < x) ? r : r + 1;

    float scale = sigf(adjp[x * 256 + y] + b3[0]) * lisf(scores[x]) * lisf(scores[y]);
    int lab = labels[y];
    int mode = g_mask_mode;

    const float* hx = hf + x * 2048;
    const float* oy = of + y * 2048;
    float* o = out + (size_t)p * OUTC;

    for (int c = threadIdx.x; c < OUTC; c += blockDim.x) {
        float v;
        if (c < 2048)       v = hx[c];
        else if (c < 4096)  v = oy[c - 2048];
        else {
            int j = c - 4096;
            float m;
            if (mode == 0)      m = ((const unsigned char*)cmask)[lab * NCLS + j] ? 1.f : 0.f;
            else if (mode == 1) m = ((const int*)cmask)[lab * NCLS + j] ? 1.f : 0.f;
            else                m = ((const float*)cmask)[lab * NCLS + j];
            v = scale * m;
        }
        o[c] = v;
    }
}

// ---------------- host ----------------
static void add_job(GJobs& J, int idx, const float* A,
                    const __nv_bfloat16* Ahi, const __nv_bfloat16* Alo, int lda,
                    const __nv_bfloat16* Bhi, const __nv_bfloat16* Blo,
                    const float* bias, float* C, float* C2, int ldc,
                    int M, int N, int K, int nk, int reluA, int& total)
{
    int gx = N / 128, gy = (M + 127) / 128;
    J.A[idx] = A; J.Ahi[idx] = Ahi; J.Alo[idx] = Alo;
    J.Bhi[idx] = Bhi; J.Blo[idx] = Blo; J.bias[idx] = bias;
    J.C[idx] = C; J.C2[idx] = C2; J.lda[idx] = lda; J.ldc[idx] = ldc;
    J.M[idx] = M; J.N[idx] = N; J.K[idx] = K; J.kslice[idx] = K / nk;
    J.gx[idx] = gx; J.gy[idx] = gy; J.b0[idx] = total; J.reluA[idx] = reluA;
    total += gx * gy * nk;
}

extern "C" void kernel_launch(void* const* d_in, const int* in_sizes, int n_in,
                              void* d_out, int out_size)
{
    const float *box = 0, *nsp = 0, *scores = 0;
    const int *labels = 0;
    const void *cmask = 0;
    const float *W_bh1 = 0, *b_bh1 = 0, *W_bh2 = 0, *b_bh2 = 0, *W_sa = 0;
    const float *W_a1 = 0, *b_a1 = 0, *W_a2 = 0, *b_a2 = 0, *W_a3 = 0, *b_a3 = 0;
    const float *W_hm = 0, *b_hm = 0, *W_om = 0, *b_om = 0, *W_hu = 0, *W_ou = 0;

    int c256 = 0, c1k = 0, c1m = 0, c2m = 0;
    for (int i = 0; i < n_in; i++) {
        const void* p = d_in[i];
        switch (in_sizes[i]) {
            case 3211264:  box = (const float*)p; break;
            case 262144:   nsp = (const float*)p; break;
            case 256:      if (c256++ == 0) scores = (const float*)p; else labels = (const int*)p; break;
            case 9360:     cmask = p; break;
            case 12845056: W_bh1 = (const float*)p; break;
            case 1024:
                switch (c1k++) {
                    case 0: b_bh1 = (const float*)p; break;
                    case 1: b_bh2 = (const float*)p; break;
                    case 2: b_a2  = (const float*)p; break;
                    case 3: W_a3  = (const float*)p; break;
                    case 4: b_hm  = (const float*)p; break;
                    case 5: b_om  = (const float*)p; break;
                } break;
            case 1048576:
                switch (c1m++) {
                    case 0: W_bh2 = (const float*)p; break;
                    case 1: W_sa  = (const float*)p; break;
                    case 2: W_hm  = (const float*)p; break;
                    case 3: W_om  = (const float*)p; break;
                } break;
            case 8388608:  W_a1 = (const float*)p; break;
            case 2048:     b_a1 = (const float*)p; break;
            case 2097152:
                switch (c2m++) {
                    case 0: W_a2 = (const float*)p; break;
                    case 1: W_hu = (const float*)p; break;
                    case 2: W_ou = (const float*)p; break;
                } break;
            case 1:        b_a3 = (const float*)p; break;
            default: break;
        }
    }

    float *enc1, *nssa, *Af, *Aof, *adjp, *obj, *hum, *hf, *hcatA, *hcatB, *of, *ocatA, *ocatB, *whuhm;
    __half *Ahh, *Aoh;
    cudaGetSymbolAddress((void**)&enc1, g_enc1);
    cudaGetSymbolAddress((void**)&nssa, g_nssa);
    cudaGetSymbolAddress((void**)&Af,   g_Af);
    cudaGetSymbolAddress((void**)&Aof,  g_Aof);
    cudaGetSymbolAddress((void**)&Ahh,  g_Ahh);
    cudaGetSymbolAddress((void**)&Aoh,  g_Aoh);
    cudaGetSymbolAddress((void**)&adjp, g_adjp);
    cudaGetSymbolAddress((void**)&obj,  g_obj);
    cudaGetSymbolAddress((void**)&hum,  g_hum);
    cudaGetSymbolAddress((void**)&hf,   g_hf);
    cudaGetSymbolAddress((void**)&hcatA, g_hcatA);
    cudaGetSymbolAddress((void**)&hcatB, g_hcatB);
    cudaGetSymbolAddress((void**)&of,   g_of);
    cudaGetSymbolAddress((void**)&ocatA, g_ocatA);
    cudaGetSymbolAddress((void**)&ocatB, g_ocatB);
    cudaGetSymbolAddress((void**)&whuhm, g_whuhm);

    __nv_bfloat16 *bh1hi, *bh1lo, *bh2hi, *bh2lo, *sahi, *salo, *omhi, *omlo, *hmhi, *hmlo;
    __nv_bfloat16 *a1hi, *a1lo, *huhi, *hulo, *ouhi, *oulo, *boxhi, *boxlo, *huhmhi, *huhmlo;
    __half *a2h;
    cudaGetSymbolAddress((void**)&bh1hi, g_bh1hi);
    cudaGetSymbolAddress((void**)&bh1lo, g_bh1lo);
    cudaGetSymbolAddress((void**)&bh2hi, g_bh2hi);
    cudaGetSymbolAddress((void**)&bh2lo, g_bh2lo);
    cudaGetSymbolAddress((void**)&sahi,  g_sahi);
    cudaGetSymbolAddress((void**)&salo,  g_salo);
    cudaGetSymbolAddress((void**)&omhi,  g_omhi);
    cudaGetSymbolAddress((void**)&omlo,  g_omlo);
    cudaGetSymbolAddress((void**)&hmhi,  g_hmhi);
    cudaGetSymbolAddress((void**)&hmlo,  g_hmlo);
    cudaGetSymbolAddress((void**)&a1hi,  g_a1hi);
    cudaGetSymbolAddress((void**)&a1lo,  g_a1lo);
    cudaGetSymbolAddress((void**)&huhi,  g_huhi);
    cudaGetSymbolAddress((void**)&hulo,  g_hulo);
    cudaGetSymbolAddress((void**)&ouhi,  g_ouhi);
    cudaGetSymbolAddress((void**)&oulo,  g_oulo);
    cudaGetSymbolAddress((void**)&huhmhi, g_huhmhi);
    cudaGetSymbolAddress((void**)&huhmlo, g_huhmlo);
    cudaGetSymbolAddress((void**)&a2h,   g_a2h);
    cudaGetSymbolAddress((void**)&boxhi, g_boxhi);
    cudaGetSymbolAddress((void**)&boxlo, g_boxlo);

    cudaFuncSetAttribute(pair_mma_k, cudaFuncAttributeMaxDynamicSharedMemorySize, PR_SMEM);
    cudaFuncSetAttribute(gemm_jobs_k, cudaFuncAttributeMaxDynamicSharedMemorySize, GM_SMEM);

    detect_k<<<1, 256>>>((const unsigned char*)cmask);

    // ---- batched weight conversions + box pre-split ----
    {
        CvJobs J;
        J.njobs = 10;
        const float* Ws[10] = { W_bh1, W_a1, W_a1 + (size_t)2048 * 2048, W_bh2, W_sa,
                                W_om, W_hm, W_hu, W_ou, W_a2 };
        void* his[10] = { bh1hi, a1hi, a1hi + (size_t)2048 * 2048, bh2hi, sahi,
                          omhi, hmhi, huhi, ouhi, a2h };
        __nv_bfloat16* los[10] = { bh1lo, a1lo, a1lo + (size_t)2048 * 2048, bh2lo, salo,
                                   omlo, hmlo, hulo, oulo, 0 };
        int Ks[10] = { 12544, 2048, 2048, 1024, 1024, 1024, 1024, 2048, 2048, 2048 };
        int Ns[10] = { 1024, 2048, 2048, 1024, 1024, 1024, 1024, 1024, 1024, 1024 };
        int total = 0;
        for (int j = 0; j < 10; j++) {
            J.W[j] = Ws[j]; J.hi[j] = his[j]; J.lo[j] = los[j];
            J.K[j] = Ks[j]; J.N[j] = Ns[j];
            J.b0[j] = total;
            total += (Ks[j] >> 5) * (Ns[j] >> 5);
        }
        convall_k<<<total, dim3(32, 8)>>>(J);
    }
    convA_k<<<3211264 / 2048, 256>>>(box, boxhi, boxlo, 3211264);

    zeroinit_k<<<(3883008 + 255) / 256, 256>>>(enc1, Af, Aof, obj, hum, adjp, nssa, of, whuhm);

    // ---- encoder + W_huhm composition ----
    {
        GJobs J; int total = 0; J.njobs = 1;
        add_job(J, 0, 0, boxhi, boxlo, 12544, bh1hi, bh1lo, b_bh1, enc1, 0, 1024,
                NOBJ, 1024, 12544, 28, 0, total);
        gemm_jobs_k<<<total, 256, GM_SMEM>>>(J);
    }
    {
        GJobs J; int total = 0; J.njobs = 3;
        add_job(J, 0, enc1, 0, 0, 1024, bh2hi, bh2lo, b_bh2, of, 0, 2048, NOBJ, 1024, 1024, 4, 1, total);
        add_job(J, 1, nsp, 0, 0, 1024, sahi, salo, 0, nssa, 0, 1024, NOBJ, 1024, 1024, 4, 0, total);
        add_job(J, 2, W_hu, 0, 0, 1024, hmhi, hmlo, 0, whuhm, 0, 1024, 2048, 1024, 1024, 1, 0, total);
        gemm_jobs_k<<<total, 256, GM_SMEM>>>(J);
    }
    // split W_huhm
    {
        CvJobs J;
        J.njobs = 1;
        J.W[0] = whuhm; J.hi[0] = huhmhi; J.lo[0] = huhmlo;
        J.K[0] = 2048; J.N[0] = 1024; J.b0[0] = 0;
        convall_k<<<(2048 >> 5) * (1024 >> 5), dim3(32, 8)>>>(J);
    }
    copyinit_k<<<(262144 + 255) / 256, 256>>>(of, ocatA, hf, hcatA, nsp);

    for (int it = 0; it < 2; it++) {
        float* hc_in = it ? hcatB : hcatA;
        float* hc_out = it ? hcatA : hcatB;
        float* oc_in = it ? ocatB : ocatA;
        float* oc_out = it ? ocatA : ocatB;
        if (it == 1) zero2_k<<<(671744 + 255) / 256, 256>>>(Af, Aof, adjp);

        // B1: A_h, A_o, obj
        {
            GJobs J; int total = 0; J.njobs = 3;
            add_job(J, 0, hf, 0, 0, 2048, a1hi, a1lo, b_a1, Af, 0, 2048, NHUM, 2048, 2048, 8, 0, total);
            add_job(J, 1, of, 0, 0, 2048, a1hi + (size_t)2048 * 2048, a1lo + (size_t)2048 * 2048,
                    0, Aof, 0, 2048, NOBJ, 2048, 2048, 8, 0, total);
            add_job(J, 2, of, 0, 0, 2048, omhi, omlo, b_om, obj, 0, 1024, NOBJ, 1024, 1024, 8, 0, total);
            gemm_jobs_k<<<total, 256, GM_SMEM>>>(J);
        }
        cvt_k<<<(655360 + 255) / 256, 256>>>(Af, Aof, Ahh, Aoh);

        // pair GEMM -> adjp (64-row tiles)
        pair_mma_k<<<dim3(8, 256), 256, PR_SMEM>>>(Ahh, Aoh, a2h, b_a2, W_a3, adjp);

        // aggo: hc_in right; zero hf-left, hum, hc_out-left
        aggo_k<<<dim3(8, NHUM), 128>>>(adjp, b_a3, obj, nssa, hc_in, hc_out, hf, hum);

        // h_upd (dual-write hf-left + hc_out-left) + hum (composed weights)
        {
            GJobs J; int total = 0; J.njobs = 2;
            add_job(J, 0, hc_in, 0, 0, 2048, huhi, hulo, 0, hf, hc_out, 2048, NHUM, 1024, 2048, 16, 0, total);
            add_job(J, 1, hc_in, 0, 0, 2048, huhmhi, huhmlo, b_hm, hum, 0, 1024, NHUM, 1024, 2048, 16, 0, total);
            gemm_jobs_k<<<total, 256, GM_SMEM>>>(J);
        }

        // aggh: oc_in right; zero of-left, obj, oc_out-left
        aggh_k<<<dim3(8, NOBJ), 128>>>(adjp, b_a3, hum, nssa, oc_in, oc_out, of, obj);

        // o_upd: dual-write of-left + oc_out-left
        {
            GJobs J; int total = 0; J.njobs = 1;
            add_job(J, 0, oc_in, 0, 0, 2048, ouhi, oulo, 0, of, oc_out, 2048, NOBJ, 1024, 2048, 16, 0, total);
            gemm_jobs_k<<<total, 256, GM_SMEM>>>(J);
        }
    }

    // ---- final gather ----
    out_k<<<NKEEP, 256>>>(hf, of, adjp, b_a3, scores, labels, cmask, (float*)d_out);
}

// round 13
// speedup vs baseline: 1.6608x; 1.6608x over previous
#include <cuda_runtime.h>
#include <cuda_bf16.h>
#include <cuda_fp16.h>
#include <math.h>
#include <stdint.h>

// ---------------- problem constants ----------------
#define NOBJ 256
#define NHUM 64
#define EDIM 1024
#define NPAIR 16384
#define NKEEP 16320
#define OUTC 4213
#define NCLS 117

// ---------------- scratch ----------------
__device__ float g_enc1[NOBJ*EDIM];
__device__ float g_nssa[NOBJ*EDIM];
__device__ float g_Af[NHUM*2048];
__device__ float g_Aof[NOBJ*2048];
__device__ __half g_Ahh[NHUM*2048];
__device__ __half g_Aoh[NOBJ*2048];
__device__ float g_adjp[NPAIR];
__device__ float g_obj[NOBJ*EDIM];
__device__ float g_hum[NHUM*EDIM];
__device__ float g_hf[NHUM*2048];     // [h_enc | h_sp]
__device__ float g_hcat[NHUM*2048];   // [h_enc | agg_o]
__device__ float g_of[NOBJ*2048];     // [enc | nsp]
__device__ float g_ocat[NOBJ*2048];   // [enc | agg_h]
__device__ float g_whuhm[2048*1024];  // W_hu @ W_hm (fp32)
__device__ int   g_mask_mode;

// pre-split transposed weights [n][k]
__device__ __nv_bfloat16 g_bh1hi[1024*12544];
__device__ __nv_bfloat16 g_bh1lo[1024*12544];
__device__ __nv_bfloat16 g_bh2hi[1024*1024];
__device__ __nv_bfloat16 g_bh2lo[1024*1024];
__device__ __nv_bfloat16 g_sahi[1024*1024];
__device__ __nv_bfloat16 g_salo[1024*1024];
__device__ __nv_bfloat16 g_omhi[1024*1024];
__device__ __nv_bfloat16 g_omlo[1024*1024];
__device__ __nv_bfloat16 g_hmhi[1024*1024];
__device__ __nv_bfloat16 g_hmlo[1024*1024];
__device__ __nv_bfloat16 g_a1hi[2*2048*2048];
__device__ __nv_bfloat16 g_a1lo[2*2048*2048];
__device__ __nv_bfloat16 g_huhi[1024*2048];
__device__ __nv_bfloat16 g_hulo[1024*2048];
__device__ __nv_bfloat16 g_ouhi[1024*2048];
__device__ __nv_bfloat16 g_oulo[1024*2048];
__device__ __nv_bfloat16 g_huhmhi[1024*2048];  // (W_hu@W_hm)^T split
__device__ __nv_bfloat16 g_huhmlo[1024*2048];
__device__ __half        g_a2h[1024*2048];
__device__ __nv_bfloat16 g_boxhi[NOBJ*12544];
__device__ __nv_bfloat16 g_boxlo[NOBJ*12544];

__device__ __forceinline__ uint32_t smem_u32(const void* p) {
    uint32_t a;
    asm("{ .reg .u64 t; cvta.to.shared.u64 t, %1; cvt.u32.u64 %0, t; }" : "=r"(a) : "l"(p));
    return a;
}
__device__ __forceinline__ void cpasync16(uint32_t saddr, const void* g) {
    asm volatile("{ .reg .u64 gg; cvta.to.global.u64 gg, %1; "
                 "cp.async.cg.shared.global [%0], [gg], 16; }"
                 :: "r"(saddr), "l"(g));
}
#define CP_COMMIT() asm volatile("cp.async.commit_group;")
#define CP_WAIT0()  asm volatile("cp.async.wait_group 0;")

// ================= mma.sync helpers =================
__device__ __forceinline__ void mma_bf16(float* c, const uint32_t* a, const uint32_t* b)
{
    asm volatile("mma.sync.aligned.m16n8k16.row.col.f32.bf16.bf16.f32 "
                 "{%0,%1,%2,%3}, {%4,%5,%6,%7}, {%8,%9}, {%0,%1,%2,%3};"
                 : "+f"(c[0]), "+f"(c[1]), "+f"(c[2]), "+f"(c[3])
                 : "r"(a[0]), "r"(a[1]), "r"(a[2]), "r"(a[3]), "r"(b[0]), "r"(b[1]));
}
__device__ __forceinline__ void mma_f16(float* c, const uint32_t* a, const uint32_t* b)
{
    asm volatile("mma.sync.aligned.m16n8k16.row.col.f32.f16.f16.f32 "
                 "{%0,%1,%2,%3}, {%4,%5,%6,%7}, {%8,%9}, {%0,%1,%2,%3};"
                 : "+f"(c[0]), "+f"(c[1]), "+f"(c[2]), "+f"(c[3])
                 : "r"(a[0]), "r"(a[1]), "r"(a[2]), "r"(a[3]), "r"(b[0]), "r"(b[1]));
}
__device__ __forceinline__ void ldmx4(uint32_t* d, uint32_t addr)
{
    asm volatile("ldmatrix.sync.aligned.m8n8.x4.shared.b16 {%0,%1,%2,%3}, [%4];"
                 : "=r"(d[0]), "=r"(d[1]), "=r"(d[2]), "=r"(d[3]) : "r"(addr));
}
__device__ __forceinline__ void ldmx2(uint32_t* d, uint32_t addr)
{
    asm volatile("ldmatrix.sync.aligned.m8n8.x2.shared.b16 {%0,%1}, [%2];"
                 : "=r"(d[0]), "=r"(d[1]) : "r"(addr));
}

// bf16 hi/lo 3-pass chunk: 128x128 tile, K=64, stride 144B
__device__ __forceinline__ void mma_chunk(uint32_t abase_hi, uint32_t abase_lo,
                                          uint32_t wbase_hi, uint32_t wbase_lo,
                                          float acc[4][4][4], int lid,
                                          int warp_row, int warp_col)
{
    #pragma unroll
    for (int ks = 0; ks < 4; ks++) {
        const int kk = ks * 16;
        uint32_t bh[4][2], bl[4][2];
        const int l2 = lid & 15;
        const uint32_t bro = (uint32_t)((l2 & 7) * 144 + (kk + ((l2 & 8) ? 8 : 0)) * 2);
        #pragma unroll
        for (int an = 0; an < 4; an++) {
            uint32_t nbase = (uint32_t)((warp_col * 32 + an * 8) * 144);
            ldmx2(bh[an], wbase_hi + nbase + bro);
            ldmx2(bl[an], wbase_lo + nbase + bro);
        }
        const uint32_t aro = (uint32_t)((lid & 15) * 144 + (kk + ((lid & 16) ? 8 : 0)) * 2);
        #pragma unroll
        for (int am = 0; am < 4; am++) {
            uint32_t mbase = (uint32_t)((warp_row * 64 + am * 16) * 144);
            uint32_t ah4[4], al4[4];
            ldmx4(ah4, abase_hi + mbase + aro);
            ldmx4(al4, abase_lo + mbase + aro);
            #pragma unroll
            for (int an = 0; an < 4; an++) {
                mma_bf16(acc[am][an], ah4, bh[an]);
                mma_bf16(acc[am][an], ah4, bl[an]);
                mma_bf16(acc[am][an], al4, bh[an]);
            }
        }
    }
}

// ---------------- batched weight conversions ----------------
struct CvJobs {
    const float* W[10];
    void* hi[10];
    __nv_bfloat16* lo[10];
    int K[10];
    int N[10];
    int b0[10];
    int njobs;
};

__global__ void convall_k(CvJobs J)
{
    __shared__ float t[32][33];
    int bid = blockIdx.x;
    int j = 0;
    #pragma unroll
    for (int q = 1; q < 10; q++)
        if (q < J.njobs && bid >= J.b0[q]) j = q;
    int local = bid - J.b0[j];
    int K = J.K[j], N = J.N[j];
    int kblocks = K >> 5;
    int kb = (local % kblocks) * 32;
    int nb = (local / kblocks) * 32;
    const float* W = J.W[j];
    int tx = threadIdx.x, ty = threadIdx.y;
    #pragma unroll
    for (int i = 0; i < 4; i++)
        t[ty + 8 * i][tx] = W[(size_t)(kb + ty + 8 * i) * N + nb + tx];
    __syncthreads();
    if (J.lo[j]) {
        __nv_bfloat16* hi = (__nv_bfloat16*)J.hi[j];
        __nv_bfloat16* lo = J.lo[j];
        #pragma unroll
        for (int i = 0; i < 4; i++) {
            float v = t[tx][ty + 8 * i];
            __nv_bfloat16 h = __float2bfloat16(v);
            size_t oi = (size_t)(nb + ty + 8 * i) * K + kb + tx;
            hi[oi] = h;
            lo[oi] = __float2bfloat16(v - __bfloat162float(h));
        }
    } else {
        __half* out = (__half*)J.hi[j];
        #pragma unroll
        for (int i = 0; i < 4; i++)
            out[(size_t)(nb + ty + 8 * i) * K + kb + tx] = __float2half_rn(t[tx][ty + 8 * i]);
    }
}

__global__ void convA_k(const float* __restrict__ src, __nv_bfloat16* __restrict__ hi,
                        __nv_bfloat16* __restrict__ lo, int n)
{
    int base = (blockIdx.x * 256 + threadIdx.x) * 8;
    if (base >= n) return;
    float4 a = *(const float4*)(src + base);
    float4 b = *(const float4*)(src + base + 4);
    float v[8] = { a.x, a.y, a.z, a.w, b.x, b.y, b.z, b.w };
    __nv_bfloat16 hv[8], lv[8];
    #pragma unroll
    for (int i = 0; i < 8; i++) {
        hv[i] = __float2bfloat16(v[i]);
        lv[i] = __float2bfloat16(v[i] - __bfloat162float(hv[i]));
    }
    *(uint4*)(hi + base) = *(uint4*)hv;
    *(uint4*)(lo + base) = *(uint4*)lv;
}

// ================= unified jobs GEMM =================
#define GM_AHI 0
#define GM_ALO 18432
#define GM_WHI 36864
#define GM_WLO 55296
#define GM_SMEM 73728

struct GJobs {
    const float* A[3];
    const __nv_bfloat16* Ahi[3];
    const __nv_bfloat16* Alo[3];
    const __nv_bfloat16* Bhi[3];
    const __nv_bfloat16* Blo[3];
    const float* bias[3];
    float* C[3];
    int lda[3], ldc[3], M[3], N[3], K[3], kslice[3], b0[3], gx[3], gy[3], reluA[3];
    int njobs;
};

__device__ void gemm_body(const float* __restrict__ A,
                          const __nv_bfloat16* __restrict__ A16h,
                          const __nv_bfloat16* __restrict__ A16l, int lda,
                          const __nv_bfloat16* __restrict__ Bhi,
                          const __nv_bfloat16* __restrict__ Blo,
                          const float* __restrict__ bias, float* __restrict__ C,
                          int ldc, int M, int N, int K, int kslice, int reluA,
                          int bx, int by, int bz, char* smem)
{
    uint32_t sb = smem_u32(smem);
    const int tid = threadIdx.x;
    const int wid = tid >> 5, lid = tid & 31;
    const int col0 = bx * 128;
    const int row0 = by * 128;
    const int kstart = bz * kslice;
    const int warp_row = wid >> 2, warp_col = wid & 3;

    const int r = tid >> 1, kh = tid & 1;
    int arow = row0 + r; if (arow >= M) arow = M - 1;
    const __nv_bfloat16* whp = Bhi + (size_t)(col0 + r) * K + kstart + kh * 32;
    const __nv_bfloat16* wlp = Blo + (size_t)(col0 + r) * K + kstart + kh * 32;
    const uint32_t soff = (uint32_t)(r * 144 + kh * 64);

    float acc[4][4][4];
    #pragma unroll
    for (int i = 0; i < 4; i++)
        #pragma unroll
        for (int j = 0; j < 4; j++)
            #pragma unroll
            for (int q = 0; q < 4; q++) acc[i][j][q] = 0.f;

    const int nchunk = kslice >> 6;
    if (A16h) {
        const __nv_bfloat16* ahp = A16h + (size_t)arow * lda + kstart + kh * 32;
        const __nv_bfloat16* alp = A16l + (size_t)arow * lda + kstart + kh * 32;
        for (int c = 0; c < nchunk; c++) {
            const int k0 = c * 64;
            __syncthreads();
            #pragma unroll
            for (int j = 0; j < 4; j++) {
                cpasync16(sb + GM_WHI + soff + j * 16, whp + k0 + j * 8);
                cpasync16(sb + GM_WLO + soff + j * 16, wlp + k0 + j * 8);
            }
            #pragma unroll
            for (int j = 0; j < 4; j++) {
                cpasync16(sb + GM_AHI + soff + j * 16, ahp + k0 + j * 8);
                cpasync16(sb + GM_ALO + soff + j * 16, alp + k0 + j * 8);
            }
            CP_COMMIT();
            CP_WAIT0();
            __syncthreads();
            mma_chunk(sb + GM_AHI, sb + GM_ALO, sb + GM_WHI, sb + GM_WLO,
                      acc, lid, warp_row, warp_col);
        }
    } else {
        const float* agp = A + (size_t)arow * lda + kstart + kh * 32;
        for (int c = 0; c < nchunk; c++) {
            const int k0 = c * 64;
            __syncthreads();
            #pragma unroll
            for (int j = 0; j < 4; j++) {
                cpasync16(sb + GM_WHI + soff + j * 16, whp + k0 + j * 8);
                cpasync16(sb + GM_WLO + soff + j * 16, wlp + k0 + j * 8);
            }
            CP_COMMIT();
            const float4* p = (const float4*)(agp + k0);
            #pragma unroll
            for (int j = 0; j < 8; j++) {
                float4 a = p[j];
                if (reluA) {
                    a.x = fmaxf(a.x, 0.f); a.y = fmaxf(a.y, 0.f);
                    a.z = fmaxf(a.z, 0.f); a.w = fmaxf(a.w, 0.f);
                }
                __nv_bfloat16 h0 = __float2bfloat16(a.x), h1 = __float2bfloat16(a.y);
                __nv_bfloat16 h2 = __float2bfloat16(a.z), h3 = __float2bfloat16(a.w);
                __nv_bfloat162 hw0 = __nv_bfloat162(h0, h1), hw1 = __nv_bfloat162(h2, h3);
                __nv_bfloat162 lw0 = __nv_bfloat162(__float2bfloat16(a.x - __bfloat162float(h0)),
                                                    __float2bfloat16(a.y - __bfloat162float(h1)));
                __nv_bfloat162 lw1 = __nv_bfloat162(__float2bfloat16(a.z - __bfloat162float(h2)),
                                                    __float2bfloat16(a.w - __bfloat162float(h3)));
                *(uint2*)(smem + GM_AHI + soff + j * 8) = make_uint2(*(uint32_t*)&hw0, *(uint32_t*)&hw1);
                *(uint2*)(smem + GM_ALO + soff + j * 8) = make_uint2(*(uint32_t*)&lw0, *(uint32_t*)&lw1);
            }
            CP_WAIT0();
            __syncthreads();
            mma_chunk(sb + GM_AHI, sb + GM_ALO, sb + GM_WHI, sb + GM_WLO,
                      acc, lid, warp_row, warp_col);
        }
    }

    #pragma unroll
    for (int am = 0; am < 4; am++) {
        #pragma unroll
        for (int q = 0; q < 4; q++) {
            int row = row0 + warp_row * 64 + am * 16 + (lid >> 2) + ((q >= 2) ? 8 : 0);
            if (row >= M) continue;
            #pragma unroll
            for (int an = 0; an < 4; an++) {
                int col = col0 + warp_col * 32 + an * 8 + (lid & 3) * 2 + (q & 1);
                float v = acc[am][an][q];
                if (bz == 0 && bias) v += bias[col];
                atomicAdd(C + (size_t)row * ldc + col, v);
            }
        }
    }
}

__global__ void __launch_bounds__(256, 2)
gemm_jobs_k(GJobs J)
{
    extern __shared__ char smem[];
    int bid = blockIdx.x;
    int j = 0;
    #pragma unroll
    for (int q = 1; q < 3; q++)
        if (q < J.njobs && bid >= J.b0[q]) j = q;
    int local = bid - J.b0[j];
    int gxy = J.gx[j] * J.gy[j];
    int bz = local / gxy;
    int rem = local % gxy;
    int by = rem / J.gx[j];
    int bx = rem % J.gx[j];
    gemm_body(J.A[j], J.Ahi[j], J.Alo[j], J.lda[j], J.Bhi[j], J.Blo[j], J.bias[j], J.C[j],
              J.ldc[j], J.M[j], J.N[j], J.K[j], J.kslice[j], J.reluA[j],
              bx, by, bz, smem);
}

// ================= fp16 pair MMA: single-sync pipelined (128-row tiles) =================
#define PR_AHS   0
#define PR_ST0   4096
#define PR_A     0
#define PR_W     18432
#define PR_STAGE 36864
#define PR_RED   77824
#define PR_B2    78336
#define PR_W3    78848
#define PR_SMEM  79360

__global__ void __launch_bounds__(256, 2)
pair_mma_k(const __half* __restrict__ Ahh, const __half* __restrict__ Aoh,
           const __half* __restrict__ Wt, const float* __restrict__ b2,
           const float* __restrict__ w3, float* __restrict__ adjp)
{
    extern __shared__ char smem[];
    uint32_t sb = smem_u32(smem);
    const int tid = threadIdx.x;
    const int wid = tid >> 5, lid = tid & 31;
    const int col0 = blockIdx.x * 128;
    const int row0 = blockIdx.y * 128;
    const int h = row0 >> 8;
    const int nb = row0 & 255;
    const int warp_row = wid >> 2, warp_col = wid & 3;

    if (tid < 128) {
        *(float*)(smem + PR_B2 + tid * 4) = b2[col0 + tid];
        *(float*)(smem + PR_W3 + tid * 4) = w3[col0 + tid];
        *(float*)(smem + PR_RED + tid * 4) = 0.f;
    }
    *(uint4*)(smem + PR_AHS + tid * 16) = *(const uint4*)(Ahh + h * 2048 + tid * 8);

    const int r = tid >> 1, kh = tid & 1;
    const __half* aop = Aoh + (size_t)(nb + r) * 2048 + kh * 32;
    const __half* whp = Wt + (size_t)(col0 + r) * 2048 + kh * 32;
    const uint32_t soff = (uint32_t)(r * 144 + kh * 64);

    float acc[4][4][4];
    #pragma unroll
    for (int i = 0; i < 4; i++)
        #pragma unroll
        for (int j = 0; j < 4; j++)
            #pragma unroll
            for (int q = 0; q < 4; q++) acc[i][j][q] = 0.f;

    {
        uint32_t stb = sb + PR_ST0;
        #pragma unroll
        for (int j = 0; j < 2; j++) {
            cpasync16(stb + PR_A + soff + j * 16, aop + j * 8);
            cpasync16(stb + PR_A + soff + 32 + j * 16, aop + 16 + j * 8);
            cpasync16(stb + PR_W + soff + j * 16, whp + j * 8);
            cpasync16(stb + PR_W + soff + 32 + j * 16, whp + 16 + j * 8);
        }
        CP_COMMIT();
    }
    __syncthreads();

    const __half2 hz = __floats2half2_rn(0.f, 0.f);
    const int n_off = ((lid >> 4) & 1) * 8 + (lid & 7);
    const int kb_ = ((lid >> 3) & 1) * 8;

    for (int c = 0; c < 32; c++) {
        const int cur = c & 1;
        CP_WAIT0();
        {
            char* av = smem + PR_ST0 + cur * PR_STAGE + PR_A + soff;
            const uint4* ahq = (const uint4*)(smem + PR_AHS + (c * 64 + kh * 32) * 2);
            #pragma unroll
            for (int j = 0; j < 4; j++) {
                uint4 vo = *(uint4*)(av + j * 16);
                uint4 vh = ahq[j];
                __half2 r0 = __hmax2(__hadd2(*(__half2*)&vo.x, *(__half2*)&vh.x), hz);
                __half2 r1 = __hmax2(__hadd2(*(__half2*)&vo.y, *(__half2*)&vh.y), hz);
                __half2 r2 = __hmax2(__hadd2(*(__half2*)&vo.z, *(__half2*)&vh.z), hz);
                __half2 r3 = __hmax2(__hadd2(*(__half2*)&vo.w, *(__half2*)&vh.w), hz);
                *(uint4*)(av + j * 16) = make_uint4(*(uint32_t*)&r0, *(uint32_t*)&r1,
                                                    *(uint32_t*)&r2, *(uint32_t*)&r3);
            }
        }
        __syncthreads();
        if (c < 31) {
            uint32_t stb = sb + PR_ST0 + (cur ^ 1) * PR_STAGE;
            const int kn = (c + 1) * 64;
            #pragma unroll
            for (int j = 0; j < 2; j++) {
                cpasync16(stb + PR_A + soff + j * 16, aop + kn + j * 8);
                cpasync16(stb + PR_A + soff + 32 + j * 16, aop + kn + 16 + j * 8);
                cpasync16(stb + PR_W + soff + j * 16, whp + kn + j * 8);
                cpasync16(stb + PR_W + soff + 32 + j * 16, whp + kn + 16 + j * 8);
            }
            CP_COMMIT();
        }
        uint32_t abase = sb + PR_ST0 + cur * PR_STAGE + PR_A;
        uint32_t wbase = sb + PR_ST0 + cur * PR_STAGE + PR_W;
        #pragma unroll
        for (int ks = 0; ks < 4; ks++) {
            const int kk = ks * 16;
            uint32_t b[4][2];
            #pragma unroll
            for (int anp = 0; anp < 2; anp++) {
                uint32_t t[4];
                ldmx4(t, wbase + (uint32_t)((warp_col * 32 + anp * 16 + n_off) * 144
                                            + (kk + kb_) * 2));
                b[anp * 2][0] = t[0]; b[anp * 2][1] = t[1];
                b[anp * 2 + 1][0] = t[2]; b[anp * 2 + 1][1] = t[3];
            }
            const uint32_t aro = (uint32_t)((lid & 15) * 144 + (kk + ((lid & 16) ? 8 : 0)) * 2);
            #pragma unroll
            for (int am = 0; am < 4; am++) {
                uint32_t a4[4];
                ldmx4(a4, abase + (uint32_t)((warp_row * 64 + am * 16) * 144) + aro);
                #pragma unroll
                for (int an = 0; an < 4; an++)
                    mma_f16(acc[am][an], a4, b[an]);
            }
        }
    }

    const float* b2s = (const float*)(smem + PR_B2);
    const float* w3s = (const float*)(smem + PR_W3);
    float* sred = (float*)(smem + PR_RED);
    #pragma unroll
    for (int am = 0; am < 4; am++) {
        float pl = 0.f, ph = 0.f;
        #pragma unroll
        for (int an = 0; an < 4; an++) {
            int cb = warp_col * 32 + an * 8 + 2 * (lid & 3);
            float w0 = w3s[cb], w1 = w3s[cb + 1];
            float bb0 = b2s[cb], bb1 = b2s[cb + 1];
            pl += fmaxf(acc[am][an][0] + bb0, 0.f) * w0 + fmaxf(acc[am][an][1] + bb1, 0.f) * w1;
            ph += fmaxf(acc[am][an][2] + bb0, 0.f) * w0 + fmaxf(acc[am][an][3] + bb1, 0.f) * w1;
        }
        pl += __shfl_xor_sync(0xffffffffu, pl, 1);
        pl += __shfl_xor_sync(0xffffffffu, pl, 2);
        ph += __shfl_xor_sync(0xffffffffu, ph, 1);
        ph += __shfl_xor_sync(0xffffffffu, ph, 2);
        if ((lid & 3) == 0) {
            int rloc = warp_row * 64 + am * 16 + (lid >> 2);
            atomicAdd(sred + rloc, pl);
            atomicAdd(sred + rloc + 8, ph);
        }
    }
    __syncthreads();
    if (tid < 128) atomicAdd(adjp + row0 + tid, sred[tid]);
}

// ---------------- small fused kernels ----------------
__device__ __forceinline__ float sigf(float z) { return 1.f / (1.f + expf(-z)); }

__global__ void zeroinit_k(float* enc1, float* Af, float* Aof, float* obj,
                           float* hum, float* adjp, float* nssa, float* of,
                           float* whuhm)
{
    int i = blockIdx.x * 256 + threadIdx.x;
    if (i < 262144) enc1[i] = 0.f;
    else if (i < 393216) Af[i - 262144] = 0.f;
    else if (i < 917504) Aof[i - 393216] = 0.f;
    else if (i < 1179648) obj[i - 917504] = 0.f;
    else if (i < 1245184) hum[i - 1179648] = 0.f;
    else if (i < 1261568) adjp[i - 1245184] = 0.f;
    else if (i < 1523712) nssa[i - 1261568] = 0.f;
    else if (i < 1785856) {
        int j = i - 1523712;
        of[(j >> 10) * 2048 + (j & 1023)] = 0.f;
    }
    else if (i < 3883008) whuhm[i - 1785856] = 0.f;
}

__global__ void zero2_k(float* Af, float* Aof, float* adjp)
{
    int i = blockIdx.x * 256 + threadIdx.x;
    if (i < 131072) Af[i] = 0.f;
    else if (i < 655360) Aof[i - 131072] = 0.f;
    else if (i < 671744) adjp[i - 655360] = 0.f;
}

__global__ void copyinit_k(float* of, float* ocat, float* hf, float* hcat,
                           const float* __restrict__ nsp)
{
    int i = blockIdx.x * 256 + threadIdx.x;
    if (i >= 262144) return;
    int r = i >> 10, c = i & 1023;
    float e = fmaxf(of[r * 2048 + c], 0.f);
    of[r * 2048 + c] = e;
    float s = nsp[i];
    of[r * 2048 + 1024 + c] = s;
    ocat[r * 2048 + c] = e;
    if (r < 64) {
        hf[r * 2048 + c] = e;
        hf[r * 2048 + 1024 + c] = s;
        hcat[r * 2048 + c] = e;
    }
}

__global__ void cvt_k(const float* __restrict__ Af, const float* __restrict__ Aof,
                      __half* __restrict__ Ahh, __half* __restrict__ Aoh)
{
    int i = blockIdx.x * 256 + threadIdx.x;
    if (i < 131072) Ahh[i] = __float2half_rn(Af[i]);
    else if (i < 655360) Aoh[i - 131072] = __float2half_rn(Aof[i - 131072]);
}

__global__ void copy2d_k(float* __restrict__ dst, int dls, const float* __restrict__ src,
                         int sls, int rows, int cols)
{
    int i = blockIdx.x * blockDim.x + threadIdx.x;
    if (i < rows * cols) {
        int r = i / cols, c = i % cols;
        dst[r * dls + c] = src[r * sls + c];
    }
}

__global__ void aggo_k(const float* __restrict__ adjp, const float* __restrict__ b3,
                       const float* __restrict__ obj, const float* __restrict__ nssa,
                       float* __restrict__ hcat, float* __restrict__ hf,
                       float* __restrict__ hum)
{
    int h = blockIdx.y;
    int e = blockIdx.x * 128 + threadIdx.x;
    __shared__ float sa[256];
    float b3v = b3[0];
    for (int i = threadIdx.x; i < 256; i += 128)
        sa[i] = sigf(adjp[h * 256 + i] + b3v);
    __syncthreads();
    float a1 = 0.f, a2 = 0.f;
    #pragma unroll 4
    for (int n = 0; n < 256; n++) {
        float a = sa[n];
        float om = fmaxf(obj[n * 1024 + e], 0.f);
        float ns = nssa[n * 1024 + e];
        a1 += a * om;
        a2 += a * om * ns;
    }
    hcat[h * 2048 + 1024 + e] = nssa[h * 1024 + e] * a1 - a2;
    hf[h * 2048 + e] = 0.f;
    hum[h * 1024 + e] = 0.f;
}

__global__ void aggh_k(const float* __restrict__ adjp, const float* __restrict__ b3,
                       const float* __restrict__ hum, const float* __restrict__ nssa,
                       float* __restrict__ ocat, float* __restrict__ of,
                       float* __restrict__ obj)
{
    int n = blockIdx.y;
    int e = blockIdx.x * 128 + threadIdx.x;
    __shared__ float sa[64];
    float b3v = b3[0];
    if (threadIdx.x < 64) sa[threadIdx.x] = sigf(adjp[threadIdx.x * 256 + n] + b3v);
    __syncthreads();
    float a1 = 0.f, a2 = 0.f;
    #pragma unroll 4
    for (int h = 0; h < 64; h++) {
        float a = sa[h];
        float hm = fmaxf(hum[h * 1024 + e], 0.f);
        float hs = nssa[h * 1024 + e];
        a1 += a * hm;
        a2 += a * hm * hs;
    }
    ocat[n * 2048 + 1024 + e] = nssa[n * 1024 + e] * a1 - a2;
    of[n * 2048 + e] = 0.f;
    obj[n * 1024 + e] = 0.f;
}

__global__ void detect_k(const unsigned char* __restrict__ cm)
{
    __shared__ int s_f, s_nz;
    if (threadIdx.x == 0) { s_f = 0; s_nz = 0; }
    __syncthreads();
    int lf = 0, lnz = 0;
    for (int i = threadIdx.x; i < 9360; i += blockDim.x) {
        unsigned char b = cm[i];
        int m4 = i & 3;
        if (m4 == 3 && b == 0x3F) lf = 1;
        if (m4 != 0 && b != 0) lnz = 1;
    }
    if (lf) atomicOr(&s_f, 1);
    if (lnz) atomicOr(&s_nz, 1);
    __syncthreads();
    if (threadIdx.x == 0) g_mask_mode = s_f ? 2 : (s_nz ? 0 : 1);
}

__device__ __forceinline__ float lisf(float x)
{
    return 8.3f / (1.f + expf(12.f - 10.f * x));
}

__global__ void out_k(const float* __restrict__ hf, const float* __restrict__ of,
                      const float* __restrict__ adjp, const float* __restrict__ b3,
                      const float* __restrict__ scores, const int* __restrict__ labels,
                      const void* __restrict__ cmask, float* __restrict__ out)
{
    int p = blockIdx.x;
    int x = p / 255;
    int r = p % 255;
    int y = (r < x) ? r : r + 1;

    float scale = sigf(adjp[x * 256 + y] + b3[0]) * lisf(scores[x]) * lisf(scores[y]);
    int lab = labels[y];
    int mode = g_mask_mode;

    const float* hx = hf + x * 2048;
    const float* oy = of + y * 2048;
    float* o = out + (size_t)p * OUTC;

    for (int c = threadIdx.x; c < OUTC; c += blockDim.x) {
        float v;
        if (c < 2048)       v = hx[c];
        else if (c < 4096)  v = oy[c - 2048];
        else {
            int j = c - 4096;
            float m;
            if (mode == 0)      m = ((const unsigned char*)cmask)[lab * NCLS + j] ? 1.f : 0.f;
            else if (mode == 1) m = ((const int*)cmask)[lab * NCLS + j] ? 1.f : 0.f;
            else                m = ((const float*)cmask)[lab * NCLS + j];
            v = scale * m;
        }
        o[c] = v;
    }
}

// ---------------- host ----------------
static void add_job(GJobs& J, int idx, const float* A,
                    const __nv_bfloat16* Ahi, const __nv_bfloat16* Alo, int lda,
                    const __nv_bfloat16* Bhi, const __nv_bfloat16* Blo,
                    const float* bias, float* C, int ldc,
                    int M, int N, int K, int nk, int reluA, int& total)
{
    int gx = N / 128, gy = (M + 127) / 128;
    J.A[idx] = A; J.Ahi[idx] = Ahi; J.Alo[idx] = Alo;
    J.Bhi[idx] = Bhi; J.Blo[idx] = Blo; J.bias[idx] = bias;
    J.C[idx] = C; J.lda[idx] = lda; J.ldc[idx] = ldc;
    J.M[idx] = M; J.N[idx] = N; J.K[idx] = K; J.kslice[idx] = K / nk;
    J.gx[idx] = gx; J.gy[idx] = gy; J.b0[idx] = total; J.reluA[idx] = reluA;
    total += gx * gy * nk;
}

extern "C" void kernel_launch(void* const* d_in, const int* in_sizes, int n_in,
                              void* d_out, int out_size)
{
    const float *box = 0, *nsp = 0, *scores = 0;
    const int *labels = 0;
    const void *cmask = 0;
    const float *W_bh1 = 0, *b_bh1 = 0, *W_bh2 = 0, *b_bh2 = 0, *W_sa = 0;
    const float *W_a1 = 0, *b_a1 = 0, *W_a2 = 0, *b_a2 = 0, *W_a3 = 0, *b_a3 = 0;
    const float *W_hm = 0, *b_hm = 0, *W_om = 0, *b_om = 0, *W_hu = 0, *W_ou = 0;

    int c256 = 0, c1k = 0, c1m = 0, c2m = 0;
    for (int i = 0; i < n_in; i++) {
        const void* p = d_in[i];
        switch (in_sizes[i]) {
            case 3211264:  box = (const float*)p; break;
            case 262144:   nsp = (const float*)p; break;
            case 256:      if (c256++ == 0) scores = (const float*)p; else labels = (const int*)p; break;
            case 9360:     cmask = p; break;
            case 12845056: W_bh1 = (const float*)p; break;
            case 1024:
                switch (c1k++) {
                    case 0: b_bh1 = (const float*)p; break;
                    case 1: b_bh2 = (const float*)p; break;
                    case 2: b_a2  = (const float*)p; break;
                    case 3: W_a3  = (const float*)p; break;
                    case 4: b_hm  = (const float*)p; break;
                    case 5: b_om  = (const float*)p; break;
                } break;
            case 1048576:
                switch (c1m++) {
                    case 0: W_bh2 = (const float*)p; break;
                    case 1: W_sa  = (const float*)p; break;
                    case 2: W_hm  = (const float*)p; break;
                    case 3: W_om  = (const float*)p; break;
                } break;
            case 8388608:  W_a1 = (const float*)p; break;
            case 2048:     b_a1 = (const float*)p; break;
            case 2097152:
                switch (c2m++) {
                    case 0: W_a2 = (const float*)p; break;
                    case 1: W_hu = (const float*)p; break;
                    case 2: W_ou = (const float*)p; break;
                } break;
            case 1:        b_a3 = (const float*)p; break;
            default: break;
        }
    }

    float *enc1, *nssa, *Af, *Aof, *adjp, *obj, *hum, *hf, *hcat, *of, *ocat, *whuhm;
    __half *Ahh, *Aoh;
    cudaGetSymbolAddress((void**)&enc1, g_enc1);
    cudaGetSymbolAddress((void**)&nssa, g_nssa);
    cudaGetSymbolAddress((void**)&Af,   g_Af);
    cudaGetSymbolAddress((void**)&Aof,  g_Aof);
    cudaGetSymbolAddress((void**)&Ahh,  g_Ahh);
    cudaGetSymbolAddress((void**)&Aoh,  g_Aoh);
    cudaGetSymbolAddress((void**)&adjp, g_adjp);
    cudaGetSymbolAddress((void**)&obj,  g_obj);
    cudaGetSymbolAddress((void**)&hum,  g_hum);
    cudaGetSymbolAddress((void**)&hf,   g_hf);
    cudaGetSymbolAddress((void**)&hcat, g_hcat);
    cudaGetSymbolAddress((void**)&of,   g_of);
    cudaGetSymbolAddress((void**)&ocat, g_ocat);
    cudaGetSymbolAddress((void**)&whuhm, g_whuhm);

    __nv_bfloat16 *bh1hi, *bh1lo, *bh2hi, *bh2lo, *sahi, *salo, *omhi, *omlo, *hmhi, *hmlo;
    __nv_bfloat16 *a1hi, *a1lo, *huhi, *hulo, *ouhi, *oulo, *boxhi, *boxlo, *huhmhi, *huhmlo;
    __half *a2h;
    cudaGetSymbolAddress((void**)&bh1hi, g_bh1hi);
    cudaGetSymbolAddress((void**)&bh1lo, g_bh1lo);
    cudaGetSymbolAddress((void**)&bh2hi, g_bh2hi);
    cudaGetSymbolAddress((void**)&bh2lo, g_bh2lo);
    cudaGetSymbolAddress((void**)&sahi,  g_sahi);
    cudaGetSymbolAddress((void**)&salo,  g_salo);
    cudaGetSymbolAddress((void**)&omhi,  g_omhi);
    cudaGetSymbolAddress((void**)&omlo,  g_omlo);
    cudaGetSymbolAddress((void**)&hmhi,  g_hmhi);
    cudaGetSymbolAddress((void**)&hmlo,  g_hmlo);
    cudaGetSymbolAddress((void**)&a1hi,  g_a1hi);
    cudaGetSymbolAddress((void**)&a1lo,  g_a1lo);
    cudaGetSymbolAddress((void**)&huhi,  g_huhi);
    cudaGetSymbolAddress((void**)&hulo,  g_hulo);
    cudaGetSymbolAddress((void**)&ouhi,  g_ouhi);
    cudaGetSymbolAddress((void**)&oulo,  g_oulo);
    cudaGetSymbolAddress((void**)&huhmhi, g_huhmhi);
    cudaGetSymbolAddress((void**)&huhmlo, g_huhmlo);
    cudaGetSymbolAddress((void**)&a2h,   g_a2h);
    cudaGetSymbolAddress((void**)&boxhi, g_boxhi);
    cudaGetSymbolAddress((void**)&boxlo, g_boxlo);

    cudaFuncSetAttribute(pair_mma_k, cudaFuncAttributeMaxDynamicSharedMemorySize, PR_SMEM);
    cudaFuncSetAttribute(gemm_jobs_k, cudaFuncAttributeMaxDynamicSharedMemorySize, GM_SMEM);

    detect_k<<<1, 256>>>((const unsigned char*)cmask);

    // ---- batched weight conversions + box pre-split ----
    {
        CvJobs J;
        J.njobs = 10;
        const float* Ws[10] = { W_bh1, W_a1, W_a1 + (size_t)2048 * 2048, W_bh2, W_sa,
                                W_om, W_hm, W_hu, W_ou, W_a2 };
        void* his[10] = { bh1hi, a1hi, a1hi + (size_t)2048 * 2048, bh2hi, sahi,
                          omhi, hmhi, huhi, ouhi, a2h };
        __nv_bfloat16* los[10] = { bh1lo, a1lo, a1lo + (size_t)2048 * 2048, bh2lo, salo,
                                   omlo, hmlo, hulo, oulo, 0 };
        int Ks[10] = { 12544, 2048, 2048, 1024, 1024, 1024, 1024, 2048, 2048, 2048 };
        int Ns[10] = { 1024, 2048, 2048, 1024, 1024, 1024, 1024, 1024, 1024, 1024 };
        int total = 0;
        for (int j = 0; j < 10; j++) {
            J.W[j] = Ws[j]; J.hi[j] = his[j]; J.lo[j] = los[j];
            J.K[j] = Ks[j]; J.N[j] = Ns[j];
            J.b0[j] = total;
            total += (Ks[j] >> 5) * (Ns[j] >> 5);
        }
        convall_k<<<total, dim3(32, 8)>>>(J);
    }
    convA_k<<<3211264 / 2048, 256>>>(box, boxhi, boxlo, 3211264);

    zeroinit_k<<<(3883008 + 255) / 256, 256>>>(enc1, Af, Aof, obj, hum, adjp, nssa, of, whuhm);

    // ---- encoder + W_huhm composition ----
    {
        GJobs J; int total = 0; J.njobs = 1;
        add_job(J, 0, 0, boxhi, boxlo, 12544, bh1hi, bh1lo, b_bh1, enc1, 1024,
                NOBJ, 1024, 12544, 28, 0, total);
        gemm_jobs_k<<<total, 256, GM_SMEM>>>(J);
    }
    {
        GJobs J; int total = 0; J.njobs = 3;
        add_job(J, 0, enc1, 0, 0, 1024, bh2hi, bh2lo, b_bh2, of, 2048, NOBJ, 1024, 1024, 4, 1, total);
        add_job(J, 1, nsp, 0, 0, 1024, sahi, salo, 0, nssa, 1024, NOBJ, 1024, 1024, 4, 0, total);
        add_job(J, 2, W_hu, 0, 0, 1024, hmhi, hmlo, 0, whuhm, 1024, 2048, 1024, 1024, 1, 0, total);
        gemm_jobs_k<<<total, 256, GM_SMEM>>>(J);
    }
    // split W_huhm -> bf16 hi/lo (transposed)
    {
        CvJobs J;
        J.njobs = 1;
        J.W[0] = whuhm; J.hi[0] = huhmhi; J.lo[0] = huhmlo;
        J.K[0] = 2048; J.N[0] = 1024; J.b0[0] = 0;
        convall_k<<<(2048 >> 5) * (1024 >> 5), dim3(32, 8)>>>(J);
    }
    copyinit_k<<<(262144 + 255) / 256, 256>>>(of, ocat, hf, hcat, nsp);

    for (int it = 0; it < 2; it++) {
        if (it == 1) zero2_k<<<(671744 + 255) / 256, 256>>>(Af, Aof, adjp);

        // B1: A_h, A_o, obj (independent)
        {
            GJobs J; int total = 0; J.njobs = 3;
            add_job(J, 0, hf, 0, 0, 2048, a1hi, a1lo, b_a1, Af, 2048, NHUM, 2048, 2048, 8, 0, total);
            add_job(J, 1, of, 0, 0, 2048, a1hi + (size_t)2048 * 2048, a1lo + (size_t)2048 * 2048,
                    0, Aof, 2048, NOBJ, 2048, 2048, 8, 0, total);
            add_job(J, 2, of, 0, 0, 2048, omhi, omlo, b_om, obj, 1024, NOBJ, 1024, 1024, 8, 0, total);
            gemm_jobs_k<<<total, 256, GM_SMEM>>>(J);
        }
        cvt_k<<<(655360 + 255) / 256, 256>>>(Af, Aof, Ahh, Aoh);

        // pair GEMM -> adjp (128-row tiles, proven config)
        pair_mma_k<<<dim3(8, 128), 256, PR_SMEM>>>(Ahh, Aoh, a2h, b_a2, W_a3, adjp);

        // aggo: hcat right; zero hf-left, hum
        aggo_k<<<dim3(8, NHUM), 128>>>(adjp, b_a3, obj, nssa, hcat, hf, hum);

        // h_upd + hum (composed weights) — one batch, both read hcat
        {
            GJobs J; int total = 0; J.njobs = 2;
            add_job(J, 0, hcat, 0, 0, 2048, huhi, hulo, 0, hf, 2048, NHUM, 1024, 2048, 16, 0, total);
            add_job(J, 1, hcat, 0, 0, 2048, huhmhi, huhmlo, b_hm, hum, 1024, NHUM, 1024, 2048, 16, 0, total);
            gemm_jobs_k<<<total, 256, GM_SMEM>>>(J);
        }
        copy2d_k<<<(NHUM * 1024 + 255) / 256, 256>>>(hcat, 2048, hf, 2048, NHUM, 1024);

        // aggh: ocat right; zero of-left, obj
        aggh_k<<<dim3(8, NOBJ), 128>>>(adjp, b_a3, hum, nssa, ocat, of, obj);

        // o_upd
        {
            GJobs J; int total = 0; J.njobs = 1;
            add_job(J, 0, ocat, 0, 0, 2048, ouhi, oulo, 0, of, 2048, NOBJ, 1024, 2048, 16, 0, total);
            gemm_jobs_k<<<total, 256, GM_SMEM>>>(J);
        }
        copy2d_k<<<(NOBJ * 1024 + 255) / 256, 256>>>(ocat, 2048, of, 2048, NOBJ, 1024);
    }

    // ---- final gather ----
    out_k<<<NKEEP, 256>>>(hf, of, adjp, b_a3, scores, labels, cmask, (float*)d_out);
}

// round 14
// speedup vs baseline: 1.8159x; 1.0934x over previous
#include <cuda_runtime.h>
#include <cuda_bf16.h>
#include <cuda_fp16.h>
#include <math.h>
#include <stdint.h>

// ---------------- problem constants ----------------
#define NOBJ 256
#define NHUM 64
#define EDIM 1024
#define NPAIR 16384
#define NKEEP 16320
#define OUTC 4213
#define NCLS 117

// ---------------- scratch ----------------
__device__ float g_enc1[NOBJ*EDIM];
__device__ float g_nssa[NOBJ*EDIM];
__device__ float g_Af[NHUM*2048];
__device__ float g_Aof[NOBJ*2048];
__device__ __half g_Ahh[NHUM*2048];
__device__ __half g_Aoh[NOBJ*2048];
__device__ float g_adjp[NPAIR];
__device__ float g_obj[NOBJ*EDIM];
__device__ float g_hum[NHUM*EDIM];
__device__ float g_hf[NHUM*2048];      // [h_enc | h_sp]
__device__ float g_hcatA[NHUM*2048];   // [h_enc | agg_o] ping
__device__ float g_hcatB[NHUM*2048];   // pong
__device__ float g_of[NOBJ*2048];      // [enc | nsp]
__device__ float g_ocatA[NOBJ*2048];
__device__ float g_ocatB[NOBJ*2048];
__device__ int   g_mask_mode;

// pre-split transposed weights [n][k]
__device__ __nv_bfloat16 g_bh1hi[1024*12544];
__device__ __nv_bfloat16 g_bh1lo[1024*12544];
__device__ __nv_bfloat16 g_bh2hi[1024*1024];
__device__ __nv_bfloat16 g_bh2lo[1024*1024];
__device__ __nv_bfloat16 g_sahi[1024*1024];
__device__ __nv_bfloat16 g_salo[1024*1024];
__device__ __nv_bfloat16 g_omhi[1024*1024];
__device__ __nv_bfloat16 g_omlo[1024*1024];
__device__ __nv_bfloat16 g_hmhi[1024*1024];
__device__ __nv_bfloat16 g_hmlo[1024*1024];
__device__ __nv_bfloat16 g_a1hi[2*2048*2048];
__device__ __nv_bfloat16 g_a1lo[2*2048*2048];
__device__ __nv_bfloat16 g_huhi[1024*2048];
__device__ __nv_bfloat16 g_hulo[1024*2048];
__device__ __nv_bfloat16 g_ouhi[1024*2048];
__device__ __nv_bfloat16 g_oulo[1024*2048];
__device__ __half        g_a2h[1024*2048];
__device__ __nv_bfloat16 g_boxhi[NOBJ*12544];
__device__ __nv_bfloat16 g_boxlo[NOBJ*12544];

__device__ __forceinline__ uint32_t smem_u32(const void* p) {
    uint32_t a;
    asm("{ .reg .u64 t; cvta.to.shared.u64 t, %1; cvt.u32.u64 %0, t; }" : "=r"(a) : "l"(p));
    return a;
}
__device__ __forceinline__ void cpasync16(uint32_t saddr, const void* g) {
    asm volatile("{ .reg .u64 gg; cvta.to.global.u64 gg, %1; "
                 "cp.async.cg.shared.global [%0], [gg], 16; }"
                 :: "r"(saddr), "l"(g));
}
#define CP_COMMIT() asm volatile("cp.async.commit_group;")
#define CP_WAIT0()  asm volatile("cp.async.wait_group 0;")

// ================= mma.sync helpers =================
__device__ __forceinline__ void mma_bf16(float* c, const uint32_t* a, const uint32_t* b)
{
    asm volatile("mma.sync.aligned.m16n8k16.row.col.f32.bf16.bf16.f32 "
                 "{%0,%1,%2,%3}, {%4,%5,%6,%7}, {%8,%9}, {%0,%1,%2,%3};"
                 : "+f"(c[0]), "+f"(c[1]), "+f"(c[2]), "+f"(c[3])
                 : "r"(a[0]), "r"(a[1]), "r"(a[2]), "r"(a[3]), "r"(b[0]), "r"(b[1]));
}
__device__ __forceinline__ void mma_f16(float* c, const uint32_t* a, const uint32_t* b)
{
    asm volatile("mma.sync.aligned.m16n8k16.row.col.f32.f16.f16.f32 "
                 "{%0,%1,%2,%3}, {%4,%5,%6,%7}, {%8,%9}, {%0,%1,%2,%3};"
                 : "+f"(c[0]), "+f"(c[1]), "+f"(c[2]), "+f"(c[3])
                 : "r"(a[0]), "r"(a[1]), "r"(a[2]), "r"(a[3]), "r"(b[0]), "r"(b[1]));
}
__device__ __forceinline__ void ldmx4(uint32_t* d, uint32_t addr)
{
    asm volatile("ldmatrix.sync.aligned.m8n8.x4.shared.b16 {%0,%1,%2,%3}, [%4];"
                 : "=r"(d[0]), "=r"(d[1]), "=r"(d[2]), "=r"(d[3]) : "r"(addr));
}
__device__ __forceinline__ void ldmx2(uint32_t* d, uint32_t addr)
{
    asm volatile("ldmatrix.sync.aligned.m8n8.x2.shared.b16 {%0,%1}, [%2];"
                 : "=r"(d[0]), "=r"(d[1]) : "r"(addr));
}

// bf16 hi/lo 3-pass chunk: 128x128 tile, K=64, stride 144B
__device__ __forceinline__ void mma_chunk(uint32_t abase_hi, uint32_t abase_lo,
                                          uint32_t wbase_hi, uint32_t wbase_lo,
                                          float acc[4][4][4], int lid,
                                          int warp_row, int warp_col)
{
    #pragma unroll
    for (int ks = 0; ks < 4; ks++) {
        const int kk = ks * 16;
        uint32_t bh[4][2], bl[4][2];
        const int l2 = lid & 15;
        const uint32_t bro = (uint32_t)((l2 & 7) * 144 + (kk + ((l2 & 8) ? 8 : 0)) * 2);
        #pragma unroll
        for (int an = 0; an < 4; an++) {
            uint32_t nbase = (uint32_t)((warp_col * 32 + an * 8) * 144);
            ldmx2(bh[an], wbase_hi + nbase + bro);
            ldmx2(bl[an], wbase_lo + nbase + bro);
        }
        const uint32_t aro = (uint32_t)((lid & 15) * 144 + (kk + ((lid & 16) ? 8 : 0)) * 2);
        #pragma unroll
        for (int am = 0; am < 4; am++) {
            uint32_t mbase = (uint32_t)((warp_row * 64 + am * 16) * 144);
            uint32_t ah4[4], al4[4];
            ldmx4(ah4, abase_hi + mbase + aro);
            ldmx4(al4, abase_lo + mbase + aro);
            #pragma unroll
            for (int an = 0; an < 4; an++) {
                mma_bf16(acc[am][an], ah4, bh[an]);
                mma_bf16(acc[am][an], ah4, bl[an]);
                mma_bf16(acc[am][an], al4, bh[an]);
            }
        }
    }
}

// ---------------- batched weight conversions ----------------
struct CvJobs {
    const float* W[10];
    void* hi[10];
    __nv_bfloat16* lo[10];
    int K[10];
    int N[10];
    int b0[10];
    int njobs;
};

__global__ void convall_k(CvJobs J)
{
    __shared__ float t[32][33];
    int bid = blockIdx.x;
    int j = 0;
    #pragma unroll
    for (int q = 1; q < 10; q++)
        if (q < J.njobs && bid >= J.b0[q]) j = q;
    int local = bid - J.b0[j];
    int K = J.K[j], N = J.N[j];
    int kblocks = K >> 5;
    int kb = (local % kblocks) * 32;
    int nb = (local / kblocks) * 32;
    const float* W = J.W[j];
    int tx = threadIdx.x, ty = threadIdx.y;
    #pragma unroll
    for (int i = 0; i < 4; i++)
        t[ty + 8 * i][tx] = W[(size_t)(kb + ty + 8 * i) * N + nb + tx];
    __syncthreads();
    if (J.lo[j]) {
        __nv_bfloat16* hi = (__nv_bfloat16*)J.hi[j];
        __nv_bfloat16* lo = J.lo[j];
        #pragma unroll
        for (int i = 0; i < 4; i++) {
            float v = t[tx][ty + 8 * i];
            __nv_bfloat16 h = __float2bfloat16(v);
            size_t oi = (size_t)(nb + ty + 8 * i) * K + kb + tx;
            hi[oi] = h;
            lo[oi] = __float2bfloat16(v - __bfloat162float(h));
        }
    } else {
        __half* out = (__half*)J.hi[j];
        #pragma unroll
        for (int i = 0; i < 4; i++)
            out[(size_t)(nb + ty + 8 * i) * K + kb + tx] = __float2half_rn(t[tx][ty + 8 * i]);
    }
}

__global__ void convA_k(const float* __restrict__ src, __nv_bfloat16* __restrict__ hi,
                        __nv_bfloat16* __restrict__ lo, int n)
{
    int base = (blockIdx.x * 256 + threadIdx.x) * 8;
    if (base >= n) return;
    float4 a = *(const float4*)(src + base);
    float4 b = *(const float4*)(src + base + 4);
    float v[8] = { a.x, a.y, a.z, a.w, b.x, b.y, b.z, b.w };
    __nv_bfloat16 hv[8], lv[8];
    #pragma unroll
    for (int i = 0; i < 8; i++) {
        hv[i] = __float2bfloat16(v[i]);
        lv[i] = __float2bfloat16(v[i] - __bfloat162float(hv[i]));
    }
    *(uint4*)(hi + base) = *(uint4*)hv;
    *(uint4*)(lo + base) = *(uint4*)lv;
}

// ================= unified jobs GEMM =================
#define GM_AHI 0
#define GM_ALO 18432
#define GM_WHI 36864
#define GM_WLO 55296
#define GM_SMEM 73728

struct GJobs {
    const float* A[3];
    const __nv_bfloat16* Ahi[3];
    const __nv_bfloat16* Alo[3];
    const __nv_bfloat16* Bhi[3];
    const __nv_bfloat16* Blo[3];
    const float* bias[3];
    float* C[3];
    float* C2[3];   // optional second atomic target (same ldc)
    int lda[3], ldc[3], M[3], N[3], K[3], kslice[3], b0[3], gx[3], gy[3], reluA[3];
    int njobs;
};

__device__ void gemm_body(const float* __restrict__ A,
                          const __nv_bfloat16* __restrict__ A16h,
                          const __nv_bfloat16* __restrict__ A16l, int lda,
                          const __nv_bfloat16* __restrict__ Bhi,
                          const __nv_bfloat16* __restrict__ Blo,
                          const float* __restrict__ bias, float* __restrict__ C,
                          float* __restrict__ C2,
                          int ldc, int M, int N, int K, int kslice, int reluA,
                          int bx, int by, int bz, char* smem)
{
    uint32_t sb = smem_u32(smem);
    const int tid = threadIdx.x;
    const int wid = tid >> 5, lid = tid & 31;
    const int col0 = bx * 128;
    const int row0 = by * 128;
    const int kstart = bz * kslice;
    const int warp_row = wid >> 2, warp_col = wid & 3;

    const int r = tid >> 1, kh = tid & 1;
    int arow = row0 + r; if (arow >= M) arow = M - 1;
    const __nv_bfloat16* whp = Bhi + (size_t)(col0 + r) * K + kstart + kh * 32;
    const __nv_bfloat16* wlp = Blo + (size_t)(col0 + r) * K + kstart + kh * 32;
    const uint32_t soff = (uint32_t)(r * 144 + kh * 64);

    float acc[4][4][4];
    #pragma unroll
    for (int i = 0; i < 4; i++)
        #pragma unroll
        for (int j = 0; j < 4; j++)
            #pragma unroll
            for (int q = 0; q < 4; q++) acc[i][j][q] = 0.f;

    const int nchunk = kslice >> 6;
    if (A16h) {
        const __nv_bfloat16* ahp = A16h + (size_t)arow * lda + kstart + kh * 32;
        const __nv_bfloat16* alp = A16l + (size_t)arow * lda + kstart + kh * 32;
        for (int c = 0; c < nchunk; c++) {
            const int k0 = c * 64;
            __syncthreads();
            #pragma unroll
            for (int j = 0; j < 4; j++) {
                cpasync16(sb + GM_WHI + soff + j * 16, whp + k0 + j * 8);
                cpasync16(sb + GM_WLO + soff + j * 16, wlp + k0 + j * 8);
            }
            #pragma unroll
            for (int j = 0; j < 4; j++) {
                cpasync16(sb + GM_AHI + soff + j * 16, ahp + k0 + j * 8);
                cpasync16(sb + GM_ALO + soff + j * 16, alp + k0 + j * 8);
            }
            CP_COMMIT();
            CP_WAIT0();
            __syncthreads();
            mma_chunk(sb + GM_AHI, sb + GM_ALO, sb + GM_WHI, sb + GM_WLO,
                      acc, lid, warp_row, warp_col);
        }
    } else {
        const float* agp = A + (size_t)arow * lda + kstart + kh * 32;
        for (int c = 0; c < nchunk; c++) {
            const int k0 = c * 64;
            __syncthreads();
            #pragma unroll
            for (int j = 0; j < 4; j++) {
                cpasync16(sb + GM_WHI + soff + j * 16, whp + k0 + j * 8);
                cpasync16(sb + GM_WLO + soff + j * 16, wlp + k0 + j * 8);
            }
            CP_COMMIT();
            const float4* p = (const float4*)(agp + k0);
            #pragma unroll
            for (int j = 0; j < 8; j++) {
                float4 a = p[j];
                if (reluA) {
                    a.x = fmaxf(a.x, 0.f); a.y = fmaxf(a.y, 0.f);
                    a.z = fmaxf(a.z, 0.f); a.w = fmaxf(a.w, 0.f);
                }
                __nv_bfloat16 h0 = __float2bfloat16(a.x), h1 = __float2bfloat16(a.y);
                __nv_bfloat16 h2 = __float2bfloat16(a.z), h3 = __float2bfloat16(a.w);
                __nv_bfloat162 hw0 = __nv_bfloat162(h0, h1), hw1 = __nv_bfloat162(h2, h3);
                __nv_bfloat162 lw0 = __nv_bfloat162(__float2bfloat16(a.x - __bfloat162float(h0)),
                                                    __float2bfloat16(a.y - __bfloat162float(h1)));
                __nv_bfloat162 lw1 = __nv_bfloat162(__float2bfloat16(a.z - __bfloat162float(h2)),
                                                    __float2bfloat16(a.w - __bfloat162float(h3)));
                *(uint2*)(smem + GM_AHI + soff + j * 8) = make_uint2(*(uint32_t*)&hw0, *(uint32_t*)&hw1);
                *(uint2*)(smem + GM_ALO + soff + j * 8) = make_uint2(*(uint32_t*)&lw0, *(uint32_t*)&lw1);
            }
            CP_WAIT0();
            __syncthreads();
            mma_chunk(sb + GM_AHI, sb + GM_ALO, sb + GM_WHI, sb + GM_WLO,
                      acc, lid, warp_row, warp_col);
        }
    }

    #pragma unroll
    for (int am = 0; am < 4; am++) {
        #pragma unroll
        for (int q = 0; q < 4; q++) {
            int row = row0 + warp_row * 64 + am * 16 + (lid >> 2) + ((q >= 2) ? 8 : 0);
            if (row >= M) continue;
            #pragma unroll
            for (int an = 0; an < 4; an++) {
                int col = col0 + warp_col * 32 + an * 8 + (lid & 3) * 2 + (q & 1);
                float v = acc[am][an][q];
                if (bz == 0 && bias) v += bias[col];
                size_t idx = (size_t)row * ldc + col;
                atomicAdd(C + idx, v);
                if (C2) atomicAdd(C2 + idx, v);
            }
        }
    }
}

__global__ void __launch_bounds__(256, 2)
gemm_jobs_k(GJobs J)
{
    extern __shared__ char smem[];
    int bid = blockIdx.x;
    int j = 0;
    #pragma unroll
    for (int q = 1; q < 3; q++)
        if (q < J.njobs && bid >= J.b0[q]) j = q;
    int local = bid - J.b0[j];
    int gxy = J.gx[j] * J.gy[j];
    int bz = local / gxy;
    int rem = local % gxy;
    int by = rem / J.gx[j];
    int bx = rem % J.gx[j];
    gemm_body(J.A[j], J.Ahi[j], J.Alo[j], J.lda[j], J.Bhi[j], J.Blo[j], J.bias[j], J.C[j],
              J.C2[j], J.ldc[j], J.M[j], J.N[j], J.K[j], J.kslice[j], J.reluA[j],
              bx, by, bz, smem);
}

// ================= fp16 pair MMA: single-sync pipelined (128-row tiles) =================
#define PR_AHS   0
#define PR_ST0   4096
#define PR_A     0
#define PR_W     18432
#define PR_STAGE 36864
#define PR_RED   77824
#define PR_B2    78336
#define PR_W3    78848
#define PR_SMEM  79360

__global__ void __launch_bounds__(256, 2)
pair_mma_k(const __half* __restrict__ Ahh, const __half* __restrict__ Aoh,
           const __half* __restrict__ Wt, const float* __restrict__ b2,
           const float* __restrict__ w3, float* __restrict__ adjp)
{
    extern __shared__ char smem[];
    uint32_t sb = smem_u32(smem);
    const int tid = threadIdx.x;
    const int wid = tid >> 5, lid = tid & 31;
    const int col0 = blockIdx.x * 128;
    const int row0 = blockIdx.y * 128;
    const int h = row0 >> 8;
    const int nb = row0 & 255;
    const int warp_row = wid >> 2, warp_col = wid & 3;

    if (tid < 128) {
        *(float*)(smem + PR_B2 + tid * 4) = b2[col0 + tid];
        *(float*)(smem + PR_W3 + tid * 4) = w3[col0 + tid];
        *(float*)(smem + PR_RED + tid * 4) = 0.f;
    }
    *(uint4*)(smem + PR_AHS + tid * 16) = *(const uint4*)(Ahh + h * 2048 + tid * 8);

    const int r = tid >> 1, kh = tid & 1;
    const __half* aop = Aoh + (size_t)(nb + r) * 2048 + kh * 32;
    const __half* whp = Wt + (size_t)(col0 + r) * 2048 + kh * 32;
    const uint32_t soff = (uint32_t)(r * 144 + kh * 64);

    float acc[4][4][4];
    #pragma unroll
    for (int i = 0; i < 4; i++)
        #pragma unroll
        for (int j = 0; j < 4; j++)
            #pragma unroll
            for (int q = 0; q < 4; q++) acc[i][j][q] = 0.f;

    {
        uint32_t stb = sb + PR_ST0;
        #pragma unroll
        for (int j = 0; j < 2; j++) {
            cpasync16(stb + PR_A + soff + j * 16, aop + j * 8);
            cpasync16(stb + PR_A + soff + 32 + j * 16, aop + 16 + j * 8);
            cpasync16(stb + PR_W + soff + j * 16, whp + j * 8);
            cpasync16(stb + PR_W + soff + 32 + j * 16, whp + 16 + j * 8);
        }
        CP_COMMIT();
    }
    __syncthreads();

    const __half2 hz = __floats2half2_rn(0.f, 0.f);
    const int n_off = ((lid >> 4) & 1) * 8 + (lid & 7);
    const int kb_ = ((lid >> 3) & 1) * 8;

    for (int c = 0; c < 32; c++) {
        const int cur = c & 1;
        CP_WAIT0();
        {
            char* av = smem + PR_ST0 + cur * PR_STAGE + PR_A + soff;
            const uint4* ahq = (const uint4*)(smem + PR_AHS + (c * 64 + kh * 32) * 2);
            #pragma unroll
            for (int j = 0; j < 4; j++) {
                uint4 vo = *(uint4*)(av + j * 16);
                uint4 vh = ahq[j];
                __half2 r0 = __hmax2(__hadd2(*(__half2*)&vo.x, *(__half2*)&vh.x), hz);
                __half2 r1 = __hmax2(__hadd2(*(__half2*)&vo.y, *(__half2*)&vh.y), hz);
                __half2 r2 = __hmax2(__hadd2(*(__half2*)&vo.z, *(__half2*)&vh.z), hz);
                __half2 r3 = __hmax2(__hadd2(*(__half2*)&vo.w, *(__half2*)&vh.w), hz);
                *(uint4*)(av + j * 16) = make_uint4(*(uint32_t*)&r0, *(uint32_t*)&r1,
                                                    *(uint32_t*)&r2, *(uint32_t*)&r3);
            }
        }
        __syncthreads();
        if (c < 31) {
            uint32_t stb = sb + PR_ST0 + (cur ^ 1) * PR_STAGE;
            const int kn = (c + 1) * 64;
            #pragma unroll
            for (int j = 0; j < 2; j++) {
                cpasync16(stb + PR_A + soff + j * 16, aop + kn + j * 8);
                cpasync16(stb + PR_A + soff + 32 + j * 16, aop + kn + 16 + j * 8);
                cpasync16(stb + PR_W + soff + j * 16, whp + kn + j * 8);
                cpasync16(stb + PR_W + soff + 32 + j * 16, whp + kn + 16 + j * 8);
            }
            CP_COMMIT();
        }
        uint32_t abase = sb + PR_ST0 + cur * PR_STAGE + PR_A;
        uint32_t wbase = sb + PR_ST0 + cur * PR_STAGE + PR_W;
        #pragma unroll
        for (int ks = 0; ks < 4; ks++) {
            const int kk = ks * 16;
            uint32_t b[4][2];
            #pragma unroll
            for (int anp = 0; anp < 2; anp++) {
                uint32_t t[4];
                ldmx4(t, wbase + (uint32_t)((warp_col * 32 + anp * 16 + n_off) * 144
                                            + (kk + kb_) * 2));
                b[anp * 2][0] = t[0]; b[anp * 2][1] = t[1];
                b[anp * 2 + 1][0] = t[2]; b[anp * 2 + 1][1] = t[3];
            }
            const uint32_t aro = (uint32_t)((lid & 15) * 144 + (kk + ((lid & 16) ? 8 : 0)) * 2);
            #pragma unroll
            for (int am = 0; am < 4; am++) {
                uint32_t a4[4];
                ldmx4(a4, abase + (uint32_t)((warp_row * 64 + am * 16) * 144) + aro);
                #pragma unroll
                for (int an = 0; an < 4; an++)
                    mma_f16(acc[am][an], a4, b[an]);
            }
        }
    }

    const float* b2s = (const float*)(smem + PR_B2);
    const float* w3s = (const float*)(smem + PR_W3);
    float* sred = (float*)(smem + PR_RED);
    #pragma unroll
    for (int am = 0; am < 4; am++) {
        float pl = 0.f, ph = 0.f;
        #pragma unroll
        for (int an = 0; an < 4; an++) {
            int cb = warp_col * 32 + an * 8 + 2 * (lid & 3);
            float w0 = w3s[cb], w1 = w3s[cb + 1];
            float bb0 = b2s[cb], bb1 = b2s[cb + 1];
            pl += fmaxf(acc[am][an][0] + bb0, 0.f) * w0 + fmaxf(acc[am][an][1] + bb1, 0.f) * w1;
            ph += fmaxf(acc[am][an][2] + bb0, 0.f) * w0 + fmaxf(acc[am][an][3] + bb1, 0.f) * w1;
        }
        pl += __shfl_xor_sync(0xffffffffu, pl, 1);
        pl += __shfl_xor_sync(0xffffffffu, pl, 2);
        ph += __shfl_xor_sync(0xffffffffu, ph, 1);
        ph += __shfl_xor_sync(0xffffffffu, ph, 2);
        if ((lid & 3) == 0) {
            int rloc = warp_row * 64 + am * 16 + (lid >> 2);
            atomicAdd(sred + rloc, pl);
            atomicAdd(sred + rloc + 8, ph);
        }
    }
    __syncthreads();
    if (tid < 128) atomicAdd(adjp + row0 + tid, sred[tid]);
}

// ---------------- small fused kernels ----------------
__device__ __forceinline__ float sigf(float z) { return 1.f / (1.f + expf(-z)); }

__global__ void zeroinit_k(float* enc1, float* Af, float* Aof, float* obj,
                           float* hum, float* adjp, float* nssa, float* of)
{
    int i = blockIdx.x * 256 + threadIdx.x;
    if (i < 262144) enc1[i] = 0.f;
    else if (i < 393216) Af[i - 262144] = 0.f;
    else if (i < 917504) Aof[i - 393216] = 0.f;
    else if (i < 1179648) obj[i - 917504] = 0.f;
    else if (i < 1245184) hum[i - 1179648] = 0.f;
    else if (i < 1261568) adjp[i - 1245184] = 0.f;
    else if (i < 1523712) nssa[i - 1261568] = 0.f;
    else if (i < 1785856) {
        int j = i - 1523712;
        of[(j >> 10) * 2048 + (j & 1023)] = 0.f;
    }
}

__global__ void zero2_k(float* Af, float* Aof, float* adjp)
{
    int i = blockIdx.x * 256 + threadIdx.x;
    if (i < 131072) Af[i] = 0.f;
    else if (i < 655360) Aof[i - 131072] = 0.f;
    else if (i < 671744) adjp[i - 655360] = 0.f;
}

__global__ void copyinit_k(float* of, float* ocat, float* hf, float* hcat,
                           const float* __restrict__ nsp)
{
    int i = blockIdx.x * 256 + threadIdx.x;
    if (i >= 262144) return;
    int r = i >> 10, c = i & 1023;
    float e = fmaxf(of[r * 2048 + c], 0.f);
    of[r * 2048 + c] = e;
    float s = nsp[i];
    of[r * 2048 + 1024 + c] = s;
    ocat[r * 2048 + c] = e;
    if (r < 64) {
        hf[r * 2048 + c] = e;
        hf[r * 2048 + 1024 + c] = s;
        hcat[r * 2048 + c] = e;
    }
}

__global__ void cvt_k(const float* __restrict__ Af, const float* __restrict__ Aof,
                      __half* __restrict__ Ahh, __half* __restrict__ Aoh)
{
    int i = blockIdx.x * 256 + threadIdx.x;
    if (i < 131072) Ahh[i] = __float2half_rn(Af[i]);
    else if (i < 655360) Aoh[i - 131072] = __float2half_rn(Aof[i - 131072]);
}

// aggo: writes hcat_in-right; zeroes hf-left, hum, hcat_out-left
__global__ void aggo_k(const float* __restrict__ adjp, const float* __restrict__ b3,
                       const float* __restrict__ obj, const float* __restrict__ nssa,
                       float* __restrict__ hcat_in, float* __restrict__ hcat_out,
                       float* __restrict__ hf, float* __restrict__ hum)
{
    int h = blockIdx.y;
    int e = blockIdx.x * 128 + threadIdx.x;
    __shared__ float sa[256];
    float b3v = b3[0];
    for (int i = threadIdx.x; i < 256; i += 128)
        sa[i] = sigf(adjp[h * 256 + i] + b3v);
    __syncthreads();
    float a1 = 0.f, a2 = 0.f;
    #pragma unroll 4
    for (int n = 0; n < 256; n++) {
        float a = sa[n];
        float om = fmaxf(obj[n * 1024 + e], 0.f);
        float ns = nssa[n * 1024 + e];
        a1 += a * om;
        a2 += a * om * ns;
    }
    hcat_in[h * 2048 + 1024 + e] = nssa[h * 1024 + e] * a1 - a2;
    hcat_out[h * 2048 + e] = 0.f;
    hf[h * 2048 + e] = 0.f;
    hum[h * 1024 + e] = 0.f;
}

// aggh: writes ocat_in-right; zeroes of-left, obj, ocat_out-left
__global__ void aggh_k(const float* __restrict__ adjp, const float* __restrict__ b3,
                       const float* __restrict__ hum, const float* __restrict__ nssa,
                       float* __restrict__ ocat_in, float* __restrict__ ocat_out,
                       float* __restrict__ of, float* __restrict__ obj)
{
    int n = blockIdx.y;
    int e = blockIdx.x * 128 + threadIdx.x;
    __shared__ float sa[64];
    float b3v = b3[0];
    if (threadIdx.x < 64) sa[threadIdx.x] = sigf(adjp[threadIdx.x * 256 + n] + b3v);
    __syncthreads();
    float a1 = 0.f, a2 = 0.f;
    #pragma unroll 4
    for (int h = 0; h < 64; h++) {
        float a = sa[h];
        float hm = fmaxf(hum[h * 1024 + e], 0.f);
        float hs = nssa[h * 1024 + e];
        a1 += a * hm;
        a2 += a * hm * hs;
    }
    ocat_in[n * 2048 + 1024 + e] = nssa[n * 1024 + e] * a1 - a2;
    ocat_out[n * 2048 + e] = 0.f;
    of[n * 2048 + e] = 0.f;
    obj[n * 1024 + e] = 0.f;
}

__global__ void detect_k(const unsigned char* __restrict__ cm)
{
    __shared__ int s_f, s_nz;
    if (threadIdx.x == 0) { s_f = 0; s_nz = 0; }
    __syncthreads();
    int lf = 0, lnz = 0;
    for (int i = threadIdx.x; i < 9360; i += blockDim.x) {
        unsigned char b = cm[i];
        int m4 = i & 3;
        if (m4 == 3 && b == 0x3F) lf = 1;
        if (m4 != 0 && b != 0) lnz = 1;
    }
    if (lf) atomicOr(&s_f, 1);
    if (lnz) atomicOr(&s_nz, 1);
    __syncthreads();
    if (threadIdx.x == 0) g_mask_mode = s_f ? 2 : (s_nz ? 0 : 1);
}

__device__ __forceinline__ float lisf(float x)
{
    return 8.3f / (1.f + expf(12.f - 10.f * x));
}

__global__ void out_k(const float* __restrict__ hf, const float* __restrict__ of,
                      const float* __restrict__ adjp, const float* __restrict__ b3,
                      const float* __restrict__ scores, const int* __restrict__ labels,
                      const void* __restrict__ cmask, float* __restrict__ out)
{
    int p = blockIdx.x;
    int x = p / 255;
    int r = p % 255;
    int y = (r < x) ? r : r + 1;

    float scale = sigf(adjp[x * 256 + y] + b3[0]) * lisf(scores[x]) * lisf(scores[y]);
    int lab = labels[y];
    int mode = g_mask_mode;

    const float* hx = hf + x * 2048;
    const float* oy = of + y * 2048;
    float* o = out + (size_t)p * OUTC;

    for (int c = threadIdx.x; c < OUTC; c += blockDim.x) {
        float v;
        if (c < 2048)       v = hx[c];
        else if (c < 4096)  v = oy[c - 2048];
        else {
            int j = c - 4096;
            float m;
            if (mode == 0)      m = ((const unsigned char*)cmask)[lab * NCLS + j] ? 1.f : 0.f;
            else if (mode == 1) m = ((const int*)cmask)[lab * NCLS + j] ? 1.f : 0.f;
            else                m = ((const float*)cmask)[lab * NCLS + j];
            v = scale * m;
        }
        o[c] = v;
    }
}

// ---------------- host ----------------
static void add_job(GJobs& J, int idx, const float* A,
                    const __nv_bfloat16* Ahi, const __nv_bfloat16* Alo, int lda,
                    const __nv_bfloat16* Bhi, const __nv_bfloat16* Blo,
                    const float* bias, float* C, float* C2, int ldc,
                    int M, int N, int K, int nk, int reluA, int& total)
{
    int gx = N / 128, gy = (M + 127) / 128;
    J.A[idx] = A; J.Ahi[idx] = Ahi; J.Alo[idx] = Alo;
    J.Bhi[idx] = Bhi; J.Blo[idx] = Blo; J.bias[idx] = bias;
    J.C[idx] = C; J.C2[idx] = C2; J.lda[idx] = lda; J.ldc[idx] = ldc;
    J.M[idx] = M; J.N[idx] = N; J.K[idx] = K; J.kslice[idx] = K / nk;
    J.gx[idx] = gx; J.gy[idx] = gy; J.b0[idx] = total; J.reluA[idx] = reluA;
    total += gx * gy * nk;
}

extern "C" void kernel_launch(void* const* d_in, const int* in_sizes, int n_in,
                              void* d_out, int out_size)
{
    const float *box = 0, *nsp = 0, *scores = 0;
    const int *labels = 0;
    const void *cmask = 0;
    const float *W_bh1 = 0, *b_bh1 = 0, *W_bh2 = 0, *b_bh2 = 0, *W_sa = 0;
    const float *W_a1 = 0, *b_a1 = 0, *W_a2 = 0, *b_a2 = 0, *W_a3 = 0, *b_a3 = 0;
    const float *W_hm = 0, *b_hm = 0, *W_om = 0, *b_om = 0, *W_hu = 0, *W_ou = 0;

    int c256 = 0, c1k = 0, c1m = 0, c2m = 0;
    for (int i = 0; i < n_in; i++) {
        const void* p = d_in[i];
        switch (in_sizes[i]) {
            case 3211264:  box = (const float*)p; break;
            case 262144:   nsp = (const float*)p; break;
            case 256:      if (c256++ == 0) scores = (const float*)p; else labels = (const int*)p; break;
            case 9360:     cmask = p; break;
            case 12845056: W_bh1 = (const float*)p; break;
            case 1024:
                switch (c1k++) {
                    case 0: b_bh1 = (const float*)p; break;
                    case 1: b_bh2 = (const float*)p; break;
                    case 2: b_a2  = (const float*)p; break;
                    case 3: W_a3  = (const float*)p; break;
                    case 4: b_hm  = (const float*)p; break;
                    case 5: b_om  = (const float*)p; break;
                } break;
            case 1048576:
                switch (c1m++) {
                    case 0: W_bh2 = (const float*)p; break;
                    case 1: W_sa  = (const float*)p; break;
                    case 2: W_hm  = (const float*)p; break;
                    case 3: W_om  = (const float*)p; break;
                } break;
            case 8388608:  W_a1 = (const float*)p; break;
            case 2048:     b_a1 = (const float*)p; break;
            case 2097152:
                switch (c2m++) {
                    case 0: W_a2 = (const float*)p; break;
                    case 1: W_hu = (const float*)p; break;
                    case 2: W_ou = (const float*)p; break;
                } break;
            case 1:        b_a3 = (const float*)p; break;
            default: break;
        }
    }

    float *enc1, *nssa, *Af, *Aof, *adjp, *obj, *hum, *hf, *hcatA, *hcatB, *of, *ocatA, *ocatB;
    __half *Ahh, *Aoh;
    cudaGetSymbolAddress((void**)&enc1, g_enc1);
    cudaGetSymbolAddress((void**)&nssa, g_nssa);
    cudaGetSymbolAddress((void**)&Af,   g_Af);
    cudaGetSymbolAddress((void**)&Aof,  g_Aof);
    cudaGetSymbolAddress((void**)&Ahh,  g_Ahh);
    cudaGetSymbolAddress((void**)&Aoh,  g_Aoh);
    cudaGetSymbolAddress((void**)&adjp, g_adjp);
    cudaGetSymbolAddress((void**)&obj,  g_obj);
    cudaGetSymbolAddress((void**)&hum,  g_hum);
    cudaGetSymbolAddress((void**)&hf,   g_hf);
    cudaGetSymbolAddress((void**)&hcatA, g_hcatA);
    cudaGetSymbolAddress((void**)&hcatB, g_hcatB);
    cudaGetSymbolAddress((void**)&of,   g_of);
    cudaGetSymbolAddress((void**)&ocatA, g_ocatA);
    cudaGetSymbolAddress((void**)&ocatB, g_ocatB);

    __nv_bfloat16 *bh1hi, *bh1lo, *bh2hi, *bh2lo, *sahi, *salo, *omhi, *omlo, *hmhi, *hmlo;
    __nv_bfloat16 *a1hi, *a1lo, *huhi, *hulo, *ouhi, *oulo, *boxhi, *boxlo;
    __half *a2h;
    cudaGetSymbolAddress((void**)&bh1hi, g_bh1hi);
    cudaGetSymbolAddress((void**)&bh1lo, g_bh1lo);
    cudaGetSymbolAddress((void**)&bh2hi, g_bh2hi);
    cudaGetSymbolAddress((void**)&bh2lo, g_bh2lo);
    cudaGetSymbolAddress((void**)&sahi,  g_sahi);
    cudaGetSymbolAddress((void**)&salo,  g_salo);
    cudaGetSymbolAddress((void**)&omhi,  g_omhi);
    cudaGetSymbolAddress((void**)&omlo,  g_omlo);
    cudaGetSymbolAddress((void**)&hmhi,  g_hmhi);
    cudaGetSymbolAddress((void**)&hmlo,  g_hmlo);
    cudaGetSymbolAddress((void**)&a1hi,  g_a1hi);
    cudaGetSymbolAddress((void**)&a1lo,  g_a1lo);
    cudaGetSymbolAddress((void**)&huhi,  g_huhi);
    cudaGetSymbolAddress((void**)&hulo,  g_hulo);
    cudaGetSymbolAddress((void**)&ouhi,  g_ouhi);
    cudaGetSymbolAddress((void**)&oulo,  g_oulo);
    cudaGetSymbolAddress((void**)&a2h,   g_a2h);
    cudaGetSymbolAddress((void**)&boxhi, g_boxhi);
    cudaGetSymbolAddress((void**)&boxlo, g_boxlo);

    cudaFuncSetAttribute(pair_mma_k, cudaFuncAttributeMaxDynamicSharedMemorySize, PR_SMEM);
    cudaFuncSetAttribute(gemm_jobs_k, cudaFuncAttributeMaxDynamicSharedMemorySize, GM_SMEM);

    detect_k<<<1, 256>>>((const unsigned char*)cmask);

    // ---- batched weight conversions + box pre-split ----
    {
        CvJobs J;
        J.njobs = 10;
        const float* Ws[10] = { W_bh1, W_a1, W_a1 + (size_t)2048 * 2048, W_bh2, W_sa,
                                W_om, W_hm, W_hu, W_ou, W_a2 };
        void* his[10] = { bh1hi, a1hi, a1hi + (size_t)2048 * 2048, bh2hi, sahi,
                          omhi, hmhi, huhi, ouhi, a2h };
        __nv_bfloat16* los[10] = { bh1lo, a1lo, a1lo + (size_t)2048 * 2048, bh2lo, salo,
                                   omlo, hmlo, hulo, oulo, 0 };
        int Ks[10] = { 12544, 2048, 2048, 1024, 1024, 1024, 1024, 2048, 2048, 2048 };
        int Ns[10] = { 1024, 2048, 2048, 1024, 1024, 1024, 1024, 1024, 1024, 1024 };
        int total = 0;
        for (int j = 0; j < 10; j++) {
            J.W[j] = Ws[j]; J.hi[j] = his[j]; J.lo[j] = los[j];
            J.K[j] = Ks[j]; J.N[j] = Ns[j];
            J.b0[j] = total;
            total += (Ks[j] >> 5) * (Ns[j] >> 5);
        }
        convall_k<<<total, dim3(32, 8)>>>(J);
    }
    convA_k<<<3211264 / 2048, 256>>>(box, boxhi, boxlo, 3211264);

    zeroinit_k<<<(1785856 + 255) / 256, 256>>>(enc1, Af, Aof, obj, hum, adjp, nssa, of);

    // ---- encoder (bf16 pre-split A) ----
    {
        GJobs J; int total = 0; J.njobs = 1;
        add_job(J, 0, 0, boxhi, boxlo, 12544, bh1hi, bh1lo, b_bh1, enc1, 0, 1024,
                NOBJ, 1024, 12544, 28, 0, total);
        gemm_jobs_k<<<total, 256, GM_SMEM>>>(J);
    }
    {
        GJobs J; int total = 0; J.njobs = 2;
        add_job(J, 0, enc1, 0, 0, 1024, bh2hi, bh2lo, b_bh2, of, 0, 2048, NOBJ, 1024, 1024, 4, 1, total);
        add_job(J, 1, nsp, 0, 0, 1024, sahi, salo, 0, nssa, 0, 1024, NOBJ, 1024, 1024, 4, 0, total);
        gemm_jobs_k<<<total, 256, GM_SMEM>>>(J);
    }
    copyinit_k<<<(262144 + 255) / 256, 256>>>(of, ocatA, hf, hcatA, nsp);

    for (int it = 0; it < 2; it++) {
        float* hc_in = it ? hcatB : hcatA;
        float* hc_out = it ? hcatA : hcatB;
        float* oc_in = it ? ocatB : ocatA;
        float* oc_out = it ? ocatA : ocatB;
        if (it == 1) zero2_k<<<(671744 + 255) / 256, 256>>>(Af, Aof, adjp);

        // B1: A_h, A_o, obj (independent)
        {
            GJobs J; int total = 0; J.njobs = 3;
            add_job(J, 0, hf, 0, 0, 2048, a1hi, a1lo, b_a1, Af, 0, 2048, NHUM, 2048, 2048, 8, 0, total);
            add_job(J, 1, of, 0, 0, 2048, a1hi + (size_t)2048 * 2048, a1lo + (size_t)2048 * 2048,
                    0, Aof, 0, 2048, NOBJ, 2048, 2048, 8, 0, total);
            add_job(J, 2, of, 0, 0, 2048, omhi, omlo, b_om, obj, 0, 1024, NOBJ, 1024, 1024, 8, 0, total);
            gemm_jobs_k<<<total, 256, GM_SMEM>>>(J);
        }
        cvt_k<<<(655360 + 255) / 256, 256>>>(Af, Aof, Ahh, Aoh);

        // pair GEMM -> adjp (128-row tiles, proven config)
        pair_mma_k<<<dim3(8, 128), 256, PR_SMEM>>>(Ahh, Aoh, a2h, b_a2, W_a3, adjp);

        // aggo: hc_in right; zero hf-left, hum, hc_out-left
        aggo_k<<<dim3(8, NHUM), 128>>>(adjp, b_a3, obj, nssa, hc_in, hc_out, hf, hum);

        // h_upd: dual-write hf-left + hc_out-left (replaces copy2d)
        {
            GJobs J; int total = 0; J.njobs = 1;
            add_job(J, 0, hc_in, 0, 0, 2048, huhi, hulo, 0, hf, hc_out, 2048, NHUM, 1024, 2048, 16, 0, total);
            gemm_jobs_k<<<total, 256, GM_SMEM>>>(J);
        }

        // hum = hf @ W_hm + b_hm (raw; relu in aggh)
        {
            GJobs J; int total = 0; J.njobs = 1;
            add_job(J, 0, hf, 0, 0, 2048, hmhi, hmlo, b_hm, hum, 0, 1024, NHUM, 1024, 1024, 16, 0, total);
            gemm_jobs_k<<<total, 256, GM_SMEM>>>(J);
        }

        // aggh: oc_in right; zero of-left, obj, oc_out-left
        aggh_k<<<dim3(8, NOBJ), 128>>>(adjp, b_a3, hum, nssa, oc_in, oc_out, of, obj);

        // o_upd: dual-write of-left + oc_out-left (replaces copy2d)
        {
            GJobs J; int total = 0; J.njobs = 1;
            add_job(J, 0, oc_in, 0, 0, 2048, ouhi, oulo, 0, of, oc_out, 2048, NOBJ, 1024, 2048, 16, 0, total);
            gemm_jobs_k<<<total, 256, GM_SMEM>>>(J);
        }
    }

    // ---- final gather ----
    out_k<<<NKEEP, 256>>>(hf, of, adjp, b_a3, scores, labels, cmask, (float*)d_out);
}

// round 15
// speedup vs baseline: 1.8703x; 1.0300x over previous
#include <cuda_runtime.h>
#include <cuda_bf16.h>
#include <cuda_fp16.h>
#include <math.h>
#include <stdint.h>

// ---------------- problem constants ----------------
#define NOBJ 256
#define NHUM 64
#define EDIM 1024
#define NPAIR 16384
#define NKEEP 16320
#define OUTC 4213
#define NCLS 117

// ---------------- scratch ----------------
__device__ float g_enc1[NOBJ*EDIM];
__device__ float g_nssa[NOBJ*EDIM];
__device__ float g_Af[NHUM*2048];
__device__ float g_Aof[NOBJ*2048];
__device__ __half g_Ahh[NHUM*2048];
__device__ __half g_Aoh[NOBJ*2048];
__device__ float g_adjp[NPAIR];
__device__ float g_obj[NOBJ*EDIM];
__device__ float g_hum[NHUM*EDIM];
__device__ float g_hf[NHUM*2048];      // [h_enc | h_sp]
__device__ float g_hcatA[NHUM*2048];   // [h_enc | agg_o] ping
__device__ float g_hcatB[NHUM*2048];   // pong
__device__ float g_of[NOBJ*2048];      // [enc | nsp]
__device__ float g_ocatA[NOBJ*2048];
__device__ float g_ocatB[NOBJ*2048];
__device__ int   g_mask_mode;

// pre-split transposed weights [n][k]
__device__ __nv_bfloat16 g_bh1hi[1024*12544];
__device__ __nv_bfloat16 g_bh1lo[1024*12544];
__device__ __nv_bfloat16 g_bh2hi[1024*1024];
__device__ __nv_bfloat16 g_bh2lo[1024*1024];
__device__ __nv_bfloat16 g_sahi[1024*1024];
__device__ __nv_bfloat16 g_salo[1024*1024];
__device__ __nv_bfloat16 g_omhi[1024*1024];
__device__ __nv_bfloat16 g_omlo[1024*1024];
__device__ __nv_bfloat16 g_hmhi[1024*1024];
__device__ __nv_bfloat16 g_hmlo[1024*1024];
__device__ __nv_bfloat16 g_a1hi[2*2048*2048];
__device__ __nv_bfloat16 g_a1lo[2*2048*2048];
__device__ __nv_bfloat16 g_huhi[1024*2048];
__device__ __nv_bfloat16 g_hulo[1024*2048];
__device__ __nv_bfloat16 g_ouhi[1024*2048];
__device__ __nv_bfloat16 g_oulo[1024*2048];
__device__ __half        g_a2h[1024*2048];
__device__ __nv_bfloat16 g_boxhi[NOBJ*12544];
__device__ __nv_bfloat16 g_boxlo[NOBJ*12544];

__device__ __forceinline__ uint32_t smem_u32(const void* p) {
    uint32_t a;
    asm("{ .reg .u64 t; cvta.to.shared.u64 t, %1; cvt.u32.u64 %0, t; }" : "=r"(a) : "l"(p));
    return a;
}
__device__ __forceinline__ void cpasync16(uint32_t saddr, const void* g) {
    asm volatile("{ .reg .u64 gg; cvta.to.global.u64 gg, %1; "
                 "cp.async.cg.shared.global [%0], [gg], 16; }"
                 :: "r"(saddr), "l"(g));
}
#define CP_COMMIT() asm volatile("cp.async.commit_group;")
#define CP_WAIT0()  asm volatile("cp.async.wait_group 0;")

// ================= mma.sync helpers =================
__device__ __forceinline__ void mma_bf16(float* c, const uint32_t* a, const uint32_t* b)
{
    asm volatile("mma.sync.aligned.m16n8k16.row.col.f32.bf16.bf16.f32 "
                 "{%0,%1,%2,%3}, {%4,%5,%6,%7}, {%8,%9}, {%0,%1,%2,%3};"
                 : "+f"(c[0]), "+f"(c[1]), "+f"(c[2]), "+f"(c[3])
                 : "r"(a[0]), "r"(a[1]), "r"(a[2]), "r"(a[3]), "r"(b[0]), "r"(b[1]));
}
__device__ __forceinline__ void mma_f16(float* c, const uint32_t* a, const uint32_t* b)
{
    asm volatile("mma.sync.aligned.m16n8k16.row.col.f32.f16.f16.f32 "
                 "{%0,%1,%2,%3}, {%4,%5,%6,%7}, {%8,%9}, {%0,%1,%2,%3};"
                 : "+f"(c[0]), "+f"(c[1]), "+f"(c[2]), "+f"(c[3])
                 : "r"(a[0]), "r"(a[1]), "r"(a[2]), "r"(a[3]), "r"(b[0]), "r"(b[1]));
}
__device__ __forceinline__ void ldmx4(uint32_t* d, uint32_t addr)
{
    asm volatile("ldmatrix.sync.aligned.m8n8.x4.shared.b16 {%0,%1,%2,%3}, [%4];"
                 : "=r"(d[0]), "=r"(d[1]), "=r"(d[2]), "=r"(d[3]) : "r"(addr));
}
__device__ __forceinline__ void ldmx2(uint32_t* d, uint32_t addr)
{
    asm volatile("ldmatrix.sync.aligned.m8n8.x2.shared.b16 {%0,%1}, [%2];"
                 : "=r"(d[0]), "=r"(d[1]) : "r"(addr));
}

// bf16 hi/lo 3-pass chunk: 128x128 tile, K=64, stride 144B
__device__ __forceinline__ void mma_chunk(uint32_t abase_hi, uint32_t abase_lo,
                                          uint32_t wbase_hi, uint32_t wbase_lo,
                                          float acc[4][4][4], int lid,
                                          int warp_row, int warp_col)
{
    #pragma unroll
    for (int ks = 0; ks < 4; ks++) {
        const int kk = ks * 16;
        uint32_t bh[4][2], bl[4][2];
        const int l2 = lid & 15;
        const uint32_t bro = (uint32_t)((l2 & 7) * 144 + (kk + ((l2 & 8) ? 8 : 0)) * 2);
        #pragma unroll
        for (int an = 0; an < 4; an++) {
            uint32_t nbase = (uint32_t)((warp_col * 32 + an * 8) * 144);
            ldmx2(bh[an], wbase_hi + nbase + bro);
            ldmx2(bl[an], wbase_lo + nbase + bro);
        }
        const uint32_t aro = (uint32_t)((lid & 15) * 144 + (kk + ((lid & 16) ? 8 : 0)) * 2);
        #pragma unroll
        for (int am = 0; am < 4; am++) {
            uint32_t mbase = (uint32_t)((warp_row * 64 + am * 16) * 144);
            uint32_t ah4[4], al4[4];
            ldmx4(ah4, abase_hi + mbase + aro);
            ldmx4(al4, abase_lo + mbase + aro);
            #pragma unroll
            for (int an = 0; an < 4; an++) {
                mma_bf16(acc[am][an], ah4, bh[an]);
                mma_bf16(acc[am][an], ah4, bl[an]);
                mma_bf16(acc[am][an], al4, bh[an]);
            }
        }
    }
}

// ---------------- batched weight conversions ----------------
struct CvJobs {
    const float* W[10];
    void* hi[10];
    __nv_bfloat16* lo[10];
    int K[10];
    int N[10];
    int b0[10];
    int njobs;
};

__global__ void convall_k(CvJobs J)
{
    __shared__ float t[32][33];
    int bid = blockIdx.x;
    int j = 0;
    #pragma unroll
    for (int q = 1; q < 10; q++)
        if (q < J.njobs && bid >= J.b0[q]) j = q;
    int local = bid - J.b0[j];
    int K = J.K[j], N = J.N[j];
    int kblocks = K >> 5;
    int kb = (local % kblocks) * 32;
    int nb = (local / kblocks) * 32;
    const float* W = J.W[j];
    int tx = threadIdx.x, ty = threadIdx.y;
    #pragma unroll
    for (int i = 0; i < 4; i++)
        t[ty + 8 * i][tx] = W[(size_t)(kb + ty + 8 * i) * N + nb + tx];
    __syncthreads();
    if (J.lo[j]) {
        __nv_bfloat16* hi = (__nv_bfloat16*)J.hi[j];
        __nv_bfloat16* lo = J.lo[j];
        #pragma unroll
        for (int i = 0; i < 4; i++) {
            float v = t[tx][ty + 8 * i];
            __nv_bfloat16 h = __float2bfloat16(v);
            size_t oi = (size_t)(nb + ty + 8 * i) * K + kb + tx;
            hi[oi] = h;
            lo[oi] = __float2bfloat16(v - __bfloat162float(h));
        }
    } else {
        __half* out = (__half*)J.hi[j];
        #pragma unroll
        for (int i = 0; i < 4; i++)
            out[(size_t)(nb + ty + 8 * i) * K + kb + tx] = __float2half_rn(t[tx][ty + 8 * i]);
    }
}

__global__ void convA_k(const float* __restrict__ src, __nv_bfloat16* __restrict__ hi,
                        __nv_bfloat16* __restrict__ lo, int n)
{
    int base = (blockIdx.x * 256 + threadIdx.x) * 8;
    if (base >= n) return;
    float4 a = *(const float4*)(src + base);
    float4 b = *(const float4*)(src + base + 4);
    float v[8] = { a.x, a.y, a.z, a.w, b.x, b.y, b.z, b.w };
    __nv_bfloat16 hv[8], lv[8];
    #pragma unroll
    for (int i = 0; i < 8; i++) {
        hv[i] = __float2bfloat16(v[i]);
        lv[i] = __float2bfloat16(v[i] - __bfloat162float(hv[i]));
    }
    *(uint4*)(hi + base) = *(uint4*)hv;
    *(uint4*)(lo + base) = *(uint4*)lv;
}

// ================= unified jobs GEMM =================
#define GM_AHI 0
#define GM_ALO 18432
#define GM_WHI 36864
#define GM_WLO 55296
#define GM_SMEM 73728

struct GJobs {
    const float* A[3];
    const __nv_bfloat16* Ahi[3];
    const __nv_bfloat16* Alo[3];
    const __nv_bfloat16* Bhi[3];
    const __nv_bfloat16* Blo[3];
    const float* bias[3];
    float* C[3];
    float* C2[3];   // optional second atomic target (same ldc)
    int lda[3], ldc[3], M[3], N[3], K[3], kslice[3], b0[3], gx[3], gy[3], reluA[3];
    int njobs;
};

__device__ void gemm_body(const float* __restrict__ A,
                          const __nv_bfloat16* __restrict__ A16h,
                          const __nv_bfloat16* __restrict__ A16l, int lda,
                          const __nv_bfloat16* __restrict__ Bhi,
                          const __nv_bfloat16* __restrict__ Blo,
                          const float* __restrict__ bias, float* __restrict__ C,
                          float* __restrict__ C2,
                          int ldc, int M, int N, int K, int kslice, int reluA,
                          int bx, int by, int bz, char* smem)
{
    uint32_t sb = smem_u32(smem);
    const int tid = threadIdx.x;
    const int wid = tid >> 5, lid = tid & 31;
    const int col0 = bx * 128;
    const int row0 = by * 128;
    const int kstart = bz * kslice;
    const int warp_row = wid >> 2, warp_col = wid & 3;

    const int r = tid >> 1, kh = tid & 1;
    int arow = row0 + r; if (arow >= M) arow = M - 1;
    const __nv_bfloat16* whp = Bhi + (size_t)(col0 + r) * K + kstart + kh * 32;
    const __nv_bfloat16* wlp = Blo + (size_t)(col0 + r) * K + kstart + kh * 32;
    const uint32_t soff = (uint32_t)(r * 144 + kh * 64);

    float acc[4][4][4];
    #pragma unroll
    for (int i = 0; i < 4; i++)
        #pragma unroll
        for (int j = 0; j < 4; j++)
            #pragma unroll
            for (int q = 0; q < 4; q++) acc[i][j][q] = 0.f;

    const int nchunk = kslice >> 6;
    if (A16h) {
        const __nv_bfloat16* ahp = A16h + (size_t)arow * lda + kstart + kh * 32;
        const __nv_bfloat16* alp = A16l + (size_t)arow * lda + kstart + kh * 32;
        for (int c = 0; c < nchunk; c++) {
            const int k0 = c * 64;
            __syncthreads();
            #pragma unroll
            for (int j = 0; j < 4; j++) {
                cpasync16(sb + GM_WHI + soff + j * 16, whp + k0 + j * 8);
                cpasync16(sb + GM_WLO + soff + j * 16, wlp + k0 + j * 8);
            }
            #pragma unroll
            for (int j = 0; j < 4; j++) {
                cpasync16(sb + GM_AHI + soff + j * 16, ahp + k0 + j * 8);
                cpasync16(sb + GM_ALO + soff + j * 16, alp + k0 + j * 8);
            }
            CP_COMMIT();
            CP_WAIT0();
            __syncthreads();
            mma_chunk(sb + GM_AHI, sb + GM_ALO, sb + GM_WHI, sb + GM_WLO,
                      acc, lid, warp_row, warp_col);
        }
    } else {
        const float* agp = A + (size_t)arow * lda + kstart + kh * 32;
        for (int c = 0; c < nchunk; c++) {
            const int k0 = c * 64;
            __syncthreads();
            #pragma unroll
            for (int j = 0; j < 4; j++) {
                cpasync16(sb + GM_WHI + soff + j * 16, whp + k0 + j * 8);
                cpasync16(sb + GM_WLO + soff + j * 16, wlp + k0 + j * 8);
            }
            CP_COMMIT();
            const float4* p = (const float4*)(agp + k0);
            #pragma unroll
            for (int j = 0; j < 8; j++) {
                float4 a = p[j];
                if (reluA) {
                    a.x = fmaxf(a.x, 0.f); a.y = fmaxf(a.y, 0.f);
                    a.z = fmaxf(a.z, 0.f); a.w = fmaxf(a.w, 0.f);
                }
                __nv_bfloat16 h0 = __float2bfloat16(a.x), h1 = __float2bfloat16(a.y);
                __nv_bfloat16 h2 = __float2bfloat16(a.z), h3 = __float2bfloat16(a.w);
                __nv_bfloat162 hw0 = __nv_bfloat162(h0, h1), hw1 = __nv_bfloat162(h2, h3);
                __nv_bfloat162 lw0 = __nv_bfloat162(__float2bfloat16(a.x - __bfloat162float(h0)),
                                                    __float2bfloat16(a.y - __bfloat162float(h1)));
                __nv_bfloat162 lw1 = __nv_bfloat162(__float2bfloat16(a.z - __bfloat162float(h2)),
                                                    __float2bfloat16(a.w - __bfloat162float(h3)));
                *(uint2*)(smem + GM_AHI + soff + j * 8) = make_uint2(*(uint32_t*)&hw0, *(uint32_t*)&hw1);
                *(uint2*)(smem + GM_ALO + soff + j * 8) = make_uint2(*(uint32_t*)&lw0, *(uint32_t*)&lw1);
            }
            CP_WAIT0();
            __syncthreads();
            mma_chunk(sb + GM_AHI, sb + GM_ALO, sb + GM_WHI, sb + GM_WLO,
                      acc, lid, warp_row, warp_col);
        }
    }

    #pragma unroll
    for (int am = 0; am < 4; am++) {
        #pragma unroll
        for (int q = 0; q < 4; q++) {
            int row = row0 + warp_row * 64 + am * 16 + (lid >> 2) + ((q >= 2) ? 8 : 0);
            if (row >= M) continue;
            #pragma unroll
            for (int an = 0; an < 4; an++) {
                int col = col0 + warp_col * 32 + an * 8 + (lid & 3) * 2 + (q & 1);
                float v = acc[am][an][q];
                if (bz == 0 && bias) v += bias[col];
                size_t idx = (size_t)row * ldc + col;
                atomicAdd(C + idx, v);
                if (C2) atomicAdd(C2 + idx, v);
            }
        }
    }
}

__global__ void __launch_bounds__(256, 2)
gemm_jobs_k(GJobs J)
{
    extern __shared__ char smem[];
    int bid = blockIdx.x;
    int j = 0;
    #pragma unroll
    for (int q = 1; q < 3; q++)
        if (q < J.njobs && bid >= J.b0[q]) j = q;
    int local = bid - J.b0[j];
    int gxy = J.gx[j] * J.gy[j];
    int bz = local / gxy;
    int rem = local % gxy;
    int by = rem / J.gx[j];
    int bx = rem % J.gx[j];
    gemm_body(J.A[j], J.Ahi[j], J.Alo[j], J.lda[j], J.Bhi[j], J.Blo[j], J.bias[j], J.C[j],
              J.C2[j], J.ldc[j], J.M[j], J.N[j], J.K[j], J.kslice[j], J.reluA[j],
              bx, by, bz, smem);
}

// ================= fp16 pair MMA: single-sync pipelined (128-row tiles) =================
#define PR_AHS   0
#define PR_ST0   4096
#define PR_A     0
#define PR_W     18432
#define PR_STAGE 36864
#define PR_RED   77824
#define PR_B2    78336
#define PR_W3    78848
#define PR_SMEM  79360

__global__ void __launch_bounds__(256, 2)
pair_mma_k(const __half* __restrict__ Ahh, const __half* __restrict__ Aoh,
           const __half* __restrict__ Wt, const float* __restrict__ b2,
           const float* __restrict__ w3, float* __restrict__ adjp)
{
    extern __shared__ char smem[];
    uint32_t sb = smem_u32(smem);
    const int tid = threadIdx.x;
    const int wid = tid >> 5, lid = tid & 31;
    const int col0 = blockIdx.x * 128;
    const int row0 = blockIdx.y * 128;
    const int h = row0 >> 8;
    const int nb = row0 & 255;
    const int warp_row = wid >> 2, warp_col = wid & 3;

    if (tid < 128) {
        *(float*)(smem + PR_B2 + tid * 4) = b2[col0 + tid];
        *(float*)(smem + PR_W3 + tid * 4) = w3[col0 + tid];
        *(float*)(smem + PR_RED + tid * 4) = 0.f;
    }
    *(uint4*)(smem + PR_AHS + tid * 16) = *(const uint4*)(Ahh + h * 2048 + tid * 8);

    const int r = tid >> 1, kh = tid & 1;
    const __half* aop = Aoh + (size_t)(nb + r) * 2048 + kh * 32;
    const __half* whp = Wt + (size_t)(col0 + r) * 2048 + kh * 32;
    const uint32_t soff = (uint32_t)(r * 144 + kh * 64);

    float acc[4][4][4];
    #pragma unroll
    for (int i = 0; i < 4; i++)
        #pragma unroll
        for (int j = 0; j < 4; j++)
            #pragma unroll
            for (int q = 0; q < 4; q++) acc[i][j][q] = 0.f;

    {
        uint32_t stb = sb + PR_ST0;
        #pragma unroll
        for (int j = 0; j < 2; j++) {
            cpasync16(stb + PR_A + soff + j * 16, aop + j * 8);
            cpasync16(stb + PR_A + soff + 32 + j * 16, aop + 16 + j * 8);
            cpasync16(stb + PR_W + soff + j * 16, whp + j * 8);
            cpasync16(stb + PR_W + soff + 32 + j * 16, whp + 16 + j * 8);
        }
        CP_COMMIT();
    }
    __syncthreads();

    const __half2 hz = __floats2half2_rn(0.f, 0.f);
    const int n_off = ((lid >> 4) & 1) * 8 + (lid & 7);
    const int kb_ = ((lid >> 3) & 1) * 8;

    for (int c = 0; c < 32; c++) {
        const int cur = c & 1;
        CP_WAIT0();
        {
            char* av = smem + PR_ST0 + cur * PR_STAGE + PR_A + soff;
            const uint4* ahq = (const uint4*)(smem + PR_AHS + (c * 64 + kh * 32) * 2);
            #pragma unroll
            for (int j = 0; j < 4; j++) {
                uint4 vo = *(uint4*)(av + j * 16);
                uint4 vh = ahq[j];
                __half2 r0 = __hmax2(__hadd2(*(__half2*)&vo.x, *(__half2*)&vh.x), hz);
                __half2 r1 = __hmax2(__hadd2(*(__half2*)&vo.y, *(__half2*)&vh.y), hz);
                __half2 r2 = __hmax2(__hadd2(*(__half2*)&vo.z, *(__half2*)&vh.z), hz);
                __half2 r3 = __hmax2(__hadd2(*(__half2*)&vo.w, *(__half2*)&vh.w), hz);
                *(uint4*)(av + j * 16) = make_uint4(*(uint32_t*)&r0, *(uint32_t*)&r1,
                                                    *(uint32_t*)&r2, *(uint32_t*)&r3);
            }
        }
        __syncthreads();
        if (c < 31) {
            uint32_t stb = sb + PR_ST0 + (cur ^ 1) * PR_STAGE;
            const int kn = (c + 1) * 64;
            #pragma unroll
            for (int j = 0; j < 2; j++) {
                cpasync16(stb + PR_A + soff + j * 16, aop + kn + j * 8);
                cpasync16(stb + PR_A + soff + 32 + j * 16, aop + kn + 16 + j * 8);
                cpasync16(stb + PR_W + soff + j * 16, whp + kn + j * 8);
                cpasync16(stb + PR_W + soff + 32 + j * 16, whp + kn + 16 + j * 8);
            }
            CP_COMMIT();
        }
        uint32_t abase = sb + PR_ST0 + cur * PR_STAGE + PR_A;
        uint32_t wbase = sb + PR_ST0 + cur * PR_STAGE + PR_W;
        #pragma unroll
        for (int ks = 0; ks < 4; ks++) {
            const int kk = ks * 16;
            uint32_t b[4][2];
            #pragma unroll
            for (int anp = 0; anp < 2; anp++) {
                uint32_t t[4];
                ldmx4(t, wbase + (uint32_t)((warp_col * 32 + anp * 16 + n_off) * 144
                                            + (kk + kb_) * 2));
                b[anp * 2][0] = t[0]; b[anp * 2][1] = t[1];
                b[anp * 2 + 1][0] = t[2]; b[anp * 2 + 1][1] = t[3];
            }
            const uint32_t aro = (uint32_t)((lid & 15) * 144 + (kk + ((lid & 16) ? 8 : 0)) * 2);
            #pragma unroll
            for (int am = 0; am < 4; am++) {
                uint32_t a4[4];
                ldmx4(a4, abase + (uint32_t)((warp_row * 64 + am * 16) * 144) + aro);
                #pragma unroll
                for (int an = 0; an < 4; an++)
                    mma_f16(acc[am][an], a4, b[an]);
            }
        }
    }

    const float* b2s = (const float*)(smem + PR_B2);
    const float* w3s = (const float*)(smem + PR_W3);
    float* sred = (float*)(smem + PR_RED);
    #pragma unroll
    for (int am = 0; am < 4; am++) {
        float pl = 0.f, ph = 0.f;
        #pragma unroll
        for (int an = 0; an < 4; an++) {
            int cb = warp_col * 32 + an * 8 + 2 * (lid & 3);
            float w0 = w3s[cb], w1 = w3s[cb + 1];
            float bb0 = b2s[cb], bb1 = b2s[cb + 1];
            pl += fmaxf(acc[am][an][0] + bb0, 0.f) * w0 + fmaxf(acc[am][an][1] + bb1, 0.f) * w1;
            ph += fmaxf(acc[am][an][2] + bb0, 0.f) * w0 + fmaxf(acc[am][an][3] + bb1, 0.f) * w1;
        }
        pl += __shfl_xor_sync(0xffffffffu, pl, 1);
        pl += __shfl_xor_sync(0xffffffffu, pl, 2);
        ph += __shfl_xor_sync(0xffffffffu, ph, 1);
        ph += __shfl_xor_sync(0xffffffffu, ph, 2);
        if ((lid & 3) == 0) {
            int rloc = warp_row * 64 + am * 16 + (lid >> 2);
            atomicAdd(sred + rloc, pl);
            atomicAdd(sred + rloc + 8, ph);
        }
    }
    __syncthreads();
    if (tid < 128) atomicAdd(adjp + row0 + tid, sred[tid]);
}

// ---------------- small fused kernels ----------------
__device__ __forceinline__ float sigf(float z) { return 1.f / (1.f + expf(-z)); }

__global__ void zeroinit_k(float* enc1, float* Af, float* Aof, float* obj,
                           float* hum, float* adjp, float* nssa, float* of)
{
    int i = blockIdx.x * 256 + threadIdx.x;
    if (i < 262144) enc1[i] = 0.f;
    else if (i < 393216) Af[i - 262144] = 0.f;
    else if (i < 917504) Aof[i - 393216] = 0.f;
    else if (i < 1179648) obj[i - 917504] = 0.f;
    else if (i < 1245184) hum[i - 1179648] = 0.f;
    else if (i < 1261568) adjp[i - 1245184] = 0.f;
    else if (i < 1523712) nssa[i - 1261568] = 0.f;
    else if (i < 1785856) {
        int j = i - 1523712;
        of[(j >> 10) * 2048 + (j & 1023)] = 0.f;
    }
}

__global__ void zero2_k(float* Af, float* Aof, float* adjp)
{
    int i = blockIdx.x * 256 + threadIdx.x;
    if (i < 131072) Af[i] = 0.f;
    else if (i < 655360) Aof[i - 131072] = 0.f;
    else if (i < 671744) adjp[i - 655360] = 0.f;
}

__global__ void copyinit_k(float* of, float* ocat, float* hf, float* hcat,
                           const float* __restrict__ nsp)
{
    int i = blockIdx.x * 256 + threadIdx.x;
    if (i >= 262144) return;
    int r = i >> 10, c = i & 1023;
    float e = fmaxf(of[r * 2048 + c], 0.f);
    of[r * 2048 + c] = e;
    float s = nsp[i];
    of[r * 2048 + 1024 + c] = s;
    ocat[r * 2048 + c] = e;
    if (r < 64) {
        hf[r * 2048 + c] = e;
        hf[r * 2048 + 1024 + c] = s;
        hcat[r * 2048 + c] = e;
    }
}

__global__ void cvt_k(const float* __restrict__ Af, const float* __restrict__ Aof,
                      __half* __restrict__ Ahh, __half* __restrict__ Aoh)
{
    int i = blockIdx.x * 256 + threadIdx.x;
    if (i < 131072) Ahh[i] = __float2half_rn(Af[i]);
    else if (i < 655360) Aoh[i - 131072] = __float2half_rn(Aof[i - 131072]);
}

// aggo: writes hcat_in-right; zeroes hf-left, hum, hcat_out-left
__global__ void aggo_k(const float* __restrict__ adjp, const float* __restrict__ b3,
                       const float* __restrict__ obj, const float* __restrict__ nssa,
                       float* __restrict__ hcat_in, float* __restrict__ hcat_out,
                       float* __restrict__ hf, float* __restrict__ hum)
{
    int h = blockIdx.y;
    int e = blockIdx.x * 128 + threadIdx.x;
    __shared__ float sa[256];
    float b3v = b3[0];
    for (int i = threadIdx.x; i < 256; i += 128)
        sa[i] = sigf(adjp[h * 256 + i] + b3v);
    __syncthreads();
    float a1 = 0.f, a2 = 0.f;
    #pragma unroll 4
    for (int n = 0; n < 256; n++) {
        float a = sa[n];
        float om = fmaxf(obj[n * 1024 + e], 0.f);
        float ns = nssa[n * 1024 + e];
        a1 += a * om;
        a2 += a * om * ns;
    }
    hcat_in[h * 2048 + 1024 + e] = nssa[h * 1024 + e] * a1 - a2;
    hcat_out[h * 2048 + e] = 0.f;
    hf[h * 2048 + e] = 0.f;
    hum[h * 1024 + e] = 0.f;
}

// aggh: writes ocat_in-right; zeroes of-left, obj, ocat_out-left
__global__ void aggh_k(const float* __restrict__ adjp, const float* __restrict__ b3,
                       const float* __restrict__ hum, const float* __restrict__ nssa,
                       float* __restrict__ ocat_in, float* __restrict__ ocat_out,
                       float* __restrict__ of, float* __restrict__ obj)
{
    int n = blockIdx.y;
    int e = blockIdx.x * 128 + threadIdx.x;
    __shared__ float sa[64];
    float b3v = b3[0];
    if (threadIdx.x < 64) sa[threadIdx.x] = sigf(adjp[threadIdx.x * 256 + n] + b3v);
    __syncthreads();
    float a1 = 0.f, a2 = 0.f;
    #pragma unroll 4
    for (int h = 0; h < 64; h++) {
        float a = sa[h];
        float hm = fmaxf(hum[h * 1024 + e], 0.f);
        float hs = nssa[h * 1024 + e];
        a1 += a * hm;
        a2 += a * hm * hs;
    }
    ocat_in[n * 2048 + 1024 + e] = nssa[n * 1024 + e] * a1 - a2;
    ocat_out[n * 2048 + e] = 0.f;
    of[n * 2048 + e] = 0.f;
    obj[n * 1024 + e] = 0.f;
}

__global__ void detect_k(const unsigned char* __restrict__ cm)
{
    __shared__ int s_f, s_nz;
    if (threadIdx.x == 0) { s_f = 0; s_nz = 0; }
    __syncthreads();
    int lf = 0, lnz = 0;
    for (int i = threadIdx.x; i < 9360; i += blockDim.x) {
        unsigned char b = cm[i];
        int m4 = i & 3;
        if (m4 == 3 && b == 0x3F) lf = 1;
        if (m4 != 0 && b != 0) lnz = 1;
    }
    if (lf) atomicOr(&s_f, 1);
    if (lnz) atomicOr(&s_nz, 1);
    __syncthreads();
    if (threadIdx.x == 0) g_mask_mode = s_f ? 2 : (s_nz ? 0 : 1);
}

__device__ __forceinline__ float lisf(float x)
{
    return 8.3f / (1.f + expf(12.f - 10.f * x));
}

// ---------------- final gather: phase-aligned float4 stores ----------------
__device__ __forceinline__ float outval(int c, const float* hx, const float* oy,
                                        float scale, int lab, int mode,
                                        const void* cmask)
{
    if (c < 2048) return hx[c];
    if (c < 4096) return oy[c - 2048];
    int j = c - 4096;
    float m;
    if (mode == 0)      m = ((const unsigned char*)cmask)[lab * NCLS + j] ? 1.f : 0.f;
    else if (mode == 1) m = ((const int*)cmask)[lab * NCLS + j] ? 1.f : 0.f;
    else                m = ((const float*)cmask)[lab * NCLS + j];
    return scale * m;
}

__global__ void out_k(const float* __restrict__ hf, const float* __restrict__ of,
                      const float* __restrict__ adjp, const float* __restrict__ b3,
                      const float* __restrict__ scores, const int* __restrict__ labels,
                      const void* __restrict__ cmask, float* __restrict__ out)
{
    int p = blockIdx.x;
    int x = p / 255;
    int r = p % 255;
    int y = (r < x) ? r : r + 1;

    float scale = sigf(adjp[x * 256 + y] + b3[0]) * lisf(scores[x]) * lisf(scores[y]);
    int lab = labels[y];
    int mode = g_mask_mode;

    const float* hx = hf + x * 2048;
    const float* oy = of + y * 2048;
    float* o = out + (size_t)p * OUTC;

    // row start element-offset mod 4 = p mod 4 (since OUTC % 4 == 1)
    int phase = (4 - (p & 3)) & 3;          // scalar head length to 16B-align
    int nvec = (OUTC - phase) >> 2;         // float4 groups
    int tail0 = phase + nvec * 4;

    if (threadIdx.x < phase) {
        int c = threadIdx.x;
        o[c] = outval(c, hx, oy, scale, lab, mode, cmask);
    }
    for (int g = threadIdx.x; g < nvec; g += blockDim.x) {
        int c = phase + g * 4;
        float4 v;
        v.x = outval(c,     hx, oy, scale, lab, mode, cmask);
        v.y = outval(c + 1, hx, oy, scale, lab, mode, cmask);
        v.z = outval(c + 2, hx, oy, scale, lab, mode, cmask);
        v.w = outval(c + 3, hx, oy, scale, lab, mode, cmask);
        *(float4*)(o + c) = v;
    }
    for (int c = tail0 + threadIdx.x; c < OUTC; c += blockDim.x)
        o[c] = outval(c, hx, oy, scale, lab, mode, cmask);
}

// ---------------- host ----------------
static void add_job(GJobs& J, int idx, const float* A,
                    const __nv_bfloat16* Ahi, const __nv_bfloat16* Alo, int lda,
                    const __nv_bfloat16* Bhi, const __nv_bfloat16* Blo,
                    const float* bias, float* C, float* C2, int ldc,
                    int M, int N, int K, int nk, int reluA, int& total)
{
    int gx = N / 128, gy = (M + 127) / 128;
    J.A[idx] = A; J.Ahi[idx] = Ahi; J.Alo[idx] = Alo;
    J.Bhi[idx] = Bhi; J.Blo[idx] = Blo; J.bias[idx] = bias;
    J.C[idx] = C; J.C2[idx] = C2; J.lda[idx] = lda; J.ldc[idx] = ldc;
    J.M[idx] = M; J.N[idx] = N; J.K[idx] = K; J.kslice[idx] = K / nk;
    J.gx[idx] = gx; J.gy[idx] = gy; J.b0[idx] = total; J.reluA[idx] = reluA;
    total += gx * gy * nk;
}

extern "C" void kernel_launch(void* const* d_in, const int* in_sizes, int n_in,
                              void* d_out, int out_size)
{
    const float *box = 0, *nsp = 0, *scores = 0;
    const int *labels = 0;
    const void *cmask = 0;
    const float *W_bh1 = 0, *b_bh1 = 0, *W_bh2 = 0, *b_bh2 = 0, *W_sa = 0;
    const float *W_a1 = 0, *b_a1 = 0, *W_a2 = 0, *b_a2 = 0, *W_a3 = 0, *b_a3 = 0;
    const float *W_hm = 0, *b_hm = 0, *W_om = 0, *b_om = 0, *W_hu = 0, *W_ou = 0;

    int c256 = 0, c1k = 0, c1m = 0, c2m = 0;
    for (int i = 0; i < n_in; i++) {
        const void* p = d_in[i];
        switch (in_sizes[i]) {
            case 3211264:  box = (const float*)p; break;
            case 262144:   nsp = (const float*)p; break;
            case 256:      if (c256++ == 0) scores = (const float*)p; else labels = (const int*)p; break;
            case 9360:     cmask = p; break;
            case 12845056: W_bh1 = (const float*)p; break;
            case 1024:
                switch (c1k++) {
                    case 0: b_bh1 = (const float*)p; break;
                    case 1: b_bh2 = (const float*)p; break;
                    case 2: b_a2  = (const float*)p; break;
                    case 3: W_a3  = (const float*)p; break;
                    case 4: b_hm  = (const float*)p; break;
                    case 5: b_om  = (const float*)p; break;
                } break;
            case 1048576:
                switch (c1m++) {
                    case 0: W_bh2 = (const float*)p; break;
                    case 1: W_sa  = (const float*)p; break;
                    case 2: W_hm  = (const float*)p; break;
                    case 3: W_om  = (const float*)p; break;
                } break;
            case 8388608:  W_a1 = (const float*)p; break;
            case 2048:     b_a1 = (const float*)p; break;
            case 2097152:
                switch (c2m++) {
                    case 0: W_a2 = (const float*)p; break;
                    case 1: W_hu = (const float*)p; break;
                    case 2: W_ou = (const float*)p; break;
                } break;
            case 1:        b_a3 = (const float*)p; break;
            default: break;
        }
    }

    float *enc1, *nssa, *Af, *Aof, *adjp, *obj, *hum, *hf, *hcatA, *hcatB, *of, *ocatA, *ocatB;
    __half *Ahh, *Aoh;
    cudaGetSymbolAddress((void**)&enc1, g_enc1);
    cudaGetSymbolAddress((void**)&nssa, g_nssa);
    cudaGetSymbolAddress((void**)&Af,   g_Af);
    cudaGetSymbolAddress((void**)&Aof,  g_Aof);
    cudaGetSymbolAddress((void**)&Ahh,  g_Ahh);
    cudaGetSymbolAddress((void**)&Aoh,  g_Aoh);
    cudaGetSymbolAddress((void**)&adjp, g_adjp);
    cudaGetSymbolAddress((void**)&obj,  g_obj);
    cudaGetSymbolAddress((void**)&hum,  g_hum);
    cudaGetSymbolAddress((void**)&hf,   g_hf);
    cudaGetSymbolAddress((void**)&hcatA, g_hcatA);
    cudaGetSymbolAddress((void**)&hcatB, g_hcatB);
    cudaGetSymbolAddress((void**)&of,   g_of);
    cudaGetSymbolAddress((void**)&ocatA, g_ocatA);
    cudaGetSymbolAddress((void**)&ocatB, g_ocatB);

    __nv_bfloat16 *bh1hi, *bh1lo, *bh2hi, *bh2lo, *sahi, *salo, *omhi, *omlo, *hmhi, *hmlo;
    __nv_bfloat16 *a1hi, *a1lo, *huhi, *hulo, *ouhi, *oulo, *boxhi, *boxlo;
    __half *a2h;
    cudaGetSymbolAddress((void**)&bh1hi, g_bh1hi);
    cudaGetSymbolAddress((void**)&bh1lo, g_bh1lo);
    cudaGetSymbolAddress((void**)&bh2hi, g_bh2hi);
    cudaGetSymbolAddress((void**)&bh2lo, g_bh2lo);
    cudaGetSymbolAddress((void**)&sahi,  g_sahi);
    cudaGetSymbolAddress((void**)&salo,  g_salo);
    cudaGetSymbolAddress((void**)&omhi,  g_omhi);
    cudaGetSymbolAddress((void**)&omlo,  g_omlo);
    cudaGetSymbolAddress((void**)&hmhi,  g_hmhi);
    cudaGetSymbolAddress((void**)&hmlo,  g_hmlo);
    cudaGetSymbolAddress((void**)&a1hi,  g_a1hi);
    cudaGetSymbolAddress((void**)&a1lo,  g_a1lo);
    cudaGetSymbolAddress((void**)&huhi,  g_huhi);
    cudaGetSymbolAddress((void**)&hulo,  g_hulo);
    cudaGetSymbolAddress((void**)&ouhi,  g_ouhi);
    cudaGetSymbolAddress((void**)&oulo,  g_oulo);
    cudaGetSymbolAddress((void**)&a2h,   g_a2h);
    cudaGetSymbolAddress((void**)&boxhi, g_boxhi);
    cudaGetSymbolAddress((void**)&boxlo, g_boxlo);

    cudaFuncSetAttribute(pair_mma_k, cudaFuncAttributeMaxDynamicSharedMemorySize, PR_SMEM);
    cudaFuncSetAttribute(gemm_jobs_k, cudaFuncAttributeMaxDynamicSharedMemorySize, GM_SMEM);

    detect_k<<<1, 256>>>((const unsigned char*)cmask);

    // ---- batched weight conversions + box pre-split ----
    {
        CvJobs J;
        J.njobs = 10;
        const float* Ws[10] = { W_bh1, W_a1, W_a1 + (size_t)2048 * 2048, W_bh2, W_sa,
                                W_om, W_hm, W_hu, W_ou, W_a2 };
        void* his[10] = { bh1hi, a1hi, a1hi + (size_t)2048 * 2048, bh2hi, sahi,
                          omhi, hmhi, huhi, ouhi, a2h };
        __nv_bfloat16* los[10] = { bh1lo, a1lo, a1lo + (size_t)2048 * 2048, bh2lo, salo,
                                   omlo, hmlo, hulo, oulo, 0 };
        int Ks[10] = { 12544, 2048, 2048, 1024, 1024, 1024, 1024, 2048, 2048, 2048 };
        int Ns[10] = { 1024, 2048, 2048, 1024, 1024, 1024, 1024, 1024, 1024, 1024 };
        int total = 0;
        for (int j = 0; j < 10; j++) {
            J.W[j] = Ws[j]; J.hi[j] = his[j]; J.lo[j] = los[j];
            J.K[j] = Ks[j]; J.N[j] = Ns[j];
            J.b0[j] = total;
            total += (Ks[j] >> 5) * (Ns[j] >> 5);
        }
        convall_k<<<total, dim3(32, 8)>>>(J);
    }
    convA_k<<<3211264 / 2048, 256>>>(box, boxhi, boxlo, 3211264);

    zeroinit_k<<<(1785856 + 255) / 256, 256>>>(enc1, Af, Aof, obj, hum, adjp, nssa, of);

    // ---- encoder (bf16 pre-split A) ----
    {
        GJobs J; int total = 0; J.njobs = 1;
        add_job(J, 0, 0, boxhi, boxlo, 12544, bh1hi, bh1lo, b_bh1, enc1, 0, 1024,
                NOBJ, 1024, 12544, 28, 0, total);
        gemm_jobs_k<<<total, 256, GM_SMEM>>>(J);
    }
    {
        GJobs J; int total = 0; J.njobs = 2;
        add_job(J, 0, enc1, 0, 0, 1024, bh2hi, bh2lo, b_bh2, of, 0, 2048, NOBJ, 1024, 1024, 4, 1, total);
        add_job(J, 1, nsp, 0, 0, 1024, sahi, salo, 0, nssa, 0, 1024, NOBJ, 1024, 1024, 4, 0, total);
        gemm_jobs_k<<<total, 256, GM_SMEM>>>(J);
    }
    copyinit_k<<<(262144 + 255) / 256, 256>>>(of, ocatA, hf, hcatA, nsp);

    for (int it = 0; it < 2; it++) {
        float* hc_in = it ? hcatB : hcatA;
        float* hc_out = it ? hcatA : hcatB;
        float* oc_in = it ? ocatB : ocatA;
        float* oc_out = it ? ocatA : ocatB;
        if (it == 1) zero2_k<<<(671744 + 255) / 256, 256>>>(Af, Aof, adjp);

        // B1: A_h, A_o, obj (independent)
        {
            GJobs J; int total = 0; J.njobs = 3;
            add_job(J, 0, hf, 0, 0, 2048, a1hi, a1lo, b_a1, Af, 0, 2048, NHUM, 2048, 2048, 8, 0, total);
            add_job(J, 1, of, 0, 0, 2048, a1hi + (size_t)2048 * 2048, a1lo + (size_t)2048 * 2048,
                    0, Aof, 0, 2048, NOBJ, 2048, 2048, 8, 0, total);
            add_job(J, 2, of, 0, 0, 2048, omhi, omlo, b_om, obj, 0, 1024, NOBJ, 1024, 1024, 8, 0, total);
            gemm_jobs_k<<<total, 256, GM_SMEM>>>(J);
        }
        cvt_k<<<(655360 + 255) / 256, 256>>>(Af, Aof, Ahh, Aoh);

        // pair GEMM -> adjp (128-row tiles, proven config)
        pair_mma_k<<<dim3(8, 128), 256, PR_SMEM>>>(Ahh, Aoh, a2h, b_a2, W_a3, adjp);

        // aggo: hc_in right; zero hf-left, hum, hc_out-left
        aggo_k<<<dim3(8, NHUM), 128>>>(adjp, b_a3, obj, nssa, hc_in, hc_out, hf, hum);

        // h_upd: dual-write hf-left + hc_out-left
        {
            GJobs J; int total = 0; J.njobs = 1;
            add_job(J, 0, hc_in, 0, 0, 2048, huhi, hulo, 0, hf, hc_out, 2048, NHUM, 1024, 2048, 16, 0, total);
            gemm_jobs_k<<<total, 256, GM_SMEM>>>(J);
        }

        // hum = hf @ W_hm + b_hm (raw; relu in aggh)
        {
            GJobs J; int total = 0; J.njobs = 1;
            add_job(J, 0, hf, 0, 0, 2048, hmhi, hmlo, b_hm, hum, 0, 1024, NHUM, 1024, 1024, 16, 0, total);
            gemm_jobs_k<<<total, 256, GM_SMEM>>>(J);
        }

        // aggh: oc_in right; zero of-left, obj, oc_out-left
        aggh_k<<<dim3(8, NOBJ), 128>>>(adjp, b_a3, hum, nssa, oc_in, oc_out, of, obj);

        // o_upd: dual-write of-left + oc_out-left
        {
            GJobs J; int total = 0; J.njobs = 1;
            add_job(J, 0, oc_in, 0, 0, 2048, ouhi, oulo, 0, of, oc_out, 2048, NOBJ, 1024, 2048, 16, 0, total);
            gemm_jobs_k<<<total, 256, GM_SMEM>>>(J);
        }
    }

    // ---- final gather ----
    out_k<<<NKEEP, 256>>>(hf, of, adjp, b_a3, scores, labels, cmask, (float*)d_out);
}

// round 16
// speedup vs baseline: 1.8812x; 1.0058x over previous
#include <cuda_runtime.h>
#include <cuda_bf16.h>
#include <cuda_fp16.h>
#include <math.h>
#include <stdint.h>

// ---------------- problem constants ----------------
#define NOBJ 256
#define NHUM 64
#define EDIM 1024
#define NPAIR 16384
#define NKEEP 16320
#define OUTC 4213
#define NCLS 117

// ---------------- scratch ----------------
__device__ float g_enc1[NOBJ*EDIM];
__device__ float g_nssa[NOBJ*EDIM];
__device__ float g_Af[NHUM*2048];
__device__ float g_Aof[NOBJ*2048];
__device__ __half g_Ahh[NHUM*2048];
__device__ __half g_Aoh[NOBJ*2048];
__device__ float g_adjp[NPAIR];
__device__ float g_obj[NOBJ*EDIM];
__device__ float g_hum[NHUM*EDIM];
__device__ float g_hf[NHUM*2048];      // [h_enc | h_sp]
__device__ float g_hcatA[NHUM*2048];   // [h_enc | agg_o] ping
__device__ float g_hcatB[NHUM*2048];   // pong
__device__ float g_of[NOBJ*2048];      // [enc | nsp]
__device__ float g_ocatA[NOBJ*2048];
__device__ float g_ocatB[NOBJ*2048];
__device__ int   g_mask_mode;

// pre-split transposed weights [n][k]
__device__ __nv_bfloat16 g_bh1hi[1024*12544];
__device__ __nv_bfloat16 g_bh1lo[1024*12544];
__device__ __nv_bfloat16 g_bh2hi[1024*1024];
__device__ __nv_bfloat16 g_bh2lo[1024*1024];
__device__ __nv_bfloat16 g_sahi[1024*1024];
__device__ __nv_bfloat16 g_salo[1024*1024];
__device__ __nv_bfloat16 g_omhi[1024*1024];
__device__ __nv_bfloat16 g_omlo[1024*1024];
__device__ __nv_bfloat16 g_hmhi[1024*1024];
__device__ __nv_bfloat16 g_hmlo[1024*1024];
__device__ __nv_bfloat16 g_a1hi[2*2048*2048];
__device__ __nv_bfloat16 g_a1lo[2*2048*2048];
__device__ __nv_bfloat16 g_huhi[1024*2048];
__device__ __nv_bfloat16 g_hulo[1024*2048];
__device__ __nv_bfloat16 g_ouhi[1024*2048];
__device__ __nv_bfloat16 g_oulo[1024*2048];
__device__ __half        g_a2h[1024*2048];
__device__ __nv_bfloat16 g_boxhi[NOBJ*12544];
__device__ __nv_bfloat16 g_boxlo[NOBJ*12544];

__device__ __forceinline__ uint32_t smem_u32(const void* p) {
    uint32_t a;
    asm("{ .reg .u64 t; cvta.to.shared.u64 t, %1; cvt.u32.u64 %0, t; }" : "=r"(a) : "l"(p));
    return a;
}
__device__ __forceinline__ void cpasync16(uint32_t saddr, const void* g) {
    asm volatile("{ .reg .u64 gg; cvta.to.global.u64 gg, %1; "
                 "cp.async.cg.shared.global [%0], [gg], 16; }"
                 :: "r"(saddr), "l"(g));
}
#define CP_COMMIT() asm volatile("cp.async.commit_group;")
#define CP_WAIT0()  asm volatile("cp.async.wait_group 0;")

// ================= mma.sync helpers =================
__device__ __forceinline__ void mma_bf16(float* c, const uint32_t* a, const uint32_t* b)
{
    asm volatile("mma.sync.aligned.m16n8k16.row.col.f32.bf16.bf16.f32 "
                 "{%0,%1,%2,%3}, {%4,%5,%6,%7}, {%8,%9}, {%0,%1,%2,%3};"
                 : "+f"(c[0]), "+f"(c[1]), "+f"(c[2]), "+f"(c[3])
                 : "r"(a[0]), "r"(a[1]), "r"(a[2]), "r"(a[3]), "r"(b[0]), "r"(b[1]));
}
__device__ __forceinline__ void mma_f16(float* c, const uint32_t* a, const uint32_t* b)
{
    asm volatile("mma.sync.aligned.m16n8k16.row.col.f32.f16.f16.f32 "
                 "{%0,%1,%2,%3}, {%4,%5,%6,%7}, {%8,%9}, {%0,%1,%2,%3};"
                 : "+f"(c[0]), "+f"(c[1]), "+f"(c[2]), "+f"(c[3])
                 : "r"(a[0]), "r"(a[1]), "r"(a[2]), "r"(a[3]), "r"(b[0]), "r"(b[1]));
}
__device__ __forceinline__ void ldmx4(uint32_t* d, uint32_t addr)
{
    asm volatile("ldmatrix.sync.aligned.m8n8.x4.shared.b16 {%0,%1,%2,%3}, [%4];"
                 : "=r"(d[0]), "=r"(d[1]), "=r"(d[2]), "=r"(d[3]) : "r"(addr));
}
__device__ __forceinline__ void ldmx2(uint32_t* d, uint32_t addr)
{
    asm volatile("ldmatrix.sync.aligned.m8n8.x2.shared.b16 {%0,%1}, [%2];"
                 : "=r"(d[0]), "=r"(d[1]) : "r"(addr));
}

// bf16 hi/lo 3-pass chunk: 128x128 tile, K=64, stride 144B
__device__ __forceinline__ void mma_chunk(uint32_t abase_hi, uint32_t abase_lo,
                                          uint32_t wbase_hi, uint32_t wbase_lo,
                                          float acc[4][4][4], int lid,
                                          int warp_row, int warp_col)
{
    #pragma unroll
    for (int ks = 0; ks < 4; ks++) {
        const int kk = ks * 16;
        uint32_t bh[4][2], bl[4][2];
        const int l2 = lid & 15;
        const uint32_t bro = (uint32_t)((l2 & 7) * 144 + (kk + ((l2 & 8) ? 8 : 0)) * 2);
        #pragma unroll
        for (int an = 0; an < 4; an++) {
            uint32_t nbase = (uint32_t)((warp_col * 32 + an * 8) * 144);
            ldmx2(bh[an], wbase_hi + nbase + bro);
            ldmx2(bl[an], wbase_lo + nbase + bro);
        }
        const uint32_t aro = (uint32_t)((lid & 15) * 144 + (kk + ((lid & 16) ? 8 : 0)) * 2);
        #pragma unroll
        for (int am = 0; am < 4; am++) {
            uint32_t mbase = (uint32_t)((warp_row * 64 + am * 16) * 144);
            uint32_t ah4[4], al4[4];
            ldmx4(ah4, abase_hi + mbase + aro);
            ldmx4(al4, abase_lo + mbase + aro);
            #pragma unroll
            for (int an = 0; an < 4; an++) {
                mma_bf16(acc[am][an], ah4, bh[an]);
                mma_bf16(acc[am][an], ah4, bl[an]);
                mma_bf16(acc[am][an], al4, bh[an]);
            }
        }
    }
}

// ---------------- batched weight conversions ----------------
struct CvJobs {
    const float* W[10];
    void* hi[10];
    __nv_bfloat16* lo[10];
    int K[10];
    int N[10];
    int b0[10];
    int njobs;
};

__global__ void convall_k(CvJobs J)
{
    __shared__ float t[32][33];
    int bid = blockIdx.x;
    int j = 0;
    #pragma unroll
    for (int q = 1; q < 10; q++)
        if (q < J.njobs && bid >= J.b0[q]) j = q;
    int local = bid - J.b0[j];
    int K = J.K[j], N = J.N[j];
    int kblocks = K >> 5;
    int kb = (local % kblocks) * 32;
    int nb = (local / kblocks) * 32;
    const float* W = J.W[j];
    int tx = threadIdx.x, ty = threadIdx.y;
    #pragma unroll
    for (int i = 0; i < 4; i++)
        t[ty + 8 * i][tx] = W[(size_t)(kb + ty + 8 * i) * N + nb + tx];
    __syncthreads();
    if (J.lo[j]) {
        __nv_bfloat16* hi = (__nv_bfloat16*)J.hi[j];
        __nv_bfloat16* lo = J.lo[j];
        #pragma unroll
        for (int i = 0; i < 4; i++) {
            float v = t[tx][ty + 8 * i];
            __nv_bfloat16 h = __float2bfloat16(v);
            size_t oi = (size_t)(nb + ty + 8 * i) * K + kb + tx;
            hi[oi] = h;
            lo[oi] = __float2bfloat16(v - __bfloat162float(h));
        }
    } else {
        __half* out = (__half*)J.hi[j];
        #pragma unroll
        for (int i = 0; i < 4; i++)
            out[(size_t)(nb + ty + 8 * i) * K + kb + tx] = __float2half_rn(t[tx][ty + 8 * i]);
    }
}

__global__ void convA_k(const float* __restrict__ src, __nv_bfloat16* __restrict__ hi,
                        __nv_bfloat16* __restrict__ lo, int n)
{
    int base = (blockIdx.x * 256 + threadIdx.x) * 8;
    if (base >= n) return;
    float4 a = *(const float4*)(src + base);
    float4 b = *(const float4*)(src + base + 4);
    float v[8] = { a.x, a.y, a.z, a.w, b.x, b.y, b.z, b.w };
    __nv_bfloat16 hv[8], lv[8];
    #pragma unroll
    for (int i = 0; i < 8; i++) {
        hv[i] = __float2bfloat16(v[i]);
        lv[i] = __float2bfloat16(v[i] - __bfloat162float(hv[i]));
    }
    *(uint4*)(hi + base) = *(uint4*)hv;
    *(uint4*)(lo + base) = *(uint4*)lv;
}

// ================= unified jobs GEMM =================
#define GM_AHI 0
#define GM_ALO 18432
#define GM_WHI 36864
#define GM_WLO 55296
#define GM_SMEM 73728

struct GJobs {
    const float* A[3];
    const __nv_bfloat16* Ahi[3];
    const __nv_bfloat16* Alo[3];
    const __nv_bfloat16* Bhi[3];
    const __nv_bfloat16* Blo[3];
    const float* bias[3];
    float* C[3];
    float* C2[3];   // optional second atomic target (same ldc)
    int lda[3], ldc[3], M[3], N[3], K[3], kslice[3], b0[3], gx[3], gy[3], reluA[3];
    int njobs;
};

__device__ void gemm_body(const float* __restrict__ A,
                          const __nv_bfloat16* __restrict__ A16h,
                          const __nv_bfloat16* __restrict__ A16l, int lda,
                          const __nv_bfloat16* __restrict__ Bhi,
                          const __nv_bfloat16* __restrict__ Blo,
                          const float* __restrict__ bias, float* __restrict__ C,
                          float* __restrict__ C2,
                          int ldc, int M, int N, int K, int kslice, int reluA,
                          int bx, int by, int bz, char* smem)
{
    uint32_t sb = smem_u32(smem);
    const int tid = threadIdx.x;
    const int wid = tid >> 5, lid = tid & 31;
    const int col0 = bx * 128;
    const int row0 = by * 128;
    const int kstart = bz * kslice;
    const int warp_row = wid >> 2, warp_col = wid & 3;

    const int r = tid >> 1, kh = tid & 1;
    int arow = row0 + r; if (arow >= M) arow = M - 1;
    const __nv_bfloat16* whp = Bhi + (size_t)(col0 + r) * K + kstart + kh * 32;
    const __nv_bfloat16* wlp = Blo + (size_t)(col0 + r) * K + kstart + kh * 32;
    const uint32_t soff = (uint32_t)(r * 144 + kh * 64);

    float acc[4][4][4];
    #pragma unroll
    for (int i = 0; i < 4; i++)
        #pragma unroll
        for (int j = 0; j < 4; j++)
            #pragma unroll
            for (int q = 0; q < 4; q++) acc[i][j][q] = 0.f;

    const int nchunk = kslice >> 6;
    if (A16h) {
        const __nv_bfloat16* ahp = A16h + (size_t)arow * lda + kstart + kh * 32;
        const __nv_bfloat16* alp = A16l + (size_t)arow * lda + kstart + kh * 32;
        for (int c = 0; c < nchunk; c++) {
            const int k0 = c * 64;
            __syncthreads();
            #pragma unroll
            for (int j = 0; j < 4; j++) {
                cpasync16(sb + GM_WHI + soff + j * 16, whp + k0 + j * 8);
                cpasync16(sb + GM_WLO + soff + j * 16, wlp + k0 + j * 8);
            }
            #pragma unroll
            for (int j = 0; j < 4; j++) {
                cpasync16(sb + GM_AHI + soff + j * 16, ahp + k0 + j * 8);
                cpasync16(sb + GM_ALO + soff + j * 16, alp + k0 + j * 8);
            }
            CP_COMMIT();
            CP_WAIT0();
            __syncthreads();
            mma_chunk(sb + GM_AHI, sb + GM_ALO, sb + GM_WHI, sb + GM_WLO,
                      acc, lid, warp_row, warp_col);
        }
    } else {
        const float* agp = A + (size_t)arow * lda + kstart + kh * 32;
        for (int c = 0; c < nchunk; c++) {
            const int k0 = c * 64;
            __syncthreads();
            #pragma unroll
            for (int j = 0; j < 4; j++) {
                cpasync16(sb + GM_WHI + soff + j * 16, whp + k0 + j * 8);
                cpasync16(sb + GM_WLO + soff + j * 16, wlp + k0 + j * 8);
            }
            CP_COMMIT();
            const float4* p = (const float4*)(agp + k0);
            #pragma unroll
            for (int j = 0; j < 8; j++) {
                float4 a = p[j];
                if (reluA) {
                    a.x = fmaxf(a.x, 0.f); a.y = fmaxf(a.y, 0.f);
                    a.z = fmaxf(a.z, 0.f); a.w = fmaxf(a.w, 0.f);
                }
                __nv_bfloat16 h0 = __float2bfloat16(a.x), h1 = __float2bfloat16(a.y);
                __nv_bfloat16 h2 = __float2bfloat16(a.z), h3 = __float2bfloat16(a.w);
                __nv_bfloat162 hw0 = __nv_bfloat162(h0, h1), hw1 = __nv_bfloat162(h2, h3);
                __nv_bfloat162 lw0 = __nv_bfloat162(__float2bfloat16(a.x - __bfloat162float(h0)),
                                                    __float2bfloat16(a.y - __bfloat162float(h1)));
                __nv_bfloat162 lw1 = __nv_bfloat162(__float2bfloat16(a.z - __bfloat162float(h2)),
                                                    __float2bfloat16(a.w - __bfloat162float(h3)));
                *(uint2*)(smem + GM_AHI + soff + j * 8) = make_uint2(*(uint32_t*)&hw0, *(uint32_t*)&hw1);
                *(uint2*)(smem + GM_ALO + soff + j * 8) = make_uint2(*(uint32_t*)&lw0, *(uint32_t*)&lw1);
            }
            CP_WAIT0();
            __syncthreads();
            mma_chunk(sb + GM_AHI, sb + GM_ALO, sb + GM_WHI, sb + GM_WLO,
                      acc, lid, warp_row, warp_col);
        }
    }

    #pragma unroll
    for (int am = 0; am < 4; am++) {
        #pragma unroll
        for (int q = 0; q < 4; q++) {
            int row = row0 + warp_row * 64 + am * 16 + (lid >> 2) + ((q >= 2) ? 8 : 0);
            if (row >= M) continue;
            #pragma unroll
            for (int an = 0; an < 4; an++) {
                int col = col0 + warp_col * 32 + an * 8 + (lid & 3) * 2 + (q & 1);
                float v = acc[am][an][q];
                if (bz == 0 && bias) v += bias[col];
                size_t idx = (size_t)row * ldc + col;
                atomicAdd(C + idx, v);
                if (C2) atomicAdd(C2 + idx, v);
            }
        }
    }
}

__global__ void __launch_bounds__(256, 2)
gemm_jobs_k(GJobs J)
{
    extern __shared__ char smem[];
    int bid = blockIdx.x;
    int j = 0;
    #pragma unroll
    for (int q = 1; q < 3; q++)
        if (q < J.njobs && bid >= J.b0[q]) j = q;
    int local = bid - J.b0[j];
    int gxy = J.gx[j] * J.gy[j];
    int bz = local / gxy;
    int rem = local % gxy;
    int by = rem / J.gx[j];
    int bx = rem % J.gx[j];
    gemm_body(J.A[j], J.Ahi[j], J.Alo[j], J.lda[j], J.Bhi[j], J.Blo[j], J.bias[j], J.C[j],
              J.C2[j], J.ldc[j], J.M[j], J.N[j], J.K[j], J.kslice[j], J.reluA[j],
              bx, by, bz, smem);
}

// ================= fp16 pair MMA: single-sync pipelined (128-row tiles) =================
#define PR_AHS   0
#define PR_ST0   4096
#define PR_A     0
#define PR_W     18432
#define PR_STAGE 36864
#define PR_RED   77824
#define PR_B2    78336
#define PR_W3    78848
#define PR_SMEM  79360

__global__ void __launch_bounds__(256, 2)
pair_mma_k(const __half* __restrict__ Ahh, const __half* __restrict__ Aoh,
           const __half* __restrict__ Wt, const float* __restrict__ b2,
           const float* __restrict__ w3, float* __restrict__ adjp)
{
    extern __shared__ char smem[];
    uint32_t sb = smem_u32(smem);
    const int tid = threadIdx.x;
    const int wid = tid >> 5, lid = tid & 31;
    const int col0 = blockIdx.x * 128;
    const int row0 = blockIdx.y * 128;
    const int h = row0 >> 8;
    const int nb = row0 & 255;
    const int warp_row = wid >> 2, warp_col = wid & 3;

    if (tid < 128) {
        *(float*)(smem + PR_B2 + tid * 4) = b2[col0 + tid];
        *(float*)(smem + PR_W3 + tid * 4) = w3[col0 + tid];
        *(float*)(smem + PR_RED + tid * 4) = 0.f;
    }
    *(uint4*)(smem + PR_AHS + tid * 16) = *(const uint4*)(Ahh + h * 2048 + tid * 8);

    const int r = tid >> 1, kh = tid & 1;
    const __half* aop = Aoh + (size_t)(nb + r) * 2048 + kh * 32;
    const __half* whp = Wt + (size_t)(col0 + r) * 2048 + kh * 32;
    const uint32_t soff = (uint32_t)(r * 144 + kh * 64);

    float acc[4][4][4];
    #pragma unroll
    for (int i = 0; i < 4; i++)
        #pragma unroll
        for (int j = 0; j < 4; j++)
            #pragma unroll
            for (int q = 0; q < 4; q++) acc[i][j][q] = 0.f;

    {
        uint32_t stb = sb + PR_ST0;
        #pragma unroll
        for (int j = 0; j < 2; j++) {
            cpasync16(stb + PR_A + soff + j * 16, aop + j * 8);
            cpasync16(stb + PR_A + soff + 32 + j * 16, aop + 16 + j * 8);
            cpasync16(stb + PR_W + soff + j * 16, whp + j * 8);
            cpasync16(stb + PR_W + soff + 32 + j * 16, whp + 16 + j * 8);
        }
        CP_COMMIT();
    }
    __syncthreads();

    const __half2 hz = __floats2half2_rn(0.f, 0.f);
    const int n_off = ((lid >> 4) & 1) * 8 + (lid & 7);
    const int kb_ = ((lid >> 3) & 1) * 8;

    for (int c = 0; c < 32; c++) {
        const int cur = c & 1;
        CP_WAIT0();
        {
            char* av = smem + PR_ST0 + cur * PR_STAGE + PR_A + soff;
            const uint4* ahq = (const uint4*)(smem + PR_AHS + (c * 64 + kh * 32) * 2);
            #pragma unroll
            for (int j = 0; j < 4; j++) {
                uint4 vo = *(uint4*)(av + j * 16);
                uint4 vh = ahq[j];
                __half2 r0 = __hmax2(__hadd2(*(__half2*)&vo.x, *(__half2*)&vh.x), hz);
                __half2 r1 = __hmax2(__hadd2(*(__half2*)&vo.y, *(__half2*)&vh.y), hz);
                __half2 r2 = __hmax2(__hadd2(*(__half2*)&vo.z, *(__half2*)&vh.z), hz);
                __half2 r3 = __hmax2(__hadd2(*(__half2*)&vo.w, *(__half2*)&vh.w), hz);
                *(uint4*)(av + j * 16) = make_uint4(*(uint32_t*)&r0, *(uint32_t*)&r1,
                                                    *(uint32_t*)&r2, *(uint32_t*)&r3);
            }
        }
        __syncthreads();
        if (c < 31) {
            uint32_t stb = sb + PR_ST0 + (cur ^ 1) * PR_STAGE;
            const int kn = (c + 1) * 64;
            #pragma unroll
            for (int j = 0; j < 2; j++) {
                cpasync16(stb + PR_A + soff + j * 16, aop + kn + j * 8);
                cpasync16(stb + PR_A + soff + 32 + j * 16, aop + kn + 16 + j * 8);
                cpasync16(stb + PR_W + soff + j * 16, whp + kn + j * 8);
                cpasync16(stb + PR_W + soff + 32 + j * 16, whp + kn + 16 + j * 8);
            }
            CP_COMMIT();
        }
        uint32_t abase = sb + PR_ST0 + cur * PR_STAGE + PR_A;
        uint32_t wbase = sb + PR_ST0 + cur * PR_STAGE + PR_W;
        #pragma unroll
        for (int ks = 0; ks < 4; ks++) {
            const int kk = ks * 16;
            uint32_t b[4][2];
            #pragma unroll
            for (int anp = 0; anp < 2; anp++) {
                uint32_t t[4];
                ldmx4(t, wbase + (uint32_t)((warp_col * 32 + anp * 16 + n_off) * 144
                                            + (kk + kb_) * 2));
                b[anp * 2][0] = t[0]; b[anp * 2][1] = t[1];
                b[anp * 2 + 1][0] = t[2]; b[anp * 2 + 1][1] = t[3];
            }
            const uint32_t aro = (uint32_t)((lid & 15) * 144 + (kk + ((lid & 16) ? 8 : 0)) * 2);
            #pragma unroll
            for (int am = 0; am < 4; am++) {
                uint32_t a4[4];
                ldmx4(a4, abase + (uint32_t)((warp_row * 64 + am * 16) * 144) + aro);
                #pragma unroll
                for (int an = 0; an < 4; an++)
                    mma_f16(acc[am][an], a4, b[an]);
            }
        }
    }

    const float* b2s = (const float*)(smem + PR_B2);
    const float* w3s = (const float*)(smem + PR_W3);
    float* sred = (float*)(smem + PR_RED);
    #pragma unroll
    for (int am = 0; am < 4; am++) {
        float pl = 0.f, ph = 0.f;
        #pragma unroll
        for (int an = 0; an < 4; an++) {
            int cb = warp_col * 32 + an * 8 + 2 * (lid & 3);
            float w0 = w3s[cb], w1 = w3s[cb + 1];
            float bb0 = b2s[cb], bb1 = b2s[cb + 1];
            pl += fmaxf(acc[am][an][0] + bb0, 0.f) * w0 + fmaxf(acc[am][an][1] + bb1, 0.f) * w1;
            ph += fmaxf(acc[am][an][2] + bb0, 0.f) * w0 + fmaxf(acc[am][an][3] + bb1, 0.f) * w1;
        }
        pl += __shfl_xor_sync(0xffffffffu, pl, 1);
        pl += __shfl_xor_sync(0xffffffffu, pl, 2);
        ph += __shfl_xor_sync(0xffffffffu, ph, 1);
        ph += __shfl_xor_sync(0xffffffffu, ph, 2);
        if ((lid & 3) == 0) {
            int rloc = warp_row * 64 + am * 16 + (lid >> 2);
            atomicAdd(sred + rloc, pl);
            atomicAdd(sred + rloc + 8, ph);
        }
    }
    __syncthreads();
    if (tid < 128) atomicAdd(adjp + row0 + tid, sred[tid]);
}

// ---------------- small fused kernels ----------------
__device__ __forceinline__ float sigf(float z) { return 1.f / (1.f + expf(-z)); }

__global__ void zeroinit_k(float* enc1, float* Af, float* Aof, float* obj,
                           float* hum, float* adjp, float* nssa, float* of)
{
    int i = blockIdx.x * 256 + threadIdx.x;
    if (i < 262144) enc1[i] = 0.f;
    else if (i < 393216) Af[i - 262144] = 0.f;
    else if (i < 917504) Aof[i - 393216] = 0.f;
    else if (i < 1179648) obj[i - 917504] = 0.f;
    else if (i < 1245184) hum[i - 1179648] = 0.f;
    else if (i < 1261568) adjp[i - 1245184] = 0.f;
    else if (i < 1523712) nssa[i - 1261568] = 0.f;
    else if (i < 1785856) {
        int j = i - 1523712;
        of[(j >> 10) * 2048 + (j & 1023)] = 0.f;
    }
}

__global__ void copyinit_k(float* of, float* ocat, float* hf, float* hcat,
                           const float* __restrict__ nsp)
{
    int i = blockIdx.x * 256 + threadIdx.x;
    if (i >= 262144) return;
    int r = i >> 10, c = i & 1023;
    float e = fmaxf(of[r * 2048 + c], 0.f);
    of[r * 2048 + c] = e;
    float s = nsp[i];
    of[r * 2048 + 1024 + c] = s;
    ocat[r * 2048 + c] = e;
    if (r < 64) {
        hf[r * 2048 + c] = e;
        hf[r * 2048 + 1024 + c] = s;
        hcat[r * 2048 + c] = e;
    }
}

// cvt + in-place zero of Af/Aof (next-iter atomic targets); optional adjp zero.
// items 0..81919: 8-elem fp32->fp16 convert + zero source
// items 81920..83967: zero 8 adjp elems (only when zadj)
__global__ void cvtz_k(float* __restrict__ Af, float* __restrict__ Aof,
                       __half* __restrict__ Ahh, __half* __restrict__ Aoh,
                       float* __restrict__ adjp, int zadj)
{
    int i = blockIdx.x * 256 + threadIdx.x;
    const float4 z4 = make_float4(0.f, 0.f, 0.f, 0.f);
    if (i < 81920) {
        int base = i * 8;
        float* src;
        __half* dst;
        if (base < 131072) { src = Af + base; dst = Ahh + base; }
        else { src = Aof + (base - 131072); dst = Aoh + (base - 131072); }
        float4 a = *(float4*)src;
        float4 b = *(float4*)(src + 4);
        __half hv[8];
        hv[0] = __float2half_rn(a.x); hv[1] = __float2half_rn(a.y);
        hv[2] = __float2half_rn(a.z); hv[3] = __float2half_rn(a.w);
        hv[4] = __float2half_rn(b.x); hv[5] = __float2half_rn(b.y);
        hv[6] = __float2half_rn(b.z); hv[7] = __float2half_rn(b.w);
        *(uint4*)dst = *(uint4*)hv;
        *(float4*)src = z4;
        *(float4*)(src + 4) = z4;
    } else if (zadj && i < 81920 + 2048) {
        int base = (i - 81920) * 8;
        *(float4*)(adjp + base) = z4;
        *(float4*)(adjp + base + 4) = z4;
    }
}

// aggo: writes hcat_in-right; zeroes hf-left, hum, hcat_out-left
__global__ void aggo_k(const float* __restrict__ adjp, const float* __restrict__ b3,
                       const float* __restrict__ obj, const float* __restrict__ nssa,
                       float* __restrict__ hcat_in, float* __restrict__ hcat_out,
                       float* __restrict__ hf, float* __restrict__ hum)
{
    int h = blockIdx.y;
    int e = blockIdx.x * 128 + threadIdx.x;
    __shared__ float sa[256];
    float b3v = b3[0];
    for (int i = threadIdx.x; i < 256; i += 128)
        sa[i] = sigf(adjp[h * 256 + i] + b3v);
    __syncthreads();
    float a1 = 0.f, a2 = 0.f;
    #pragma unroll 4
    for (int n = 0; n < 256; n++) {
        float a = sa[n];
        float om = fmaxf(obj[n * 1024 + e], 0.f);
        float ns = nssa[n * 1024 + e];
        a1 += a * om;
        a2 += a * om * ns;
    }
    hcat_in[h * 2048 + 1024 + e] = nssa[h * 1024 + e] * a1 - a2;
    hcat_out[h * 2048 + e] = 0.f;
    hf[h * 2048 + e] = 0.f;
    hum[h * 1024 + e] = 0.f;
}

// aggh: writes ocat_in-right; zeroes of-left, obj, ocat_out-left
__global__ void aggh_k(const float* __restrict__ adjp, const float* __restrict__ b3,
                       const float* __restrict__ hum, const float* __restrict__ nssa,
                       float* __restrict__ ocat_in, float* __restrict__ ocat_out,
                       float* __restrict__ of, float* __restrict__ obj)
{
    int n = blockIdx.y;
    int e = blockIdx.x * 128 + threadIdx.x;
    __shared__ float sa[64];
    float b3v = b3[0];
    if (threadIdx.x < 64) sa[threadIdx.x] = sigf(adjp[threadIdx.x * 256 + n] + b3v);
    __syncthreads();
    float a1 = 0.f, a2 = 0.f;
    #pragma unroll 4
    for (int h = 0; h < 64; h++) {
        float a = sa[h];
        float hm = fmaxf(hum[h * 1024 + e], 0.f);
        float hs = nssa[h * 1024 + e];
        a1 += a * hm;
        a2 += a * hm * hs;
    }
    ocat_in[n * 2048 + 1024 + e] = nssa[n * 1024 + e] * a1 - a2;
    ocat_out[n * 2048 + e] = 0.f;
    of[n * 2048 + e] = 0.f;
    obj[n * 1024 + e] = 0.f;
}

__global__ void detect_k(const unsigned char* __restrict__ cm)
{
    __shared__ int s_f, s_nz;
    if (threadIdx.x == 0) { s_f = 0; s_nz = 0; }
    __syncthreads();
    int lf = 0, lnz = 0;
    for (int i = threadIdx.x; i < 9360; i += blockDim.x) {
        unsigned char b = cm[i];
        int m4 = i & 3;
        if (m4 == 3 && b == 0x3F) lf = 1;
        if (m4 != 0 && b != 0) lnz = 1;
    }
    if (lf) atomicOr(&s_f, 1);
    if (lnz) atomicOr(&s_nz, 1);
    __syncthreads();
    if (threadIdx.x == 0) g_mask_mode = s_f ? 2 : (s_nz ? 0 : 1);
}

__device__ __forceinline__ float lisf(float x)
{
    return 8.3f / (1.f + expf(12.f - 10.f * x));
}

// ---------------- final gather: phase-aligned float4 stores ----------------
__device__ __forceinline__ float outval(int c, const float* hx, const float* oy,
                                        float scale, int lab, int mode,
                                        const void* cmask)
{
    if (c < 2048) return hx[c];
    if (c < 4096) return oy[c - 2048];
    int j = c - 4096;
    float m;
    if (mode == 0)      m = ((const unsigned char*)cmask)[lab * NCLS + j] ? 1.f : 0.f;
    else if (mode == 1) m = ((const int*)cmask)[lab * NCLS + j] ? 1.f : 0.f;
    else                m = ((const float*)cmask)[lab * NCLS + j];
    return scale * m;
}

__global__ void out_k(const float* __restrict__ hf, const float* __restrict__ of,
                      const float* __restrict__ adjp, const float* __restrict__ b3,
                      const float* __restrict__ scores, const int* __restrict__ labels,
                      const void* __restrict__ cmask, float* __restrict__ out)
{
    int p = blockIdx.x;
    int x = p / 255;
    int r = p % 255;
    int y = (r < x) ? r : r + 1;

    float scale = sigf(adjp[x * 256 + y] + b3[0]) * lisf(scores[x]) * lisf(scores[y]);
    int lab = labels[y];
    int mode = g_mask_mode;

    const float* hx = hf + x * 2048;
    const float* oy = of + y * 2048;
    float* o = out + (size_t)p * OUTC;

    int phase = (4 - (p & 3)) & 3;
    int nvec = (OUTC - phase) >> 2;
    int tail0 = phase + nvec * 4;

    if (threadIdx.x < phase) {
        int c = threadIdx.x;
        o[c] = outval(c, hx, oy, scale, lab, mode, cmask);
    }
    for (int g = threadIdx.x; g < nvec; g += blockDim.x) {
        int c = phase + g * 4;
        float4 v;
        v.x = outval(c,     hx, oy, scale, lab, mode, cmask);
        v.y = outval(c + 1, hx, oy, scale, lab, mode, cmask);
        v.z = outval(c + 2, hx, oy, scale, lab, mode, cmask);
        v.w = outval(c + 3, hx, oy, scale, lab, mode, cmask);
        *(float4*)(o + c) = v;
    }
    for (int c = tail0 + threadIdx.x; c < OUTC; c += blockDim.x)
        o[c] = outval(c, hx, oy, scale, lab, mode, cmask);
}

// ---------------- host ----------------
static void add_job(GJobs& J, int idx, const float* A,
                    const __nv_bfloat16* Ahi, const __nv_bfloat16* Alo, int lda,
                    const __nv_bfloat16* Bhi, const __nv_bfloat16* Blo,
                    const float* bias, float* C, float* C2, int ldc,
                    int M, int N, int K, int nk, int reluA, int& total)
{
    int gx = N / 128, gy = (M + 127) / 128;
    J.A[idx] = A; J.Ahi[idx] = Ahi; J.Alo[idx] = Alo;
    J.Bhi[idx] = Bhi; J.Blo[idx] = Blo; J.bias[idx] = bias;
    J.C[idx] = C; J.C2[idx] = C2; J.lda[idx] = lda; J.ldc[idx] = ldc;
    J.M[idx] = M; J.N[idx] = N; J.K[idx] = K; J.kslice[idx] = K / nk;
    J.gx[idx] = gx; J.gy[idx] = gy; J.b0[idx] = total; J.reluA[idx] = reluA;
    total += gx * gy * nk;
}

extern "C" void kernel_launch(void* const* d_in, const int* in_sizes, int n_in,
                              void* d_out, int out_size)
{
    const float *box = 0, *nsp = 0, *scores = 0;
    const int *labels = 0;
    const void *cmask = 0;
    const float *W_bh1 = 0, *b_bh1 = 0, *W_bh2 = 0, *b_bh2 = 0, *W_sa = 0;
    const float *W_a1 = 0, *b_a1 = 0, *W_a2 = 0, *b_a2 = 0, *W_a3 = 0, *b_a3 = 0;
    const float *W_hm = 0, *b_hm = 0, *W_om = 0, *b_om = 0, *W_hu = 0, *W_ou = 0;

    int c256 = 0, c1k = 0, c1m = 0, c2m = 0;
    for (int i = 0; i < n_in; i++) {
        const void* p = d_in[i];
        switch (in_sizes[i]) {
            case 3211264:  box = (const float*)p; break;
            case 262144:   nsp = (const float*)p; break;
            case 256:      if (c256++ == 0) scores = (const float*)p; else labels = (const int*)p; break;
            case 9360:     cmask = p; break;
            case 12845056: W_bh1 = (const float*)p; break;
            case 1024:
                switch (c1k++) {
                    case 0: b_bh1 = (const float*)p; break;
                    case 1: b_bh2 = (const float*)p; break;
                    case 2: b_a2  = (const float*)p; break;
                    case 3: W_a3  = (const float*)p; break;
                    case 4: b_hm  = (const float*)p; break;
                    case 5: b_om  = (const float*)p; break;
                } break;
            case 1048576:
                switch (c1m++) {
                    case 0: W_bh2 = (const float*)p; break;
                    case 1: W_sa  = (const float*)p; break;
                    case 2: W_hm  = (const float*)p; break;
                    case 3: W_om  = (const float*)p; break;
                } break;
            case 8388608:  W_a1 = (const float*)p; break;
            case 2048:     b_a1 = (const float*)p; break;
            case 2097152:
                switch (c2m++) {
                    case 0: W_a2 = (const float*)p; break;
                    case 1: W_hu = (const float*)p; break;
                    case 2: W_ou = (const float*)p; break;
                } break;
            case 1:        b_a3 = (const float*)p; break;
            default: break;
        }
    }

    float *enc1, *nssa, *Af, *Aof, *adjp, *obj, *hum, *hf, *hcatA, *hcatB, *of, *ocatA, *ocatB;
    __half *Ahh, *Aoh;
    cudaGetSymbolAddress((void**)&enc1, g_enc1);
    cudaGetSymbolAddress((void**)&nssa, g_nssa);
    cudaGetSymbolAddress((void**)&Af,   g_Af);
    cudaGetSymbolAddress((void**)&Aof,  g_Aof);
    cudaGetSymbolAddress((void**)&Ahh,  g_Ahh);
    cudaGetSymbolAddress((void**)&Aoh,  g_Aoh);
    cudaGetSymbolAddress((void**)&adjp, g_adjp);
    cudaGetSymbolAddress((void**)&obj,  g_obj);
    cudaGetSymbolAddress((void**)&hum,  g_hum);
    cudaGetSymbolAddress((void**)&hf,   g_hf);
    cudaGetSymbolAddress((void**)&hcatA, g_hcatA);
    cudaGetSymbolAddress((void**)&hcatB, g_hcatB);
    cudaGetSymbolAddress((void**)&of,   g_of);
    cudaGetSymbolAddress((void**)&ocatA, g_ocatA);
    cudaGetSymbolAddress((void**)&ocatB, g_ocatB);

    __nv_bfloat16 *bh1hi, *bh1lo, *bh2hi, *bh2lo, *sahi, *salo, *omhi, *omlo, *hmhi, *hmlo;
    __nv_bfloat16 *a1hi, *a1lo, *huhi, *hulo, *ouhi, *oulo, *boxhi, *boxlo;
    __half *a2h;
    cudaGetSymbolAddress((void**)&bh1hi, g_bh1hi);
    cudaGetSymbolAddress((void**)&bh1lo, g_bh1lo);
    cudaGetSymbolAddress((void**)&bh2hi, g_bh2hi);
    cudaGetSymbolAddress((void**)&bh2lo, g_bh2lo);
    cudaGetSymbolAddress((void**)&sahi,  g_sahi);
    cudaGetSymbolAddress((void**)&salo,  g_salo);
    cudaGetSymbolAddress((void**)&omhi,  g_omhi);
    cudaGetSymbolAddress((void**)&omlo,  g_omlo);
    cudaGetSymbolAddress((void**)&hmhi,  g_hmhi);
    cudaGetSymbolAddress((void**)&hmlo,  g_hmlo);
    cudaGetSymbolAddress((void**)&a1hi,  g_a1hi);
    cudaGetSymbolAddress((void**)&a1lo,  g_a1lo);
    cudaGetSymbolAddress((void**)&huhi,  g_huhi);
    cudaGetSymbolAddress((void**)&hulo,  g_hulo);
    cudaGetSymbolAddress((void**)&ouhi,  g_ouhi);
    cudaGetSymbolAddress((void**)&oulo,  g_oulo);
    cudaGetSymbolAddress((void**)&a2h,   g_a2h);
    cudaGetSymbolAddress((void**)&boxhi, g_boxhi);
    cudaGetSymbolAddress((void**)&boxlo, g_boxlo);

    cudaFuncSetAttribute(pair_mma_k, cudaFuncAttributeMaxDynamicSharedMemorySize, PR_SMEM);
    cudaFuncSetAttribute(gemm_jobs_k, cudaFuncAttributeMaxDynamicSharedMemorySize, GM_SMEM);

    detect_k<<<1, 256>>>((const unsigned char*)cmask);

    // ---- batched weight conversions + box pre-split ----
    {
        CvJobs J;
        J.njobs = 10;
        const float* Ws[10] = { W_bh1, W_a1, W_a1 + (size_t)2048 * 2048, W_bh2, W_sa,
                                W_om, W_hm, W_hu, W_ou, W_a2 };
        void* his[10] = { bh1hi, a1hi, a1hi + (size_t)2048 * 2048, bh2hi, sahi,
                          omhi, hmhi, huhi, ouhi, a2h };
        __nv_bfloat16* los[10] = { bh1lo, a1lo, a1lo + (size_t)2048 * 2048, bh2lo, salo,
                                   omlo, hmlo, hulo, oulo, 0 };
        int Ks[10] = { 12544, 2048, 2048, 1024, 1024, 1024, 1024, 2048, 2048, 2048 };
        int Ns[10] = { 1024, 2048, 2048, 1024, 1024, 1024, 1024, 1024, 1024, 1024 };
        int total = 0;
        for (int j = 0; j < 10; j++) {
            J.W[j] = Ws[j]; J.hi[j] = his[j]; J.lo[j] = los[j];
            J.K[j] = Ks[j]; J.N[j] = Ns[j];
            J.b0[j] = total;
            total += (Ks[j] >> 5) * (Ns[j] >> 5);
        }
        convall_k<<<total, dim3(32, 8)>>>(J);
    }
    convA_k<<<3211264 / 2048, 256>>>(box, boxhi, boxlo, 3211264);

    zeroinit_k<<<(1785856 + 255) / 256, 256>>>(enc1, Af, Aof, obj, hum, adjp, nssa, of);

    // ---- encoder (bf16 pre-split A) ----
    {
        GJobs J; int total = 0; J.njobs = 1;
        add_job(J, 0, 0, boxhi, boxlo, 12544, bh1hi, bh1lo, b_bh1, enc1, 0, 1024,
                NOBJ, 1024, 12544, 28, 0, total);
        gemm_jobs_k<<<total, 256, GM_SMEM>>>(J);
    }
    {
        GJobs J; int total = 0; J.njobs = 2;
        add_job(J, 0, enc1, 0, 0, 1024, bh2hi, bh2lo, b_bh2, of, 0, 2048, NOBJ, 1024, 1024, 4, 1, total);
        add_job(J, 1, nsp, 0, 0, 1024, sahi, salo, 0, nssa, 0, 1024, NOBJ, 1024, 1024, 4, 0, total);
        gemm_jobs_k<<<total, 256, GM_SMEM>>>(J);
    }
    copyinit_k<<<(262144 + 255) / 256, 256>>>(of, ocatA, hf, hcatA, nsp);

    for (int it = 0; it < 2; it++) {
        float* hc_in = it ? hcatB : hcatA;
        float* hc_out = it ? hcatA : hcatB;
        float* oc_in = it ? ocatB : ocatA;
        float* oc_out = it ? ocatA : ocatB;

        // B1: A_h, A_o, obj (independent)
        {
            GJobs J; int total = 0; J.njobs = 3;
            add_job(J, 0, hf, 0, 0, 2048, a1hi, a1lo, b_a1, Af, 0, 2048, NHUM, 2048, 2048, 8, 0, total);
            add_job(J, 1, of, 0, 0, 2048, a1hi + (size_t)2048 * 2048, a1lo + (size_t)2048 * 2048,
                    0, Aof, 0, 2048, NOBJ, 2048, 2048, 8, 0, total);
            add_job(J, 2, of, 0, 0, 2048, omhi, omlo, b_om, obj, 0, 1024, NOBJ, 1024, 1024, 8, 0, total);
            gemm_jobs_k<<<total, 256, GM_SMEM>>>(J);
        }
        // cvt Af/Aof -> fp16 + zero Af/Aof for next iter; iter2 also zeroes adjp
        cvtz_k<<<(81920 + 2048 + 255) / 256, 256>>>(Af, Aof, Ahh, Aoh, adjp, it);

        // pair GEMM -> adjp (128-row tiles, proven config)
        pair_mma_k<<<dim3(8, 128), 256, PR_SMEM>>>(Ahh, Aoh, a2h, b_a2, W_a3, adjp);

        // aggo: hc_in right; zero hf-left, hum, hc_out-left
        aggo_k<<<dim3(8, NHUM), 128>>>(adjp, b_a3, obj, nssa, hc_in, hc_out, hf, hum);

        // h_upd: dual-write hf-left + hc_out-left
        {
            GJobs J; int total = 0; J.njobs = 1;
            add_job(J, 0, hc_in, 0, 0, 2048, huhi, hulo, 0, hf, hc_out, 2048, NHUM, 1024, 2048, 16, 0, total);
            gemm_jobs_k<<<total, 256, GM_SMEM>>>(J);
        }

        // hum = hf @ W_hm + b_hm (raw; relu in aggh)
        {
            GJobs J; int total = 0; J.njobs = 1;
            add_job(J, 0, hf, 0, 0, 2048, hmhi, hmlo, b_hm, hum, 0, 1024, NHUM, 1024, 1024, 16, 0, total);
            gemm_jobs_k<<<total, 256, GM_SMEM>>>(J);
        }

        // aggh: oc_in right; zero of-left, obj, oc_out-left
        aggh_k<<<dim3(8, NOBJ), 128>>>(adjp, b_a3, hum, nssa, oc_in, oc_out, of, obj);

        // o_upd: dual-write of-left + oc_out-left
        {
            GJobs J; int total = 0; J.njobs = 1;
            add_job(J, 0, oc_in, 0, 0, 2048, ouhi, oulo, 0, of, oc_out, 2048, NOBJ, 1024, 2048, 16, 0, total);
            gemm_jobs_k<<<total, 256, GM_SMEM>>>(J);
        }
    }

    // ---- final gather ----
    out_k<<<NKEEP, 256>>>(hf, of, adjp, b_a3, scores, labels, cmask, (float*)d_out);
}